// round 1
// baseline (speedup 1.0000x reference)
#include <cuda_runtime.h>
#include <cuda_bf16.h>
#include <cstdint>

// Problem constants
#define Bz 4
#define Sz 1024
#define Dz 512
#define Hz 8
#define DKz 64
#define Lz 4
#define DFFz 2048
#define SOFTCAP 30.0f
#define PAD_IDX 0
#define START_IDX 1

#define ROWS (Bz*Sz)           // 4096
#define XSZ  (ROWS*Dz)         // 2,097,152
#define H1SZ (ROWS*DFFz)       // 8,388,608

// Persistent scratch (allocation-free per harness rules)
__device__ float g_x[XSZ];
__device__ float g_xn[XSZ];
__device__ float g_q[XSZ];
__device__ float g_k[XSZ];
__device__ float g_v[XSZ];
__device__ float g_o[XSZ];
__device__ float g_h1[H1SZ];
__device__ float g_cb[ROWS];
__device__ int   g_keep[ROWS];

// ---------------------------------------------------------------------------
// Embedding + right-shift + count bias + keep mask
// ---------------------------------------------------------------------------
__global__ void embed_kernel(const int* __restrict__ tok,
                             const float* __restrict__ cnt,
                             const float* __restrict__ emb)
{
    int r = blockIdx.x;           // 0..ROWS-1
    int b = r / Sz, s = r % Sz;
    int t;
    float c;
    if (s == 0) { t = START_IDX; c = 1.0f; }
    else        { t = tok[b*Sz + s - 1]; c = cnt[b*Sz + s - 1]; }
    if (threadIdx.x == 0) {
        g_cb[r]   = log1pf(c + 1e-6f);
        g_keep[r] = (t != PAD_IDX);
    }
    const float4* src = (const float4*)(emb + (size_t)t * Dz);
    float4* dst = (float4*)(g_x + (size_t)r * Dz);
    dst[threadIdx.x] = src[threadIdx.x];   // 128 threads * float4 = 512
}

// ---------------------------------------------------------------------------
// LayerNorm (two-pass, exact mean/var), D=512, 128 threads/row
// ---------------------------------------------------------------------------
__device__ __forceinline__ float block_reduce_sum(float v, float* red)
{
    int lane = threadIdx.x & 31, warp = threadIdx.x >> 5;
    #pragma unroll
    for (int o = 16; o > 0; o >>= 1) v += __shfl_xor_sync(0xffffffffu, v, o);
    if (lane == 0) red[warp] = v;
    __syncthreads();
    float r = 0.f;
    if (warp == 0) {
        r = (lane < (blockDim.x >> 5)) ? red[lane] : 0.f;
        #pragma unroll
        for (int o = 16; o > 0; o >>= 1) r += __shfl_xor_sync(0xffffffffu, r, o);
        if (lane == 0) red[0] = r;
    }
    __syncthreads();
    r = red[0];
    __syncthreads();
    return r;
}

__global__ void layernorm_kernel(const float* __restrict__ x,
                                 const float* __restrict__ gam,
                                 const float* __restrict__ bet,
                                 float* __restrict__ out)
{
    __shared__ float red[32];
    int r = blockIdx.x;
    const float4* xr = (const float4*)(x + (size_t)r * Dz);
    float4 v = xr[threadIdx.x];
    float s = v.x + v.y + v.z + v.w;
    float tot = block_reduce_sum(s, red);
    float mu = tot * (1.0f / Dz);
    float d0 = v.x - mu, d1 = v.y - mu, d2 = v.z - mu, d3 = v.w - mu;
    float sq = d0*d0 + d1*d1 + d2*d2 + d3*d3;
    float var = block_reduce_sum(sq, red) * (1.0f / Dz);
    float rstd = rsqrtf(var + 1e-5f);
    float4 gg = ((const float4*)gam)[threadIdx.x];
    float4 bb = ((const float4*)bet)[threadIdx.x];
    float4 o;
    o.x = d0 * rstd * gg.x + bb.x;
    o.y = d1 * rstd * gg.y + bb.y;
    o.z = d2 * rstd * gg.z + bb.z;
    o.w = d3 * rstd * gg.w + bb.w;
    ((float4*)(out + (size_t)r * Dz))[threadIdx.x] = o;
}

// ---------------------------------------------------------------------------
// SGEMM: C[M,N] = A[M,K] @ W[K,N] + bias  (+ epilogue)
// EPI 0: +bias   EPI 1: gelu(+bias)   EPI 2: +bias + res[M,N]
// BM=128 BN=128 BK=8 TM=8 TN=8, 256 threads
// ---------------------------------------------------------------------------
__device__ __forceinline__ float gelu_f(float x)
{
    float x3 = x * x * x;
    return 0.5f * x * (1.f + tanhf(0.7978845608028654f * (x + 0.044715f * x3)));
}

template<int EPI>
__global__ void __launch_bounds__(256, 2)
sgemm_kernel(int M, int N, int K,
             const float* __restrict__ A,
             const float* __restrict__ W,
             const float* __restrict__ bias,
             const float* __restrict__ res,
             float* __restrict__ C)
{
    const int BM = 128, BN = 128, BK = 8, TM = 8, TN = 8;
    __shared__ float As[BK][BM];
    __shared__ float Bs[BK][BN];
    int bx = blockIdx.x, by = blockIdx.y;
    int tid = threadIdx.x;
    int tcol = (tid % 16) * TN;
    int trow = (tid / 16) * TM;

    const float* Ab = A + (size_t)by * BM * K;
    const float* Wb = W + (size_t)bx * BN;

    float acc[TM][TN];
    #pragma unroll
    for (int i = 0; i < TM; i++)
        #pragma unroll
        for (int j = 0; j < TN; j++) acc[i][j] = 0.f;

    int aRow = tid >> 1, aCol = (tid & 1) * 4;
    int bRow = tid >> 5, bCol = (tid & 31) * 4;

    for (int k0 = 0; k0 < K; k0 += BK) {
        float4 a4 = *(const float4*)(Ab + (size_t)aRow * K + k0 + aCol);
        As[aCol + 0][aRow] = a4.x;
        As[aCol + 1][aRow] = a4.y;
        As[aCol + 2][aRow] = a4.z;
        As[aCol + 3][aRow] = a4.w;
        float4 b4 = *(const float4*)(Wb + (size_t)(k0 + bRow) * N + bCol);
        *(float4*)(&Bs[bRow][bCol]) = b4;
        __syncthreads();
        #pragma unroll
        for (int kk = 0; kk < BK; kk++) {
            float rM[TM], rN[TN];
            #pragma unroll
            for (int i = 0; i < TM; i++) rM[i] = As[kk][trow + i];
            #pragma unroll
            for (int j = 0; j < TN; j++) rN[j] = Bs[kk][tcol + j];
            #pragma unroll
            for (int i = 0; i < TM; i++)
                #pragma unroll
                for (int j = 0; j < TN; j++) acc[i][j] += rM[i] * rN[j];
        }
        __syncthreads();
    }

    #pragma unroll
    for (int i = 0; i < TM; i++) {
        size_t row = (size_t)by * BM + trow + i;
        #pragma unroll
        for (int j = 0; j < TN; j++) {
            size_t col = (size_t)bx * BN + tcol + j;
            float v = acc[i][j] + bias[col];
            if (EPI == 1) v = gelu_f(v);
            if (EPI == 2) v += res[row * N + col];
            C[row * N + col] = v;
        }
    }
}

// ---------------------------------------------------------------------------
// Per-vector quant-dequant (TurboQuant style), one warp per 64-elem vector
// ---------------------------------------------------------------------------
__global__ void quantdq_kernel(float* __restrict__ t, const float* __restrict__ levels)
{
    __shared__ float lv[8];
    if (threadIdx.x < 8) lv[threadIdx.x] = levels[threadIdx.x];
    __syncthreads();
    int warp = threadIdx.x >> 5, lane = threadIdx.x & 31;
    int w = blockIdx.x * 8 + warp;                 // vector id, B*S*H total
    float* p = t + (size_t)(w / Hz) * Dz + (size_t)(w % Hz) * DKz;

    float x0 = p[lane], x1 = p[lane + 32];
    float ss = x0 * x0 + x1 * x1;
    #pragma unroll
    for (int o = 16; o > 0; o >>= 1) ss += __shfl_xor_sync(0xffffffffu, ss, o);
    float nrm = sqrtf(ss);
    float inv = 1.f / (nrm + 1e-8f);
    float u0 = x0 * inv, u1 = x1 * inv;
    float a0 = fabsf(u0), a1 = fabsf(u1);
    float sg0 = (u0 >= 0.f) ? 1.f : -1.f;
    float sg1 = (u1 >= 0.f) ? 1.f : -1.f;

    float q0 = lv[0], b0 = fabsf(a0 - lv[0]);
    float q1 = lv[0], b1 = fabsf(a1 - lv[0]);
    #pragma unroll
    for (int i = 1; i < 8; i++) {
        float d0 = fabsf(a0 - lv[i]);
        if (d0 < b0) { b0 = d0; q0 = lv[i]; }
        float d1 = fabsf(a1 - lv[i]);
        if (d1 < b1) { b1 = d1; q1 = lv[i]; }
    }
    float num = a0 * q0 + a1 * q1;
    float den = q0 * q0 + q1 * q1;
    #pragma unroll
    for (int o = 16; o > 0; o >>= 1) {
        num += __shfl_xor_sync(0xffffffffu, num, o);
        den += __shfl_xor_sync(0xffffffffu, den, o);
    }
    float rmag = num / (den + 1e-8f);
    p[lane]      = sg0 * q0 * rmag * nrm;
    p[lane + 32] = sg1 * q1 * rmag * nrm;
}

// ---------------------------------------------------------------------------
// Causal attention with softcap + count bias, 64q x 64k tiles.
// Softcap bounds scores to [-30,30] -> exp never overflows -> no online max.
// Dynamic smem: Qs/Ks/Vs/Ps [64][65] + dens/cb/keep
// ---------------------------------------------------------------------------
#define ATTN_SMEM (4*64*65*4 + 64*4*3)

__global__ void __launch_bounds__(256, 1)
attn_kernel(const float* __restrict__ gq, const float* __restrict__ gk,
            const float* __restrict__ gv, float* __restrict__ go,
            const float* __restrict__ cb, const int* __restrict__ keep)
{
    extern __shared__ float sm[];
    float (*Qs)[65] = (float(*)[65])(sm);
    float (*Ks)[65] = (float(*)[65])(sm + 64*65);
    float (*Vs)[65] = (float(*)[65])(sm + 2*64*65);
    float (*Ps)[65] = (float(*)[65])(sm + 3*64*65);
    float* dens = sm + 4*64*65;
    float* cbk  = dens + 64;
    int*   kpk  = (int*)(cbk + 64);

    int qt = blockIdx.x;          // query tile 0..15
    int bh = blockIdx.y;          // 0..31
    int b = bh / Hz, h = bh % Hz;
    int q0 = qt * 64;
    int tid = threadIdx.x;
    int tx = tid & 15, ty = tid >> 4;
    const float scale = 0.125f;   // 1/sqrt(64)

    const float* qbase = gq + ((size_t)(b * Sz + q0)) * Dz + h * DKz;
    #pragma unroll
    for (int i = 0; i < 4; i++) {
        int idx = tid + i * 256;
        int qi = idx >> 4, d4 = (idx & 15) * 4;
        float4 v4 = *(const float4*)(qbase + (size_t)qi * Dz + d4);
        Qs[qi][d4] = v4.x; Qs[qi][d4+1] = v4.y; Qs[qi][d4+2] = v4.z; Qs[qi][d4+3] = v4.w;
    }
    if (tid < 64) dens[tid] = 0.f;

    float acc[4][4];
    #pragma unroll
    for (int i = 0; i < 4; i++)
        #pragma unroll
        for (int j = 0; j < 4; j++) acc[i][j] = 0.f;

    for (int kt = 0; kt <= qt; kt++) {
        int k0 = kt * 64;
        __syncthreads();   // previous-iter reads done (and Q/den init on first iter)
        const float* kbase = gk + ((size_t)(b * Sz + k0)) * Dz + h * DKz;
        const float* vbase = gv + ((size_t)(b * Sz + k0)) * Dz + h * DKz;
        #pragma unroll
        for (int i = 0; i < 4; i++) {
            int idx = tid + i * 256;
            int r = idx >> 4, d4 = (idx & 15) * 4;
            float4 kv = *(const float4*)(kbase + (size_t)r * Dz + d4);
            Ks[r][d4] = kv.x; Ks[r][d4+1] = kv.y; Ks[r][d4+2] = kv.z; Ks[r][d4+3] = kv.w;
            float4 vv = *(const float4*)(vbase + (size_t)r * Dz + d4);
            Vs[r][d4] = vv.x; Vs[r][d4+1] = vv.y; Vs[r][d4+2] = vv.z; Vs[r][d4+3] = vv.w;
        }
        if (tid < 64) {
            cbk[tid] = cb[b * Sz + k0 + tid];
            kpk[tid] = keep[b * Sz + k0 + tid];
        }
        __syncthreads();

        float s[4][4];
        #pragma unroll
        for (int i = 0; i < 4; i++)
            #pragma unroll
            for (int j = 0; j < 4; j++) s[i][j] = 0.f;
        #pragma unroll 8
        for (int kk = 0; kk < 64; kk++) {
            float rq[4], rk[4];
            #pragma unroll
            for (int i = 0; i < 4; i++) rq[i] = Qs[ty*4 + i][kk];
            #pragma unroll
            for (int j = 0; j < 4; j++) rk[j] = Ks[tx*4 + j][kk];
            #pragma unroll
            for (int i = 0; i < 4; i++)
                #pragma unroll
                for (int j = 0; j < 4; j++) s[i][j] += rq[i] * rk[j];
        }
        #pragma unroll
        for (int i = 0; i < 4; i++) {
            int qg = q0 + ty*4 + i;
            #pragma unroll
            for (int j = 0; j < 4; j++) {
                int kg = k0 + tx*4 + j;
                float p = 0.f;
                if (kg <= qg && kpk[tx*4 + j]) {
                    float z = (s[i][j] * scale + cbk[tx*4 + j]) * (1.0f / SOFTCAP);
                    p = expf(tanhf(z) * SOFTCAP);
                }
                Ps[ty*4 + i][tx*4 + j] = p;
            }
        }
        __syncthreads();
        if (tid < 64) {
            float sum = 0.f;
            #pragma unroll 8
            for (int kk = 0; kk < 64; kk++) sum += Ps[tid][kk];
            dens[tid] += sum;
        }
        #pragma unroll 8
        for (int kk = 0; kk < 64; kk++) {
            float rp[4], rv[4];
            #pragma unroll
            for (int i = 0; i < 4; i++) rp[i] = Ps[ty*4 + i][kk];
            #pragma unroll
            for (int j = 0; j < 4; j++) rv[j] = Vs[kk][tx*4 + j];
            #pragma unroll
            for (int i = 0; i < 4; i++)
                #pragma unroll
                for (int j = 0; j < 4; j++) acc[i][j] += rp[i] * rv[j];
        }
    }
    __syncthreads();
    float* obase = go + ((size_t)(b * Sz + q0)) * Dz + h * DKz;
    #pragma unroll
    for (int i = 0; i < 4; i++) {
        float dinv = 1.f / dens[ty*4 + i];
        #pragma unroll
        for (int j = 0; j < 4; j++)
            obase[(size_t)(ty*4 + i) * Dz + tx*4 + j] = acc[i][j] * dinv;
    }
}

// ---------------------------------------------------------------------------
// Host launcher
// ---------------------------------------------------------------------------
extern "C" void kernel_launch(void* const* d_in, const int* in_sizes, int n_in,
                              void* d_out, int out_size)
{
    const int*   tok  = (const int*)  d_in[0];
    const float* cnt  = (const float*)d_in[1];
    const float* emb  = (const float*)d_in[2];
    const float* Wq   = (const float*)d_in[3];
    const float* bq   = (const float*)d_in[4];
    const float* Wk   = (const float*)d_in[5];
    const float* bk   = (const float*)d_in[6];
    const float* Wv   = (const float*)d_in[7];
    const float* bv   = (const float*)d_in[8];
    const float* Wo   = (const float*)d_in[9];
    const float* bo   = (const float*)d_in[10];
    const float* ln1g = (const float*)d_in[11];
    const float* ln1b = (const float*)d_in[12];
    const float* ln2g = (const float*)d_in[13];
    const float* ln2b = (const float*)d_in[14];
    const float* W1   = (const float*)d_in[15];
    const float* b1   = (const float*)d_in[16];
    const float* W2   = (const float*)d_in[17];
    const float* b2   = (const float*)d_in[18];
    const float* cbk  = (const float*)d_in[19];
    float* out = (float*)d_out;

    cudaFuncSetAttribute(attn_kernel, cudaFuncAttributeMaxDynamicSharedMemorySize, ATTN_SMEM);

    float *px, *pxn, *pq, *pk, *pv, *po, *ph1, *pcb;
    int *pkeep;
    cudaGetSymbolAddress((void**)&px,   g_x);
    cudaGetSymbolAddress((void**)&pxn,  g_xn);
    cudaGetSymbolAddress((void**)&pq,   g_q);
    cudaGetSymbolAddress((void**)&pk,   g_k);
    cudaGetSymbolAddress((void**)&pv,   g_v);
    cudaGetSymbolAddress((void**)&po,   g_o);
    cudaGetSymbolAddress((void**)&ph1,  g_h1);
    cudaGetSymbolAddress((void**)&pcb,  g_cb);
    cudaGetSymbolAddress((void**)&pkeep, g_keep);

    embed_kernel<<<ROWS, 128>>>(tok, cnt, emb);

    dim3 gD(Dz / 128, ROWS / 128);      // N=512 GEMMs
    dim3 gF(DFFz / 128, ROWS / 128);    // N=2048 GEMM

    for (int l = 0; l < Lz; l++) {
        const float* wq = Wq + (size_t)l * Dz * Dz;
        const float* wk = Wk + (size_t)l * Dz * Dz;
        const float* wv = Wv + (size_t)l * Dz * Dz;
        const float* wo = Wo + (size_t)l * Dz * Dz;
        const float* w1 = W1 + (size_t)l * Dz * DFFz;
        const float* w2 = W2 + (size_t)l * DFFz * Dz;

        layernorm_kernel<<<ROWS, 128>>>(px, ln1g + l*Dz, ln1b + l*Dz, pxn);

        sgemm_kernel<0><<<gD, 256>>>(ROWS, Dz, Dz, pxn, wq, bq + l*Dz, nullptr, pq);
        sgemm_kernel<0><<<gD, 256>>>(ROWS, Dz, Dz, pxn, wk, bk + l*Dz, nullptr, pk);
        sgemm_kernel<0><<<gD, 256>>>(ROWS, Dz, Dz, pxn, wv, bv + l*Dz, nullptr, pv);

        quantdq_kernel<<<ROWS * Hz / 8, 256>>>(pk, cbk + (size_t)(l*2 + 0)*8);
        quantdq_kernel<<<ROWS * Hz / 8, 256>>>(pv, cbk + (size_t)(l*2 + 1)*8);

        attn_kernel<<<dim3(Sz/64, Bz*Hz), 256, ATTN_SMEM>>>(pq, pk, pv, po, pcb, pkeep);

        // x = o @ Wo + bo + xn
        sgemm_kernel<2><<<gD, 256>>>(ROWS, Dz, Dz, po, wo, bo + l*Dz, pxn, px);

        layernorm_kernel<<<ROWS, 128>>>(px, ln2g + l*Dz, ln2b + l*Dz, pxn);

        // h1 = gelu(xn2 @ W1 + b1)
        sgemm_kernel<1><<<gF, 256>>>(ROWS, DFFz, Dz, pxn, w1, b1 + l*DFFz, nullptr, ph1);

        // x = h1 @ W2 + b2 + xn2   (last layer writes straight to d_out)
        float* dst = (l == Lz - 1) ? out : px;
        sgemm_kernel<2><<<gD, 256>>>(ROWS, Dz, DFFz, ph1, w2, b2 + l*Dz, pxn, dst);
    }
}

// round 2
// speedup vs baseline: 1.3651x; 1.3651x over previous
#include <cuda_runtime.h>
#include <cuda_bf16.h>
#include <cstdint>

// Problem constants
#define Bz 4
#define Sz 1024
#define Dz 512
#define Hz 8
#define DKz 64
#define Lz 4
#define DFFz 2048
#define SOFTCAP 30.0f
#define PAD_IDX 0
#define START_IDX 1

#define ROWS (Bz*Sz)           // 4096
#define XSZ  (ROWS*Dz)         // 2,097,152
#define H1SZ (ROWS*DFFz)       // 8,388,608

// Persistent scratch (allocation-free per harness rules)
__device__ float g_x[XSZ];
__device__ float g_xn[XSZ];
__device__ float g_q[XSZ];
__device__ float g_k[XSZ];
__device__ float g_v[XSZ];
__device__ float g_o[XSZ];
__device__ float g_h1[H1SZ];
__device__ float g_cb[ROWS];
__device__ int   g_keep[ROWS];

// ---------------------------------------------------------------------------
// Embedding + right-shift + count bias + keep mask
// ---------------------------------------------------------------------------
__global__ void embed_kernel(const int* __restrict__ tok,
                             const float* __restrict__ cnt,
                             const float* __restrict__ emb)
{
    int r = blockIdx.x;           // 0..ROWS-1
    int b = r / Sz, s = r % Sz;
    int t;
    float c;
    if (s == 0) { t = START_IDX; c = 1.0f; }
    else        { t = tok[b*Sz + s - 1]; c = cnt[b*Sz + s - 1]; }
    if (threadIdx.x == 0) {
        g_cb[r]   = log1pf(c + 1e-6f);
        g_keep[r] = (t != PAD_IDX);
    }
    const float4* src = (const float4*)(emb + (size_t)t * Dz);
    float4* dst = (float4*)(g_x + (size_t)r * Dz);
    dst[threadIdx.x] = src[threadIdx.x];   // 128 threads * float4 = 512
}

// ---------------------------------------------------------------------------
// LayerNorm (two-pass, exact mean/var), D=512, 128 threads/row
// ---------------------------------------------------------------------------
__device__ __forceinline__ float block_reduce_sum(float v, float* red)
{
    int lane = threadIdx.x & 31, warp = threadIdx.x >> 5;
    #pragma unroll
    for (int o = 16; o > 0; o >>= 1) v += __shfl_xor_sync(0xffffffffu, v, o);
    if (lane == 0) red[warp] = v;
    __syncthreads();
    float r = 0.f;
    if (warp == 0) {
        r = (lane < (blockDim.x >> 5)) ? red[lane] : 0.f;
        #pragma unroll
        for (int o = 16; o > 0; o >>= 1) r += __shfl_xor_sync(0xffffffffu, r, o);
        if (lane == 0) red[0] = r;
    }
    __syncthreads();
    r = red[0];
    __syncthreads();
    return r;
}

__global__ void layernorm_kernel(const float* __restrict__ x,
                                 const float* __restrict__ gam,
                                 const float* __restrict__ bet,
                                 float* __restrict__ out)
{
    __shared__ float red[32];
    int r = blockIdx.x;
    const float4* xr = (const float4*)(x + (size_t)r * Dz);
    float4 v = xr[threadIdx.x];
    float s = v.x + v.y + v.z + v.w;
    float tot = block_reduce_sum(s, red);
    float mu = tot * (1.0f / Dz);
    float d0 = v.x - mu, d1 = v.y - mu, d2 = v.z - mu, d3 = v.w - mu;
    float sq = d0*d0 + d1*d1 + d2*d2 + d3*d3;
    float var = block_reduce_sum(sq, red) * (1.0f / Dz);
    float rstd = rsqrtf(var + 1e-5f);
    float4 gg = ((const float4*)gam)[threadIdx.x];
    float4 bb = ((const float4*)bet)[threadIdx.x];
    float4 o;
    o.x = d0 * rstd * gg.x + bb.x;
    o.y = d1 * rstd * gg.y + bb.y;
    o.z = d2 * rstd * gg.z + bb.z;
    o.w = d3 * rstd * gg.w + bb.w;
    ((float4*)(out + (size_t)r * Dz))[threadIdx.x] = o;
}

// ---------------------------------------------------------------------------
// SGEMM v2: 128x128 tile, BK=16, double-buffered smem, 8x8 per thread as
// four 4x4 float4 blocks (trow4/tcol4 and +64) -> conflict-free LDS.128.
// EPI 0: +bias   EPI 1: gelu(+bias)   EPI 2: +bias + res[M,N]
// ---------------------------------------------------------------------------
__device__ __forceinline__ float gelu_f(float x)
{
    float x3 = x * x * x;
    return 0.5f * x * (1.f + tanhf(0.7978845608028654f * (x + 0.044715f * x3)));
}

template<int EPI>
__device__ __forceinline__ void gemm_body(
    int M, int N, int K,
    const float* __restrict__ A,
    const float* __restrict__ W,
    const float* __restrict__ bias,
    const float* __restrict__ res,
    float* __restrict__ C,
    int bx, int by)
{
    const int BM = 128, BN = 128, BK = 16;
    __shared__ float As[2][BK][BM];
    __shared__ float Bs[2][BK][BN];

    int tid = threadIdx.x;
    int trow4 = (tid >> 4) * 4;       // 0..60
    int tcol4 = (tid & 15) * 4;       // 0..60

    const float* Ab = A + (size_t)by * BM * K;
    const float* Wb = W + (size_t)bx * BN;

    int aRow = tid >> 1, aCol = (tid & 1) * 8;
    int bRow = tid >> 5, bCol = (tid & 31) * 4;

    float4 la0, la1, lb0, lb1;
    // prologue: load k0 = 0
    la0 = *(const float4*)(Ab + (size_t)aRow * K + aCol);
    la1 = *(const float4*)(Ab + (size_t)aRow * K + aCol + 4);
    lb0 = *(const float4*)(Wb + (size_t)bRow * N + bCol);
    lb1 = *(const float4*)(Wb + (size_t)(bRow + 8) * N + bCol);
    As[0][aCol + 0][aRow] = la0.x; As[0][aCol + 1][aRow] = la0.y;
    As[0][aCol + 2][aRow] = la0.z; As[0][aCol + 3][aRow] = la0.w;
    As[0][aCol + 4][aRow] = la1.x; As[0][aCol + 5][aRow] = la1.y;
    As[0][aCol + 6][aRow] = la1.z; As[0][aCol + 7][aRow] = la1.w;
    *(float4*)&Bs[0][bRow][bCol]     = lb0;
    *(float4*)&Bs[0][bRow + 8][bCol] = lb1;
    __syncthreads();

    float acc[8][8];
    #pragma unroll
    for (int i = 0; i < 8; i++)
        #pragma unroll
        for (int j = 0; j < 8; j++) acc[i][j] = 0.f;

    int buf = 0;
    for (int k0 = BK; ; k0 += BK) {
        bool more = (k0 < K);
        if (more) {
            la0 = *(const float4*)(Ab + (size_t)aRow * K + k0 + aCol);
            la1 = *(const float4*)(Ab + (size_t)aRow * K + k0 + aCol + 4);
            lb0 = *(const float4*)(Wb + (size_t)(k0 + bRow) * N + bCol);
            lb1 = *(const float4*)(Wb + (size_t)(k0 + bRow + 8) * N + bCol);
        }
        #pragma unroll
        for (int kk = 0; kk < BK; kk++) {
            float4 ra0 = *(const float4*)&As[buf][kk][trow4];
            float4 ra1 = *(const float4*)&As[buf][kk][trow4 + 64];
            float4 rb0 = *(const float4*)&Bs[buf][kk][tcol4];
            float4 rb1 = *(const float4*)&Bs[buf][kk][tcol4 + 64];
            float rm[8] = {ra0.x, ra0.y, ra0.z, ra0.w, ra1.x, ra1.y, ra1.z, ra1.w};
            float rn[8] = {rb0.x, rb0.y, rb0.z, rb0.w, rb1.x, rb1.y, rb1.z, rb1.w};
            #pragma unroll
            for (int i = 0; i < 8; i++)
                #pragma unroll
                for (int j = 0; j < 8; j++) acc[i][j] += rm[i] * rn[j];
        }
        if (!more) break;
        int nb = buf ^ 1;
        As[nb][aCol + 0][aRow] = la0.x; As[nb][aCol + 1][aRow] = la0.y;
        As[nb][aCol + 2][aRow] = la0.z; As[nb][aCol + 3][aRow] = la0.w;
        As[nb][aCol + 4][aRow] = la1.x; As[nb][aCol + 5][aRow] = la1.y;
        As[nb][aCol + 6][aRow] = la1.z; As[nb][aCol + 7][aRow] = la1.w;
        *(float4*)&Bs[nb][bRow][bCol]     = lb0;
        *(float4*)&Bs[nb][bRow + 8][bCol] = lb1;
        __syncthreads();
        buf = nb;
    }

    // Epilogue
    size_t c0 = (size_t)bx * BN + tcol4;
    float4 bias0 = *(const float4*)(bias + c0);
    float4 bias1 = *(const float4*)(bias + c0 + 64);
    #pragma unroll
    for (int i = 0; i < 8; i++) {
        size_t r = (size_t)by * BM + trow4 + (i & 3) + ((i >> 2) << 6);
        float4 v0, v1;
        v0.x = acc[i][0] + bias0.x; v0.y = acc[i][1] + bias0.y;
        v0.z = acc[i][2] + bias0.z; v0.w = acc[i][3] + bias0.w;
        v1.x = acc[i][4] + bias1.x; v1.y = acc[i][5] + bias1.y;
        v1.z = acc[i][6] + bias1.z; v1.w = acc[i][7] + bias1.w;
        if (EPI == 1) {
            v0.x = gelu_f(v0.x); v0.y = gelu_f(v0.y); v0.z = gelu_f(v0.z); v0.w = gelu_f(v0.w);
            v1.x = gelu_f(v1.x); v1.y = gelu_f(v1.y); v1.z = gelu_f(v1.z); v1.w = gelu_f(v1.w);
        }
        if (EPI == 2) {
            float4 r0 = *(const float4*)(res + r * N + c0);
            float4 r1 = *(const float4*)(res + r * N + c0 + 64);
            v0.x += r0.x; v0.y += r0.y; v0.z += r0.z; v0.w += r0.w;
            v1.x += r1.x; v1.y += r1.y; v1.z += r1.z; v1.w += r1.w;
        }
        *(float4*)(C + r * N + c0)      = v0;
        *(float4*)(C + r * N + c0 + 64) = v1;
    }
}

template<int EPI>
__global__ void __launch_bounds__(256, 2)
sgemm2_kernel(int M, int N, int K,
              const float* __restrict__ A,
              const float* __restrict__ W,
              const float* __restrict__ bias,
              const float* __restrict__ res,
              float* __restrict__ C)
{
    gemm_body<EPI>(M, N, K, A, W, bias, res, C, blockIdx.x, blockIdx.y);
}

// Fused QKV: grid.x = 3 * (512/128) = 12, which = bx>>2 selects Wq/Wk/Wv
__global__ void __launch_bounds__(256, 2)
sgemm_qkv_kernel(const float* __restrict__ A,
                 const float* __restrict__ Wq, const float* __restrict__ Wk,
                 const float* __restrict__ Wv,
                 const float* __restrict__ bq, const float* __restrict__ bk,
                 const float* __restrict__ bv,
                 float* __restrict__ Cq, float* __restrict__ Ck,
                 float* __restrict__ Cv)
{
    int which = blockIdx.x >> 2;
    int bx = blockIdx.x & 3;
    const float* W = (which == 0) ? Wq : (which == 1) ? Wk : Wv;
    const float* b = (which == 0) ? bq : (which == 1) ? bk : bv;
    float* C       = (which == 0) ? Cq : (which == 1) ? Ck : Cv;
    gemm_body<0>(ROWS, Dz, Dz, A, W, b, nullptr, C, bx, blockIdx.y);
}

// ---------------------------------------------------------------------------
// Per-vector quant-dequant, one warp per 64-elem vector.
// gridDim.y = 2 selects (k, codebook0) vs (v, codebook1).
// ---------------------------------------------------------------------------
__global__ void quantdq_kernel(float* __restrict__ tk, float* __restrict__ tv,
                               const float* __restrict__ lvk,
                               const float* __restrict__ lvv)
{
    __shared__ float lv[8];
    float* t = (blockIdx.y == 0) ? tk : tv;
    const float* levels = (blockIdx.y == 0) ? lvk : lvv;
    if (threadIdx.x < 8) lv[threadIdx.x] = levels[threadIdx.x];
    __syncthreads();
    int warp = threadIdx.x >> 5, lane = threadIdx.x & 31;
    int w = blockIdx.x * 8 + warp;                 // vector id, B*S*H total
    float* p = t + (size_t)(w / Hz) * Dz + (size_t)(w % Hz) * DKz;

    float x0 = p[lane], x1 = p[lane + 32];
    float ss = x0 * x0 + x1 * x1;
    #pragma unroll
    for (int o = 16; o > 0; o >>= 1) ss += __shfl_xor_sync(0xffffffffu, ss, o);
    float nrm = sqrtf(ss);
    float inv = 1.f / (nrm + 1e-8f);
    float u0 = x0 * inv, u1 = x1 * inv;
    float a0 = fabsf(u0), a1 = fabsf(u1);
    float sg0 = (u0 >= 0.f) ? 1.f : -1.f;
    float sg1 = (u1 >= 0.f) ? 1.f : -1.f;

    float q0 = lv[0], b0 = fabsf(a0 - lv[0]);
    float q1 = lv[0], b1 = fabsf(a1 - lv[0]);
    #pragma unroll
    for (int i = 1; i < 8; i++) {
        float d0 = fabsf(a0 - lv[i]);
        if (d0 < b0) { b0 = d0; q0 = lv[i]; }
        float d1 = fabsf(a1 - lv[i]);
        if (d1 < b1) { b1 = d1; q1 = lv[i]; }
    }
    float num = a0 * q0 + a1 * q1;
    float den = q0 * q0 + q1 * q1;
    #pragma unroll
    for (int o = 16; o > 0; o >>= 1) {
        num += __shfl_xor_sync(0xffffffffu, num, o);
        den += __shfl_xor_sync(0xffffffffu, den, o);
    }
    float rmag = num / (den + 1e-8f);
    p[lane]      = sg0 * q0 * rmag * nrm;
    p[lane + 32] = sg1 * q1 * rmag * nrm;
}

// ---------------------------------------------------------------------------
// Causal attention with softcap + count bias, 64q x 64k tiles.
// Softcap bounds scores to [-30,30] -> exp never overflows -> no online max.
// ---------------------------------------------------------------------------
#define ATTN_SMEM (4*64*65*4 + 64*4*3)

__global__ void __launch_bounds__(256, 1)
attn_kernel(const float* __restrict__ gq, const float* __restrict__ gk,
            const float* __restrict__ gv, float* __restrict__ go,
            const float* __restrict__ cb, const int* __restrict__ keep)
{
    extern __shared__ float sm[];
    float (*Qs)[65] = (float(*)[65])(sm);
    float (*Ks)[65] = (float(*)[65])(sm + 64*65);
    float (*Vs)[65] = (float(*)[65])(sm + 2*64*65);
    float (*Ps)[65] = (float(*)[65])(sm + 3*64*65);
    float* dens = sm + 4*64*65;
    float* cbk  = dens + 64;
    int*   kpk  = (int*)(cbk + 64);

    int qt = blockIdx.x;          // query tile 0..15
    int bh = blockIdx.y;          // 0..31
    int b = bh / Hz, h = bh % Hz;
    int q0 = qt * 64;
    int tid = threadIdx.x;
    int tx = tid & 15, ty = tid >> 4;
    const float scale = 0.125f;   // 1/sqrt(64)

    const float* qbase = gq + ((size_t)(b * Sz + q0)) * Dz + h * DKz;
    #pragma unroll
    for (int i = 0; i < 4; i++) {
        int idx = tid + i * 256;
        int qi = idx >> 4, d4 = (idx & 15) * 4;
        float4 v4 = *(const float4*)(qbase + (size_t)qi * Dz + d4);
        Qs[qi][d4] = v4.x; Qs[qi][d4+1] = v4.y; Qs[qi][d4+2] = v4.z; Qs[qi][d4+3] = v4.w;
    }
    if (tid < 64) dens[tid] = 0.f;

    float acc[4][4];
    #pragma unroll
    for (int i = 0; i < 4; i++)
        #pragma unroll
        for (int j = 0; j < 4; j++) acc[i][j] = 0.f;

    for (int kt = 0; kt <= qt; kt++) {
        int k0 = kt * 64;
        __syncthreads();   // previous-iter reads done (and Q/den init on first iter)
        const float* kbase = gk + ((size_t)(b * Sz + k0)) * Dz + h * DKz;
        const float* vbase = gv + ((size_t)(b * Sz + k0)) * Dz + h * DKz;
        #pragma unroll
        for (int i = 0; i < 4; i++) {
            int idx = tid + i * 256;
            int r = idx >> 4, d4 = (idx & 15) * 4;
            float4 kv = *(const float4*)(kbase + (size_t)r * Dz + d4);
            Ks[r][d4] = kv.x; Ks[r][d4+1] = kv.y; Ks[r][d4+2] = kv.z; Ks[r][d4+3] = kv.w;
            float4 vv = *(const float4*)(vbase + (size_t)r * Dz + d4);
            Vs[r][d4] = vv.x; Vs[r][d4+1] = vv.y; Vs[r][d4+2] = vv.z; Vs[r][d4+3] = vv.w;
        }
        if (tid < 64) {
            cbk[tid] = cb[b * Sz + k0 + tid];
            kpk[tid] = keep[b * Sz + k0 + tid];
        }
        __syncthreads();

        float s[4][4];
        #pragma unroll
        for (int i = 0; i < 4; i++)
            #pragma unroll
            for (int j = 0; j < 4; j++) s[i][j] = 0.f;
        #pragma unroll 8
        for (int kk = 0; kk < 64; kk++) {
            float rq[4], rk[4];
            #pragma unroll
            for (int i = 0; i < 4; i++) rq[i] = Qs[ty*4 + i][kk];
            #pragma unroll
            for (int j = 0; j < 4; j++) rk[j] = Ks[tx*4 + j][kk];
            #pragma unroll
            for (int i = 0; i < 4; i++)
                #pragma unroll
                for (int j = 0; j < 4; j++) s[i][j] += rq[i] * rk[j];
        }
        #pragma unroll
        for (int i = 0; i < 4; i++) {
            int qg = q0 + ty*4 + i;
            #pragma unroll
            for (int j = 0; j < 4; j++) {
                int kg = k0 + tx*4 + j;
                float p = 0.f;
                if (kg <= qg && kpk[tx*4 + j]) {
                    float z = (s[i][j] * scale + cbk[tx*4 + j]) * (1.0f / SOFTCAP);
                    p = expf(tanhf(z) * SOFTCAP);
                }
                Ps[ty*4 + i][tx*4 + j] = p;
            }
        }
        __syncthreads();
        if (tid < 64) {
            float sum = 0.f;
            #pragma unroll 8
            for (int kk = 0; kk < 64; kk++) sum += Ps[tid][kk];
            dens[tid] += sum;
        }
        #pragma unroll 8
        for (int kk = 0; kk < 64; kk++) {
            float rp[4], rv[4];
            #pragma unroll
            for (int i = 0; i < 4; i++) rp[i] = Ps[ty*4 + i][kk];
            #pragma unroll
            for (int j = 0; j < 4; j++) rv[j] = Vs[kk][tx*4 + j];
            #pragma unroll
            for (int i = 0; i < 4; i++)
                #pragma unroll
                for (int j = 0; j < 4; j++) acc[i][j] += rp[i] * rv[j];
        }
    }
    __syncthreads();
    float* obase = go + ((size_t)(b * Sz + q0)) * Dz + h * DKz;
    #pragma unroll
    for (int i = 0; i < 4; i++) {
        float dinv = 1.f / dens[ty*4 + i];
        #pragma unroll
        for (int j = 0; j < 4; j++)
            obase[(size_t)(ty*4 + i) * Dz + tx*4 + j] = acc[i][j] * dinv;
    }
}

// ---------------------------------------------------------------------------
// Host launcher
// ---------------------------------------------------------------------------
extern "C" void kernel_launch(void* const* d_in, const int* in_sizes, int n_in,
                              void* d_out, int out_size)
{
    const int*   tok  = (const int*)  d_in[0];
    const float* cnt  = (const float*)d_in[1];
    const float* emb  = (const float*)d_in[2];
    const float* Wq   = (const float*)d_in[3];
    const float* bq   = (const float*)d_in[4];
    const float* Wk   = (const float*)d_in[5];
    const float* bk   = (const float*)d_in[6];
    const float* Wv   = (const float*)d_in[7];
    const float* bv   = (const float*)d_in[8];
    const float* Wo   = (const float*)d_in[9];
    const float* bo   = (const float*)d_in[10];
    const float* ln1g = (const float*)d_in[11];
    const float* ln1b = (const float*)d_in[12];
    const float* ln2g = (const float*)d_in[13];
    const float* ln2b = (const float*)d_in[14];
    const float* W1   = (const float*)d_in[15];
    const float* b1   = (const float*)d_in[16];
    const float* W2   = (const float*)d_in[17];
    const float* b2   = (const float*)d_in[18];
    const float* cbk  = (const float*)d_in[19];
    float* out = (float*)d_out;

    cudaFuncSetAttribute(attn_kernel, cudaFuncAttributeMaxDynamicSharedMemorySize, ATTN_SMEM);

    float *px, *pxn, *pq, *pk, *pv, *po, *ph1, *pcb;
    int *pkeep;
    cudaGetSymbolAddress((void**)&px,   g_x);
    cudaGetSymbolAddress((void**)&pxn,  g_xn);
    cudaGetSymbolAddress((void**)&pq,   g_q);
    cudaGetSymbolAddress((void**)&pk,   g_k);
    cudaGetSymbolAddress((void**)&pv,   g_v);
    cudaGetSymbolAddress((void**)&po,   g_o);
    cudaGetSymbolAddress((void**)&ph1,  g_h1);
    cudaGetSymbolAddress((void**)&pcb,  g_cb);
    cudaGetSymbolAddress((void**)&pkeep, g_keep);

    embed_kernel<<<ROWS, 128>>>(tok, cnt, emb);

    dim3 gD(Dz / 128, ROWS / 128);      // N=512 GEMMs   (4 x 32)
    dim3 gQKV(12, ROWS / 128);          // fused QKV     (12 x 32)
    dim3 gF(DFFz / 128, ROWS / 128);    // N=2048 GEMM   (16 x 32)

    for (int l = 0; l < Lz; l++) {
        const float* wq = Wq + (size_t)l * Dz * Dz;
        const float* wk = Wk + (size_t)l * Dz * Dz;
        const float* wv = Wv + (size_t)l * Dz * Dz;
        const float* wo = Wo + (size_t)l * Dz * Dz;
        const float* w1 = W1 + (size_t)l * Dz * DFFz;
        const float* w2 = W2 + (size_t)l * DFFz * Dz;

        layernorm_kernel<<<ROWS, 128>>>(px, ln1g + l*Dz, ln1b + l*Dz, pxn);

        sgemm_qkv_kernel<<<gQKV, 256>>>(pxn, wq, wk, wv,
                                        bq + l*Dz, bk + l*Dz, bv + l*Dz,
                                        pq, pk, pv);

        quantdq_kernel<<<dim3(ROWS * Hz / 8, 2), 256>>>(
            pk, pv, cbk + (size_t)(l*2 + 0)*8, cbk + (size_t)(l*2 + 1)*8);

        attn_kernel<<<dim3(Sz/64, Bz*Hz), 256, ATTN_SMEM>>>(pq, pk, pv, po, pcb, pkeep);

        // x = o @ Wo + bo + xn
        sgemm2_kernel<2><<<gD, 256>>>(ROWS, Dz, Dz, po, wo, bo + l*Dz, pxn, px);

        layernorm_kernel<<<ROWS, 128>>>(px, ln2g + l*Dz, ln2b + l*Dz, pxn);

        // h1 = gelu(xn2 @ W1 + b1)
        sgemm2_kernel<1><<<gF, 256>>>(ROWS, DFFz, Dz, pxn, w1, b1 + l*DFFz, nullptr, ph1);

        // x = h1 @ W2 + b2 + xn2   (last layer writes straight to d_out)
        float* dst = (l == Lz - 1) ? out : px;
        sgemm2_kernel<2><<<gD, 256>>>(ROWS, Dz, DFFz, ph1, w2, b2 + l*Dz, pxn, dst);
    }
}

// round 4
// speedup vs baseline: 1.8582x; 1.3612x over previous
#include <cuda_runtime.h>
#include <cuda_bf16.h>
#include <cstdint>

// Problem constants
#define Bz 4
#define Sz 1024
#define Dz 512
#define Hz 8
#define DKz 64
#define Lz 4
#define DFFz 2048
#define SOFTCAP 30.0f
#define PAD_IDX 0
#define START_IDX 1

#define ROWS (Bz*Sz)           // 4096
#define XSZ  (ROWS*Dz)         // 2,097,152
#define H1SZ (ROWS*DFFz)       // 8,388,608

// Persistent scratch (allocation-free per harness rules)
__device__ float g_x[XSZ];
__device__ float g_xn[XSZ];
__device__ float g_q[XSZ];
__device__ float g_k[XSZ];
__device__ float g_v[XSZ];
__device__ float g_o[XSZ];
__device__ float g_h1[H1SZ];
__device__ float g_cb[ROWS];
__device__ int   g_keep[ROWS];

// ---------------------------------------------------------------------------
// Embedding + right-shift + count bias + keep mask
// ---------------------------------------------------------------------------
__global__ void embed_kernel(const int* __restrict__ tok,
                             const float* __restrict__ cnt,
                             const float* __restrict__ emb)
{
    int r = blockIdx.x;           // 0..ROWS-1
    int b = r / Sz, s = r % Sz;
    int t;
    float c;
    if (s == 0) { t = START_IDX; c = 1.0f; }
    else        { t = tok[b*Sz + s - 1]; c = cnt[b*Sz + s - 1]; }
    if (threadIdx.x == 0) {
        g_cb[r]   = log1pf(c + 1e-6f);
        g_keep[r] = (t != PAD_IDX);
    }
    const float4* src = (const float4*)(emb + (size_t)t * Dz);
    float4* dst = (float4*)(g_x + (size_t)r * Dz);
    dst[threadIdx.x] = src[threadIdx.x];   // 128 threads * float4 = 512
}

// ---------------------------------------------------------------------------
// LayerNorm (two-pass, exact mean/var), D=512, 128 threads/row
// ---------------------------------------------------------------------------
__device__ __forceinline__ float block_reduce_sum(float v, float* red)
{
    int lane = threadIdx.x & 31, warp = threadIdx.x >> 5;
    #pragma unroll
    for (int o = 16; o > 0; o >>= 1) v += __shfl_xor_sync(0xffffffffu, v, o);
    if (lane == 0) red[warp] = v;
    __syncthreads();
    float r = 0.f;
    if (warp == 0) {
        r = (lane < (blockDim.x >> 5)) ? red[lane] : 0.f;
        #pragma unroll
        for (int o = 16; o > 0; o >>= 1) r += __shfl_xor_sync(0xffffffffu, r, o);
        if (lane == 0) red[0] = r;
    }
    __syncthreads();
    r = red[0];
    __syncthreads();
    return r;
}

__global__ void layernorm_kernel(const float* __restrict__ x,
                                 const float* __restrict__ gam,
                                 const float* __restrict__ bet,
                                 float* __restrict__ out)
{
    __shared__ float red[32];
    int r = blockIdx.x;
    const float4* xr = (const float4*)(x + (size_t)r * Dz);
    float4 v = xr[threadIdx.x];
    float s = v.x + v.y + v.z + v.w;
    float tot = block_reduce_sum(s, red);
    float mu = tot * (1.0f / Dz);
    float d0 = v.x - mu, d1 = v.y - mu, d2 = v.z - mu, d3 = v.w - mu;
    float sq = d0*d0 + d1*d1 + d2*d2 + d3*d3;
    float var = block_reduce_sum(sq, red) * (1.0f / Dz);
    float rstd = rsqrtf(var + 1e-5f);
    float4 gg = ((const float4*)gam)[threadIdx.x];
    float4 bb = ((const float4*)bet)[threadIdx.x];
    float4 o;
    o.x = d0 * rstd * gg.x + bb.x;
    o.y = d1 * rstd * gg.y + bb.y;
    o.z = d2 * rstd * gg.z + bb.z;
    o.w = d3 * rstd * gg.w + bb.w;
    ((float4*)(out + (size_t)r * Dz))[threadIdx.x] = o;
}

// ---------------------------------------------------------------------------
// BF16 3-term split tensor-core GEMM (Ozaki-style):
//   x = hi + lo, hi=bf16(x), lo=bf16(x-hi);  A@B ~= Ah@Bh + Ah@Bl + Al@Bh
// BM=128 BN=128 BK=16, 8 warps, warp tile 64x32, mma.m16n8k16 bf16,
// fp32 accumulate. k-pairs packed in uint32 (low half = even k).
// EPI 0: +bias   EPI 1: gelu(+bias)   EPI 2: +bias + res[M,N]
// ---------------------------------------------------------------------------
__device__ __forceinline__ float gelu_f(float x)
{
    float x3 = x * x * x;
    return 0.5f * x * (1.f + tanhf(0.7978845608028654f * (x + 0.044715f * x3)));
}

// pack bf16 pair: lo16 = bf16(x), hi16 = bf16(y)
__device__ __forceinline__ void split2(float x, float y, uint32_t& hi, uint32_t& lo)
{
    __nv_bfloat16 hx = __float2bfloat16_rn(x);
    __nv_bfloat16 hy = __float2bfloat16_rn(y);
    float rx = x - __bfloat162float(hx);
    float ry = y - __bfloat162float(hy);
    __nv_bfloat16 lx = __float2bfloat16_rn(rx);
    __nv_bfloat16 ly = __float2bfloat16_rn(ry);
    uint16_t uhx = *reinterpret_cast<uint16_t*>(&hx);
    uint16_t uhy = *reinterpret_cast<uint16_t*>(&hy);
    uint16_t ulx = *reinterpret_cast<uint16_t*>(&lx);
    uint16_t uly = *reinterpret_cast<uint16_t*>(&ly);
    hi = (uint32_t)uhx | ((uint32_t)uhy << 16);
    lo = (uint32_t)ulx | ((uint32_t)uly << 16);
}

#define MMA_BF16(d, a0, a1, a2, a3, b0, b1) \
    asm volatile("mma.sync.aligned.m16n8k16.row.col.f32.bf16.bf16.f32 " \
        "{%0,%1,%2,%3},{%4,%5,%6,%7},{%8,%9},{%0,%1,%2,%3};" \
        : "+f"(d[0]), "+f"(d[1]), "+f"(d[2]), "+f"(d[3]) \
        : "r"(a0), "r"(a1), "r"(a2), "r"(a3), "r"(b0), "r"(b1))

template<int EPI>
__device__ __forceinline__ void gemm_body(
    int M, int N, int K,
    const float* __restrict__ A,
    const float* __restrict__ W,
    const float* __restrict__ bias,
    const float* __restrict__ res,
    float* __restrict__ C,
    int bx, int by)
{
    const int BM = 128, BN = 128, BK = 16;
    const int KP = BK / 2;                 // 8 packed k-pairs
    const int PAD = 136;                   // bank = tig*8 + gid, conflict-free
    __shared__ uint32_t AsH[2][KP][PAD];
    __shared__ uint32_t AsL[2][KP][PAD];
    __shared__ uint32_t BsH[2][KP][PAD];
    __shared__ uint32_t BsL[2][KP][PAD];

    int tid  = threadIdx.x;
    int lane = tid & 31, warp = tid >> 5;
    int wm = warp >> 2, wn = warp & 3;     // warp tile: (wm*64, wn*32)
    int gid = lane >> 2, tig = lane & 3;

    const float* Ab = A + (size_t)by * BM * K;
    const float* Wb = W + (size_t)bx * BN;

    int aRow = tid & 127, aHalf = tid >> 7;      // A: 8 consecutive k per thread
    int bG = tid >> 5, bCol = (tid & 31) * 4;    // B: k-rows 2g,2g+1, 4 n's

    float acc[4][4][4];
    #pragma unroll
    for (int mt = 0; mt < 4; mt++)
        #pragma unroll
        for (int nt = 0; nt < 4; nt++)
            #pragma unroll
            for (int i = 0; i < 4; i++) acc[mt][nt][i] = 0.f;

    float4 la0, la1, lb0, lb1;

    // prologue: k0 = 0
    la0 = *(const float4*)(Ab + (size_t)aRow * K + aHalf * 8);
    la1 = *(const float4*)(Ab + (size_t)aRow * K + aHalf * 8 + 4);
    lb0 = *(const float4*)(Wb + (size_t)(2 * bG) * N + bCol);
    lb1 = *(const float4*)(Wb + (size_t)(2 * bG + 1) * N + bCol);
    {
        int p = aHalf * 4;
        uint32_t h, l;
        split2(la0.x, la0.y, h, l); AsH[0][p+0][aRow] = h; AsL[0][p+0][aRow] = l;
        split2(la0.z, la0.w, h, l); AsH[0][p+1][aRow] = h; AsL[0][p+1][aRow] = l;
        split2(la1.x, la1.y, h, l); AsH[0][p+2][aRow] = h; AsL[0][p+2][aRow] = l;
        split2(la1.z, la1.w, h, l); AsH[0][p+3][aRow] = h; AsL[0][p+3][aRow] = l;
        uint4 ph, pl;
        split2(lb0.x, lb1.x, ph.x, pl.x);
        split2(lb0.y, lb1.y, ph.y, pl.y);
        split2(lb0.z, lb1.z, ph.z, pl.z);
        split2(lb0.w, lb1.w, ph.w, pl.w);
        *(uint4*)&BsH[0][bG][bCol] = ph;
        *(uint4*)&BsL[0][bG][bCol] = pl;
    }
    __syncthreads();

    int buf = 0;
    for (int k0 = BK; ; k0 += BK) {
        bool more = (k0 < K);
        if (more) {
            la0 = *(const float4*)(Ab + (size_t)aRow * K + k0 + aHalf * 8);
            la1 = *(const float4*)(Ab + (size_t)aRow * K + k0 + aHalf * 8 + 4);
            lb0 = *(const float4*)(Wb + (size_t)(k0 + 2 * bG) * N + bCol);
            lb1 = *(const float4*)(Wb + (size_t)(k0 + 2 * bG + 1) * N + bCol);
        }
        // one k16 MMA step covering pairs 0..7
        {
            uint32_t bh[4][2], bl[4][2];
            #pragma unroll
            for (int nt = 0; nt < 4; nt++) {
                int n = wn * 32 + nt * 8 + gid;
                bh[nt][0] = BsH[buf][tig    ][n];
                bh[nt][1] = BsH[buf][tig + 4][n];
                bl[nt][0] = BsL[buf][tig    ][n];
                bl[nt][1] = BsL[buf][tig + 4][n];
            }
            #pragma unroll
            for (int mt = 0; mt < 4; mt++) {
                int m = wm * 64 + mt * 16 + gid;
                uint32_t ah0 = AsH[buf][tig    ][m];
                uint32_t ah1 = AsH[buf][tig    ][m + 8];
                uint32_t ah2 = AsH[buf][tig + 4][m];
                uint32_t ah3 = AsH[buf][tig + 4][m + 8];
                uint32_t al0 = AsL[buf][tig    ][m];
                uint32_t al1 = AsL[buf][tig    ][m + 8];
                uint32_t al2 = AsL[buf][tig + 4][m];
                uint32_t al3 = AsL[buf][tig + 4][m + 8];
                #pragma unroll
                for (int nt = 0; nt < 4; nt++) {
                    MMA_BF16(acc[mt][nt], ah0, ah1, ah2, ah3, bh[nt][0], bh[nt][1]);
                    MMA_BF16(acc[mt][nt], ah0, ah1, ah2, ah3, bl[nt][0], bl[nt][1]);
                    MMA_BF16(acc[mt][nt], al0, al1, al2, al3, bh[nt][0], bh[nt][1]);
                }
            }
        }
        if (!more) break;
        int nb = buf ^ 1;
        {
            int p = aHalf * 4;
            uint32_t h, l;
            split2(la0.x, la0.y, h, l); AsH[nb][p+0][aRow] = h; AsL[nb][p+0][aRow] = l;
            split2(la0.z, la0.w, h, l); AsH[nb][p+1][aRow] = h; AsL[nb][p+1][aRow] = l;
            split2(la1.x, la1.y, h, l); AsH[nb][p+2][aRow] = h; AsL[nb][p+2][aRow] = l;
            split2(la1.z, la1.w, h, l); AsH[nb][p+3][aRow] = h; AsL[nb][p+3][aRow] = l;
            uint4 ph, pl;
            split2(lb0.x, lb1.x, ph.x, pl.x);
            split2(lb0.y, lb1.y, ph.y, pl.y);
            split2(lb0.z, lb1.z, ph.z, pl.z);
            split2(lb0.w, lb1.w, ph.w, pl.w);
            *(uint4*)&BsH[nb][bG][bCol] = ph;
            *(uint4*)&BsL[nb][bG][bCol] = pl;
        }
        __syncthreads();
        buf = nb;
    }

    // Epilogue: acc[mt][nt] = {(r,c),(r,c+1),(r+8,c),(r+8,c+1)}, c = 2*tig pair
    size_t rowBase = (size_t)by * BM + wm * 64;
    size_t colBase = (size_t)bx * BN + wn * 32;
    #pragma unroll
    for (int nt = 0; nt < 4; nt++) {
        size_t c = colBase + nt * 8 + tig * 2;
        float2 bb = *(const float2*)(bias + c);
        #pragma unroll
        for (int mt = 0; mt < 4; mt++) {
            size_t r0 = rowBase + mt * 16 + gid;
            size_t r1 = r0 + 8;
            float2 v0, v1;
            v0.x = acc[mt][nt][0] + bb.x; v0.y = acc[mt][nt][1] + bb.y;
            v1.x = acc[mt][nt][2] + bb.x; v1.y = acc[mt][nt][3] + bb.y;
            if (EPI == 1) {
                v0.x = gelu_f(v0.x); v0.y = gelu_f(v0.y);
                v1.x = gelu_f(v1.x); v1.y = gelu_f(v1.y);
            }
            if (EPI == 2) {
                float2 q0 = *(const float2*)(res + r0 * N + c);
                float2 q1 = *(const float2*)(res + r1 * N + c);
                v0.x += q0.x; v0.y += q0.y;
                v1.x += q1.x; v1.y += q1.y;
            }
            *(float2*)(C + r0 * N + c) = v0;
            *(float2*)(C + r1 * N + c) = v1;
        }
    }
}

template<int EPI>
__global__ void __launch_bounds__(256, 2)
sgemm2_kernel(int M, int N, int K,
              const float* __restrict__ A,
              const float* __restrict__ W,
              const float* __restrict__ bias,
              const float* __restrict__ res,
              float* __restrict__ C)
{
    gemm_body<EPI>(M, N, K, A, W, bias, res, C, blockIdx.x, blockIdx.y);
}

// Fused QKV: grid.x = 3 * (512/128) = 12, which = bx>>2 selects Wq/Wk/Wv
__global__ void __launch_bounds__(256, 2)
sgemm_qkv_kernel(const float* __restrict__ A,
                 const float* __restrict__ Wq, const float* __restrict__ Wk,
                 const float* __restrict__ Wv,
                 const float* __restrict__ bq, const float* __restrict__ bk,
                 const float* __restrict__ bv,
                 float* __restrict__ Cq, float* __restrict__ Ck,
                 float* __restrict__ Cv)
{
    int which = blockIdx.x >> 2;
    int bx = blockIdx.x & 3;
    const float* W = (which == 0) ? Wq : (which == 1) ? Wk : Wv;
    const float* b = (which == 0) ? bq : (which == 1) ? bk : bv;
    float* C       = (which == 0) ? Cq : (which == 1) ? Ck : Cv;
    gemm_body<0>(ROWS, Dz, Dz, A, W, b, nullptr, C, bx, blockIdx.y);
}

// ---------------------------------------------------------------------------
// Per-vector quant-dequant, one warp per 64-elem vector.
// gridDim.y = 2 selects (k, codebook0) vs (v, codebook1).
// ---------------------------------------------------------------------------
__global__ void quantdq_kernel(float* __restrict__ tk, float* __restrict__ tv,
                               const float* __restrict__ lvk,
                               const float* __restrict__ lvv)
{
    __shared__ float lv[8];
    float* t = (blockIdx.y == 0) ? tk : tv;
    const float* levels = (blockIdx.y == 0) ? lvk : lvv;
    if (threadIdx.x < 8) lv[threadIdx.x] = levels[threadIdx.x];
    __syncthreads();
    int warp = threadIdx.x >> 5, lane = threadIdx.x & 31;
    int w = blockIdx.x * 8 + warp;                 // vector id, B*S*H total
    float* p = t + (size_t)(w / Hz) * Dz + (size_t)(w % Hz) * DKz;

    float x0 = p[lane], x1 = p[lane + 32];
    float ss = x0 * x0 + x1 * x1;
    #pragma unroll
    for (int o = 16; o > 0; o >>= 1) ss += __shfl_xor_sync(0xffffffffu, ss, o);
    float nrm = sqrtf(ss);
    float inv = 1.f / (nrm + 1e-8f);
    float u0 = x0 * inv, u1 = x1 * inv;
    float a0 = fabsf(u0), a1 = fabsf(u1);
    float sg0 = (u0 >= 0.f) ? 1.f : -1.f;
    float sg1 = (u1 >= 0.f) ? 1.f : -1.f;

    float q0 = lv[0], b0 = fabsf(a0 - lv[0]);
    float q1 = lv[0], b1 = fabsf(a1 - lv[0]);
    #pragma unroll
    for (int i = 1; i < 8; i++) {
        float d0 = fabsf(a0 - lv[i]);
        if (d0 < b0) { b0 = d0; q0 = lv[i]; }
        float d1 = fabsf(a1 - lv[i]);
        if (d1 < b1) { b1 = d1; q1 = lv[i]; }
    }
    float num = a0 * q0 + a1 * q1;
    float den = q0 * q0 + q1 * q1;
    #pragma unroll
    for (int o = 16; o > 0; o >>= 1) {
        num += __shfl_xor_sync(0xffffffffu, num, o);
        den += __shfl_xor_sync(0xffffffffu, den, o);
    }
    float rmag = num / (den + 1e-8f);
    p[lane]      = sg0 * q0 * rmag * nrm;
    p[lane + 32] = sg1 * q1 * rmag * nrm;
}

// ---------------------------------------------------------------------------
// Causal attention with softcap + count bias, 64q x 64k tiles.
// Softcap bounds scores to [-30,30] -> exp never overflows -> no online max.
// ---------------------------------------------------------------------------
#define ATTN_SMEM (4*64*65*4 + 64*4*3)

__global__ void __launch_bounds__(256, 1)
attn_kernel(const float* __restrict__ gq, const float* __restrict__ gk,
            const float* __restrict__ gv, float* __restrict__ go,
            const float* __restrict__ cb, const int* __restrict__ keep)
{
    extern __shared__ float sm[];
    float (*Qs)[65] = (float(*)[65])(sm);
    float (*Ks)[65] = (float(*)[65])(sm + 64*65);
    float (*Vs)[65] = (float(*)[65])(sm + 2*64*65);
    float (*Ps)[65] = (float(*)[65])(sm + 3*64*65);
    float* dens = sm + 4*64*65;
    float* cbk  = dens + 64;
    int*   kpk  = (int*)(cbk + 64);

    int qt = blockIdx.x;          // query tile 0..15
    int bh = blockIdx.y;          // 0..31
    int b = bh / Hz, h = bh % Hz;
    int q0 = qt * 64;
    int tid = threadIdx.x;
    int tx = tid & 15, ty = tid >> 4;
    const float scale = 0.125f;   // 1/sqrt(64)

    const float* qbase = gq + ((size_t)(b * Sz + q0)) * Dz + h * DKz;
    #pragma unroll
    for (int i = 0; i < 4; i++) {
        int idx = tid + i * 256;
        int qi = idx >> 4, d4 = (idx & 15) * 4;
        float4 v4 = *(const float4*)(qbase + (size_t)qi * Dz + d4);
        Qs[qi][d4] = v4.x; Qs[qi][d4+1] = v4.y; Qs[qi][d4+2] = v4.z; Qs[qi][d4+3] = v4.w;
    }
    if (tid < 64) dens[tid] = 0.f;

    float acc[4][4];
    #pragma unroll
    for (int i = 0; i < 4; i++)
        #pragma unroll
        for (int j = 0; j < 4; j++) acc[i][j] = 0.f;

    for (int kt = 0; kt <= qt; kt++) {
        int k0 = kt * 64;
        __syncthreads();   // previous-iter reads done (and Q/den init on first iter)
        const float* kbase = gk + ((size_t)(b * Sz + k0)) * Dz + h * DKz;
        const float* vbase = gv + ((size_t)(b * Sz + k0)) * Dz + h * DKz;
        #pragma unroll
        for (int i = 0; i < 4; i++) {
            int idx = tid + i * 256;
            int r = idx >> 4, d4 = (idx & 15) * 4;
            float4 kv = *(const float4*)(kbase + (size_t)r * Dz + d4);
            Ks[r][d4] = kv.x; Ks[r][d4+1] = kv.y; Ks[r][d4+2] = kv.z; Ks[r][d4+3] = kv.w;
            float4 vv = *(const float4*)(vbase + (size_t)r * Dz + d4);
            Vs[r][d4] = vv.x; Vs[r][d4+1] = vv.y; Vs[r][d4+2] = vv.z; Vs[r][d4+3] = vv.w;
        }
        if (tid < 64) {
            cbk[tid] = cb[b * Sz + k0 + tid];
            kpk[tid] = keep[b * Sz + k0 + tid];
        }
        __syncthreads();

        float s[4][4];
        #pragma unroll
        for (int i = 0; i < 4; i++)
            #pragma unroll
            for (int j = 0; j < 4; j++) s[i][j] = 0.f;
        #pragma unroll 8
        for (int kk = 0; kk < 64; kk++) {
            float rq[4], rk[4];
            #pragma unroll
            for (int i = 0; i < 4; i++) rq[i] = Qs[ty*4 + i][kk];
            #pragma unroll
            for (int j = 0; j < 4; j++) rk[j] = Ks[tx*4 + j][kk];
            #pragma unroll
            for (int i = 0; i < 4; i++)
                #pragma unroll
                for (int j = 0; j < 4; j++) s[i][j] += rq[i] * rk[j];
        }
        #pragma unroll
        for (int i = 0; i < 4; i++) {
            int qg = q0 + ty*4 + i;
            #pragma unroll
            for (int j = 0; j < 4; j++) {
                int kg = k0 + tx*4 + j;
                float p = 0.f;
                if (kg <= qg && kpk[tx*4 + j]) {
                    float z = (s[i][j] * scale + cbk[tx*4 + j]) * (1.0f / SOFTCAP);
                    p = expf(tanhf(z) * SOFTCAP);
                }
                Ps[ty*4 + i][tx*4 + j] = p;
            }
        }
        __syncthreads();
        if (tid < 64) {
            float sum = 0.f;
            #pragma unroll 8
            for (int kk = 0; kk < 64; kk++) sum += Ps[tid][kk];
            dens[tid] += sum;
        }
        #pragma unroll 8
        for (int kk = 0; kk < 64; kk++) {
            float rp[4], rv[4];
            #pragma unroll
            for (int i = 0; i < 4; i++) rp[i] = Ps[ty*4 + i][kk];
            #pragma unroll
            for (int j = 0; j < 4; j++) rv[j] = Vs[kk][tx*4 + j];
            #pragma unroll
            for (int i = 0; i < 4; i++)
                #pragma unroll
                for (int j = 0; j < 4; j++) acc[i][j] += rp[i] * rv[j];
        }
    }
    __syncthreads();
    float* obase = go + ((size_t)(b * Sz + q0)) * Dz + h * DKz;
    #pragma unroll
    for (int i = 0; i < 4; i++) {
        float dinv = 1.f / dens[ty*4 + i];
        #pragma unroll
        for (int j = 0; j < 4; j++)
            obase[(size_t)(ty*4 + i) * Dz + tx*4 + j] = acc[i][j] * dinv;
    }
}

// ---------------------------------------------------------------------------
// Host launcher
// ---------------------------------------------------------------------------
extern "C" void kernel_launch(void* const* d_in, const int* in_sizes, int n_in,
                              void* d_out, int out_size)
{
    const int*   tok  = (const int*)  d_in[0];
    const float* cnt  = (const float*)d_in[1];
    const float* emb  = (const float*)d_in[2];
    const float* Wq   = (const float*)d_in[3];
    const float* bq   = (const float*)d_in[4];
    const float* Wk   = (const float*)d_in[5];
    const float* bk   = (const float*)d_in[6];
    const float* Wv   = (const float*)d_in[7];
    const float* bv   = (const float*)d_in[8];
    const float* Wo   = (const float*)d_in[9];
    const float* bo   = (const float*)d_in[10];
    const float* ln1g = (const float*)d_in[11];
    const float* ln1b = (const float*)d_in[12];
    const float* ln2g = (const float*)d_in[13];
    const float* ln2b = (const float*)d_in[14];
    const float* W1   = (const float*)d_in[15];
    const float* b1   = (const float*)d_in[16];
    const float* W2   = (const float*)d_in[17];
    const float* b2   = (const float*)d_in[18];
    const float* cbk  = (const float*)d_in[19];
    float* out = (float*)d_out;

    cudaFuncSetAttribute(attn_kernel, cudaFuncAttributeMaxDynamicSharedMemorySize, ATTN_SMEM);

    float *px, *pxn, *pq, *pk, *pv, *po, *ph1, *pcb;
    int *pkeep;
    cudaGetSymbolAddress((void**)&px,   g_x);
    cudaGetSymbolAddress((void**)&pxn,  g_xn);
    cudaGetSymbolAddress((void**)&pq,   g_q);
    cudaGetSymbolAddress((void**)&pk,   g_k);
    cudaGetSymbolAddress((void**)&pv,   g_v);
    cudaGetSymbolAddress((void**)&po,   g_o);
    cudaGetSymbolAddress((void**)&ph1,  g_h1);
    cudaGetSymbolAddress((void**)&pcb,  g_cb);
    cudaGetSymbolAddress((void**)&pkeep, g_keep);

    embed_kernel<<<ROWS, 128>>>(tok, cnt, emb);

    dim3 gD(Dz / 128, ROWS / 128);      // N=512 GEMMs   (4 x 32)
    dim3 gQKV(12, ROWS / 128);          // fused QKV     (12 x 32)
    dim3 gF(DFFz / 128, ROWS / 128);    // N=2048 GEMM   (16 x 32)

    for (int l = 0; l < Lz; l++) {
        const float* wq = Wq + (size_t)l * Dz * Dz;
        const float* wk = Wk + (size_t)l * Dz * Dz;
        const float* wv = Wv + (size_t)l * Dz * Dz;
        const float* wo = Wo + (size_t)l * Dz * Dz;
        const float* w1 = W1 + (size_t)l * Dz * DFFz;
        const float* w2 = W2 + (size_t)l * DFFz * Dz;

        layernorm_kernel<<<ROWS, 128>>>(px, ln1g + l*Dz, ln1b + l*Dz, pxn);

        sgemm_qkv_kernel<<<gQKV, 256>>>(pxn, wq, wk, wv,
                                        bq + l*Dz, bk + l*Dz, bv + l*Dz,
                                        pq, pk, pv);

        quantdq_kernel<<<dim3(ROWS * Hz / 8, 2), 256>>>(
            pk, pv, cbk + (size_t)(l*2 + 0)*8, cbk + (size_t)(l*2 + 1)*8);

        attn_kernel<<<dim3(Sz/64, Bz*Hz), 256, ATTN_SMEM>>>(pq, pk, pv, po, pcb, pkeep);

        // x = o @ Wo + bo + xn
        sgemm2_kernel<2><<<gD, 256>>>(ROWS, Dz, Dz, po, wo, bo + l*Dz, pxn, px);

        layernorm_kernel<<<ROWS, 128>>>(px, ln2g + l*Dz, ln2b + l*Dz, pxn);

        // h1 = gelu(xn2 @ W1 + b1)
        sgemm2_kernel<1><<<gF, 256>>>(ROWS, DFFz, Dz, pxn, w1, b1 + l*DFFz, nullptr, ph1);

        // x = h1 @ W2 + b2 + xn2   (last layer writes straight to d_out)
        float* dst = (l == Lz - 1) ? out : px;
        sgemm2_kernel<2><<<gD, 256>>>(ROWS, Dz, DFFz, ph1, w2, b2 + l*Dz, pxn, dst);
    }
}

// round 5
// speedup vs baseline: 1.9365x; 1.0421x over previous
#include <cuda_runtime.h>
#include <cuda_bf16.h>
#include <cstdint>

// Problem constants
#define Bz 4
#define Sz 1024
#define Dz 512
#define Hz 8
#define DKz 64
#define Lz 4
#define DFFz 2048
#define SOFTCAP 30.0f
#define PAD_IDX 0
#define START_IDX 1

#define ROWS (Bz*Sz)           // 4096
#define XSZ  (ROWS*Dz)         // 2,097,152
#define H1SZ (ROWS*DFFz)       // 8,388,608
#define DD   (Dz*Dz)           // 262144
#define DF   (Dz*DFFz)         // 1048576

// Transposed split-weight buffer layout (element offsets):
// [WQ x4L][WK x4L][WV x4L][WO x4L][W1 x4L][W2 x4L]
#define OFF_WQ 0
#define OFF_WK (4*DD)
#define OFF_WV (8*DD)
#define OFF_WO (12*DD)
#define OFF_W1 (16*DD)
#define OFF_W2 (16*DD + 4*DF)
#define WT_TOT (16*DD + 8*DF)  // 12,582,912

// Persistent scratch (allocation-free per harness rules)
__device__ float g_x[XSZ];
__device__ float g_xn[XSZ];
__device__ float g_q[XSZ];
__device__ float g_k[XSZ];
__device__ float g_v[XSZ];
__device__ float g_cb[ROWS];
__device__ int   g_keep[ROWS];
__device__ __align__(16) __nv_bfloat16 g_wth[WT_TOT];
__device__ __align__(16) __nv_bfloat16 g_wtl[WT_TOT];
__device__ __align__(16) __nv_bfloat16 g_xnh[XSZ], g_xnl[XSZ];
__device__ __align__(16) __nv_bfloat16 g_oh[XSZ],  g_ol[XSZ];
__device__ __align__(16) __nv_bfloat16 g_h1h[H1SZ], g_h1l[H1SZ];

// ---------------------------------------------------------------------------
// helpers
// ---------------------------------------------------------------------------
__device__ __forceinline__ void bsplit(float x, __nv_bfloat16& h, __nv_bfloat16& l)
{
    h = __float2bfloat16_rn(x);
    l = __float2bfloat16_rn(x - __bfloat162float(h));
}
__device__ __forceinline__ uint32_t bpack(__nv_bfloat16 a, __nv_bfloat16 b)
{
    uint16_t ua = *reinterpret_cast<uint16_t*>(&a);
    uint16_t ub = *reinterpret_cast<uint16_t*>(&b);
    return (uint32_t)ua | ((uint32_t)ub << 16);
}
// gelu(x) = 0.5x(1+tanh(t)) = x - x/(e^{2t}+1),  t = 0.79788456(x + 0.044715 x^3)
__device__ __forceinline__ float gelu_fast(float x)
{
    float t = 0.7978845608028654f * (x + 0.044715f * x * x * x);
    float e = __expf(2.f * t);
    return x - x * __fdividef(1.f, e + 1.f);
}

#define MMA_BF16(d, a0, a1, a2, a3, b0, b1) \
    asm volatile("mma.sync.aligned.m16n8k16.row.col.f32.bf16.bf16.f32 " \
        "{%0,%1,%2,%3},{%4,%5,%6,%7},{%8,%9},{%0,%1,%2,%3};" \
        : "+f"(d[0]), "+f"(d[1]), "+f"(d[2]), "+f"(d[3]) \
        : "r"(a0), "r"(a1), "r"(a2), "r"(a3), "r"(b0), "r"(b1))

#define LDSM4(r, addr) \
    asm volatile("ldmatrix.sync.aligned.m8n8.x4.shared.b16 {%0,%1,%2,%3},[%4];" \
        : "=r"((r)[0]), "=r"((r)[1]), "=r"((r)[2]), "=r"((r)[3]) : "r"(addr))

__device__ __forceinline__ void cp16(uint32_t dst, const void* src)
{
    uint64_t g = (uint64_t)__cvta_generic_to_global(src);
    asm volatile("cp.async.cg.shared.global [%0], [%1], 16;" :: "r"(dst), "l"(g));
}
#define CP_COMMIT() asm volatile("cp.async.commit_group;")
#define CP_WAIT2()  asm volatile("cp.async.wait_group 2;")

// ---------------------------------------------------------------------------
// Embedding + right-shift + count bias + keep mask
// ---------------------------------------------------------------------------
__global__ void embed_kernel(const int* __restrict__ tok,
                             const float* __restrict__ cnt,
                             const float* __restrict__ emb)
{
    int r = blockIdx.x;
    int b = r / Sz, s = r % Sz;
    int t; float c;
    if (s == 0) { t = START_IDX; c = 1.0f; }
    else        { t = tok[b*Sz + s - 1]; c = cnt[b*Sz + s - 1]; }
    if (threadIdx.x == 0) {
        g_cb[r]   = log1pf(c + 1e-6f);
        g_keep[r] = (t != PAD_IDX);
    }
    const float4* src = (const float4*)(emb + (size_t)t * Dz);
    float4* dst = (float4*)(g_x + (size_t)r * Dz);
    dst[threadIdx.x] = src[threadIdx.x];
}

// ---------------------------------------------------------------------------
// Weight transpose + bf16 split: W[K][N] (per layer) -> Wt[N][K] hi/lo bf16
// grid: (N/32, K/32, L), block 256
// ---------------------------------------------------------------------------
__global__ void tsplit_kernel(const float* __restrict__ src,
                              __nv_bfloat16* __restrict__ dh,
                              __nv_bfloat16* __restrict__ dl,
                              int K, int N)
{
    __shared__ float t[32][33];
    size_t lo = (size_t)blockIdx.z * K * N;
    src += lo; dh += lo; dl += lo;
    int n0 = blockIdx.x * 32, k0 = blockIdx.y * 32;
    int tx = threadIdx.x & 31, ty = threadIdx.x >> 5;   // ty 0..7
    #pragma unroll
    for (int i = 0; i < 4; i++)
        t[ty + 8*i][tx] = src[(size_t)(k0 + ty + 8*i) * N + n0 + tx];
    __syncthreads();
    #pragma unroll
    for (int i = 0; i < 4; i++) {
        float v = t[tx][ty + 8*i];
        __nv_bfloat16 h, l; bsplit(v, h, l);
        size_t idx = (size_t)(n0 + ty + 8*i) * K + k0 + tx;
        dh[idx] = h; dl[idx] = l;
    }
}

// ---------------------------------------------------------------------------
// LayerNorm -> fp32 xn + bf16 hi/lo pair
// ---------------------------------------------------------------------------
__device__ __forceinline__ float block_reduce_sum(float v, float* red)
{
    int lane = threadIdx.x & 31, warp = threadIdx.x >> 5;
    #pragma unroll
    for (int o = 16; o > 0; o >>= 1) v += __shfl_xor_sync(0xffffffffu, v, o);
    if (lane == 0) red[warp] = v;
    __syncthreads();
    float r = 0.f;
    if (warp == 0) {
        r = (lane < (blockDim.x >> 5)) ? red[lane] : 0.f;
        #pragma unroll
        for (int o = 16; o > 0; o >>= 1) r += __shfl_xor_sync(0xffffffffu, r, o);
        if (lane == 0) red[0] = r;
    }
    __syncthreads();
    r = red[0];
    __syncthreads();
    return r;
}

__global__ void layernorm_kernel(const float* __restrict__ x,
                                 const float* __restrict__ gam,
                                 const float* __restrict__ bet,
                                 float* __restrict__ out,
                                 __nv_bfloat16* __restrict__ outh,
                                 __nv_bfloat16* __restrict__ outl)
{
    __shared__ float red[32];
    int r = blockIdx.x;
    const float4* xr = (const float4*)(x + (size_t)r * Dz);
    float4 v = xr[threadIdx.x];
    float s = v.x + v.y + v.z + v.w;
    float tot = block_reduce_sum(s, red);
    float mu = tot * (1.0f / Dz);
    float d0 = v.x - mu, d1 = v.y - mu, d2 = v.z - mu, d3 = v.w - mu;
    float sq = d0*d0 + d1*d1 + d2*d2 + d3*d3;
    float var = block_reduce_sum(sq, red) * (1.0f / Dz);
    float rstd = rsqrtf(var + 1e-5f);
    float4 gg = ((const float4*)gam)[threadIdx.x];
    float4 bb = ((const float4*)bet)[threadIdx.x];
    float4 o;
    o.x = d0 * rstd * gg.x + bb.x;
    o.y = d1 * rstd * gg.y + bb.y;
    o.z = d2 * rstd * gg.z + bb.z;
    o.w = d3 * rstd * gg.w + bb.w;
    ((float4*)(out + (size_t)r * Dz))[threadIdx.x] = o;
    __nv_bfloat16 hx,lx,hy,ly,hz,lz,hw,lw;
    bsplit(o.x,hx,lx); bsplit(o.y,hy,ly); bsplit(o.z,hz,lz); bsplit(o.w,hw,lw);
    uint2 ph = { bpack(hx,hy), bpack(hz,hw) };
    uint2 pl = { bpack(lx,ly), bpack(lz,lw) };
    *(uint2*)(outh + (size_t)r * Dz + threadIdx.x * 4) = ph;
    *(uint2*)(outl + (size_t)r * Dz + threadIdx.x * 4) = pl;
}

// ---------------------------------------------------------------------------
// GEMM v3: C[M,N] = A@W + bias (+epi). A: bf16 hi/lo [M][K]; W: bf16 hi/lo
// transposed [N][K]. 3-term split product. BM=BN=128, BK=16, 512 thr,
// 16 warps (warp tile 32x32), cp.async 4-stage, ldmatrix fragments.
// EPI 0 bias, 1 gelu, 2 +res.  OUTBF: write bf16 hi/lo pair instead of fp32.
// smem stage: 4 arrays (Ah,Al,Bh,Bl) x 128 rows x 24 halves (48B rows).
// ---------------------------------------------------------------------------
#define GSTAGE 24576              // bytes per stage (4 * 128 * 48)
#define GSMEM  (4 * GSTAGE)       // 98304

__device__ __forceinline__ void stage_load(
    uint32_t smem_u32, int s, int k0, int K,
    const __nv_bfloat16* Ah, const __nv_bfloat16* Al,
    const __nv_bfloat16* Bh, const __nv_bfloat16* Bl,
    int aBase, int bBase, int tid)
{
    #pragma unroll
    for (int rep = 0; rep < 2; rep++) {
        int c = tid + rep * 512;
        int arr = c >> 8, r = (c >> 1) & 127, h = c & 1;
        const __nv_bfloat16* g =
            (arr == 0) ? Ah + (size_t)(aBase + r) * K :
            (arr == 1) ? Al + (size_t)(aBase + r) * K :
            (arr == 2) ? Bh + (size_t)(bBase + r) * K :
                         Bl + (size_t)(bBase + r) * K;
        uint32_t dst = smem_u32 + s * GSTAGE + arr * 6144 + r * 48 + h * 16;
        cp16(dst, g + k0 + h * 8);
    }
}

template<int EPI, int OUTBF>
__device__ __forceinline__ void gemm3_body(
    int M, int N, int K,
    const __nv_bfloat16* __restrict__ Ah, const __nv_bfloat16* __restrict__ Al,
    const __nv_bfloat16* __restrict__ Bh, const __nv_bfloat16* __restrict__ Bl,
    const float* __restrict__ bias, const float* __restrict__ res,
    float* __restrict__ C, __nv_bfloat16* __restrict__ Ch,
    __nv_bfloat16* __restrict__ Cl, int bx, int by)
{
    extern __shared__ __align__(16) char smraw[];
    uint32_t smem_u32 = (uint32_t)__cvta_generic_to_shared(smraw);
    int tid = threadIdx.x;
    int lane = tid & 31, warp = tid >> 5;
    int wm = warp >> 2, wn = warp & 3;      // 4x4 warps, tile 32x32
    int gid = lane >> 2, tig = lane & 3;
    int aBase = by * 128, bBase = bx * 128;

    float acc[2][4][4];
    #pragma unroll
    for (int mt = 0; mt < 2; mt++)
        #pragma unroll
        for (int nt = 0; nt < 4; nt++)
            #pragma unroll
            for (int i = 0; i < 4; i++) acc[mt][nt][i] = 0.f;

    int nIter = K / 16;
    #pragma unroll
    for (int s = 0; s < 3; s++) {
        stage_load(smem_u32, s, s * 16, K, Ah, Al, Bh, Bl, aBase, bBase, tid);
        CP_COMMIT();
    }

    // per-warp fragment base offsets (bytes within a stage)
    uint32_t aoff = (uint32_t)((wm*32 + (lane & 15)) * 48 + (lane >> 4) * 16);
    int brow = wn*32 + ((lane & 7) | (((lane >> 4) & 1) << 3));
    uint32_t boff = (uint32_t)(brow * 48 + ((lane >> 3) & 1) * 16);

    for (int it = 0; it < nIter; it++) {
        CP_WAIT2();
        __syncthreads();
        int s = it & 3;
        int nk = it + 3;
        if (nk < nIter)
            stage_load(smem_u32, nk & 3, nk * 16, K, Ah, Al, Bh, Bl, aBase, bBase, tid);
        CP_COMMIT();

        uint32_t sb = smem_u32 + s * GSTAGE;
        uint32_t ah[2][4], al[2][4], bh[2][4], bl[2][4];
        LDSM4(ah[0], sb + aoff);
        LDSM4(ah[1], sb + aoff + 768);
        LDSM4(al[0], sb + 6144 + aoff);
        LDSM4(al[1], sb + 6144 + aoff + 768);
        LDSM4(bh[0], sb + 12288 + boff);
        LDSM4(bh[1], sb + 12288 + boff + 768);
        LDSM4(bl[0], sb + 18432 + boff);
        LDSM4(bl[1], sb + 18432 + boff + 768);

        #pragma unroll
        for (int mt = 0; mt < 2; mt++)
            #pragma unroll
            for (int nt = 0; nt < 4; nt++) {
                int p = nt >> 1, q = (nt & 1) * 2;
                MMA_BF16(acc[mt][nt], ah[mt][0], ah[mt][1], ah[mt][2], ah[mt][3],
                         bh[p][q], bh[p][q+1]);
                MMA_BF16(acc[mt][nt], ah[mt][0], ah[mt][1], ah[mt][2], ah[mt][3],
                         bl[p][q], bl[p][q+1]);
                MMA_BF16(acc[mt][nt], al[mt][0], al[mt][1], al[mt][2], al[mt][3],
                         bh[p][q], bh[p][q+1]);
            }
    }

    // epilogue
    size_t rowBase = (size_t)by * 128 + wm * 32;
    size_t colBase = (size_t)bx * 128 + wn * 32;
    #pragma unroll
    for (int nt = 0; nt < 4; nt++) {
        size_t c = colBase + nt * 8 + tig * 2;
        float2 bb = *(const float2*)(bias + c);
        #pragma unroll
        for (int mt = 0; mt < 2; mt++) {
            size_t r0 = rowBase + mt * 16 + gid;
            size_t r1 = r0 + 8;
            float2 v0, v1;
            v0.x = acc[mt][nt][0] + bb.x; v0.y = acc[mt][nt][1] + bb.y;
            v1.x = acc[mt][nt][2] + bb.x; v1.y = acc[mt][nt][3] + bb.y;
            if (EPI == 1) {
                v0.x = gelu_fast(v0.x); v0.y = gelu_fast(v0.y);
                v1.x = gelu_fast(v1.x); v1.y = gelu_fast(v1.y);
            }
            if (EPI == 2) {
                float2 q0 = *(const float2*)(res + r0 * N + c);
                float2 q1 = *(const float2*)(res + r1 * N + c);
                v0.x += q0.x; v0.y += q0.y;
                v1.x += q1.x; v1.y += q1.y;
            }
            if (OUTBF) {
                __nv_bfloat16 h0,l0,h1_,l1_;
                bsplit(v0.x,h0,l0); bsplit(v0.y,h1_,l1_);
                *(uint32_t*)(Ch + r0 * N + c) = bpack(h0,h1_);
                *(uint32_t*)(Cl + r0 * N + c) = bpack(l0,l1_);
                bsplit(v1.x,h0,l0); bsplit(v1.y,h1_,l1_);
                *(uint32_t*)(Ch + r1 * N + c) = bpack(h0,h1_);
                *(uint32_t*)(Cl + r1 * N + c) = bpack(l0,l1_);
            } else {
                *(float2*)(C + r0 * N + c) = v0;
                *(float2*)(C + r1 * N + c) = v1;
            }
        }
    }
}

template<int EPI, int OUTBF>
__global__ void __launch_bounds__(512, 1)
gemm3_kernel(int M, int N, int K,
             const __nv_bfloat16* Ah, const __nv_bfloat16* Al,
             const __nv_bfloat16* Bh, const __nv_bfloat16* Bl,
             const float* bias, const float* res,
             float* C, __nv_bfloat16* Ch, __nv_bfloat16* Cl)
{
    gemm3_body<EPI, OUTBF>(M, N, K, Ah, Al, Bh, Bl, bias, res, C, Ch, Cl,
                           blockIdx.x, blockIdx.y);
}

// Fused QKV: grid.x = 12, which = bx>>2 selects Wq/Wk/Wv
__global__ void __launch_bounds__(512, 1)
qkv3_kernel(const __nv_bfloat16* Ah, const __nv_bfloat16* Al,
            const __nv_bfloat16* WqH, const __nv_bfloat16* WqL,
            const __nv_bfloat16* WkH, const __nv_bfloat16* WkL,
            const __nv_bfloat16* WvH, const __nv_bfloat16* WvL,
            const float* bq, const float* bk, const float* bv,
            float* Cq, float* Ck, float* Cv)
{
    int which = blockIdx.x >> 2;
    int bx = blockIdx.x & 3;
    const __nv_bfloat16* Bh = (which == 0) ? WqH : (which == 1) ? WkH : WvH;
    const __nv_bfloat16* Bl = (which == 0) ? WqL : (which == 1) ? WkL : WvL;
    const float* b = (which == 0) ? bq : (which == 1) ? bk : bv;
    float* C       = (which == 0) ? Cq : (which == 1) ? Ck : Cv;
    gemm3_body<0, 0>(ROWS, Dz, Dz, Ah, Al, Bh, Bl, b, nullptr, C, nullptr, nullptr,
                     bx, blockIdx.y);
}

// ---------------------------------------------------------------------------
// Per-vector quant-dequant, one warp per 64-elem vector.
// ---------------------------------------------------------------------------
__global__ void quantdq_kernel(float* __restrict__ tk, float* __restrict__ tv,
                               const float* __restrict__ lvk,
                               const float* __restrict__ lvv)
{
    __shared__ float lv[8];
    float* t = (blockIdx.y == 0) ? tk : tv;
    const float* levels = (blockIdx.y == 0) ? lvk : lvv;
    if (threadIdx.x < 8) lv[threadIdx.x] = levels[threadIdx.x];
    __syncthreads();
    int warp = threadIdx.x >> 5, lane = threadIdx.x & 31;
    int w = blockIdx.x * 8 + warp;
    float* p = t + (size_t)(w / Hz) * Dz + (size_t)(w % Hz) * DKz;

    float x0 = p[lane], x1 = p[lane + 32];
    float ss = x0 * x0 + x1 * x1;
    #pragma unroll
    for (int o = 16; o > 0; o >>= 1) ss += __shfl_xor_sync(0xffffffffu, ss, o);
    float nrm = sqrtf(ss);
    float inv = 1.f / (nrm + 1e-8f);
    float u0 = x0 * inv, u1 = x1 * inv;
    float a0 = fabsf(u0), a1 = fabsf(u1);
    float sg0 = (u0 >= 0.f) ? 1.f : -1.f;
    float sg1 = (u1 >= 0.f) ? 1.f : -1.f;

    float q0 = lv[0], b0 = fabsf(a0 - lv[0]);
    float q1 = lv[0], b1 = fabsf(a1 - lv[0]);
    #pragma unroll
    for (int i = 1; i < 8; i++) {
        float d0 = fabsf(a0 - lv[i]);
        if (d0 < b0) { b0 = d0; q0 = lv[i]; }
        float d1 = fabsf(a1 - lv[i]);
        if (d1 < b1) { b1 = d1; q1 = lv[i]; }
    }
    float num = a0 * q0 + a1 * q1;
    float den = q0 * q0 + q1 * q1;
    #pragma unroll
    for (int o = 16; o > 0; o >>= 1) {
        num += __shfl_xor_sync(0xffffffffu, num, o);
        den += __shfl_xor_sync(0xffffffffu, den, o);
    }
    float rmag = num / (den + 1e-8f);
    p[lane]      = sg0 * q0 * rmag * nrm;
    p[lane + 32] = sg1 * q1 * rmag * nrm;
}

// ---------------------------------------------------------------------------
// Causal attention, 64q x 64k tiles, softcap via 2x __expf; bf16-pair output.
// ---------------------------------------------------------------------------
#define ATTN_SMEM (4*64*65*4 + 64*4*3)

__global__ void __launch_bounds__(256, 1)
attn_kernel(const float* __restrict__ gq, const float* __restrict__ gk,
            const float* __restrict__ gv,
            __nv_bfloat16* __restrict__ o_hi, __nv_bfloat16* __restrict__ o_lo,
            const float* __restrict__ cb, const int* __restrict__ keep)
{
    extern __shared__ float sm[];
    float (*Qs)[65] = (float(*)[65])(sm);
    float (*Ks)[65] = (float(*)[65])(sm + 64*65);
    float (*Vs)[65] = (float(*)[65])(sm + 2*64*65);
    float (*Ps)[65] = (float(*)[65])(sm + 3*64*65);
    float* dens = sm + 4*64*65;
    float* cbk  = dens + 64;
    int*   kpk  = (int*)(cbk + 64);

    int qt = blockIdx.x;
    int bh = blockIdx.y;
    int b = bh / Hz, h = bh % Hz;
    int q0 = qt * 64;
    int tid = threadIdx.x;
    int tx = tid & 15, ty = tid >> 4;
    const float scale = 0.125f;

    const float* qbase = gq + ((size_t)(b * Sz + q0)) * Dz + h * DKz;
    #pragma unroll
    for (int i = 0; i < 4; i++) {
        int idx = tid + i * 256;
        int qi = idx >> 4, d4 = (idx & 15) * 4;
        float4 v4 = *(const float4*)(qbase + (size_t)qi * Dz + d4);
        Qs[qi][d4] = v4.x; Qs[qi][d4+1] = v4.y; Qs[qi][d4+2] = v4.z; Qs[qi][d4+3] = v4.w;
    }
    if (tid < 64) dens[tid] = 0.f;

    float acc[4][4];
    #pragma unroll
    for (int i = 0; i < 4; i++)
        #pragma unroll
        for (int j = 0; j < 4; j++) acc[i][j] = 0.f;

    for (int kt = 0; kt <= qt; kt++) {
        int k0 = kt * 64;
        __syncthreads();
        const float* kbase = gk + ((size_t)(b * Sz + k0)) * Dz + h * DKz;
        const float* vbase = gv + ((size_t)(b * Sz + k0)) * Dz + h * DKz;
        #pragma unroll
        for (int i = 0; i < 4; i++) {
            int idx = tid + i * 256;
            int r = idx >> 4, d4 = (idx & 15) * 4;
            float4 kv = *(const float4*)(kbase + (size_t)r * Dz + d4);
            Ks[r][d4] = kv.x; Ks[r][d4+1] = kv.y; Ks[r][d4+2] = kv.z; Ks[r][d4+3] = kv.w;
            float4 vv = *(const float4*)(vbase + (size_t)r * Dz + d4);
            Vs[r][d4] = vv.x; Vs[r][d4+1] = vv.y; Vs[r][d4+2] = vv.z; Vs[r][d4+3] = vv.w;
        }
        if (tid < 64) {
            cbk[tid] = cb[b * Sz + k0 + tid];
            kpk[tid] = keep[b * Sz + k0 + tid];
        }
        __syncthreads();

        float s[4][4];
        #pragma unroll
        for (int i = 0; i < 4; i++)
            #pragma unroll
            for (int j = 0; j < 4; j++) s[i][j] = 0.f;
        #pragma unroll 8
        for (int kk = 0; kk < 64; kk++) {
            float rq[4], rk[4];
            #pragma unroll
            for (int i = 0; i < 4; i++) rq[i] = Qs[ty*4 + i][kk];
            #pragma unroll
            for (int j = 0; j < 4; j++) rk[j] = Ks[tx*4 + j][kk];
            #pragma unroll
            for (int i = 0; i < 4; i++)
                #pragma unroll
                for (int j = 0; j < 4; j++) s[i][j] += rq[i] * rk[j];
        }
        #pragma unroll
        for (int i = 0; i < 4; i++) {
            int qg = q0 + ty*4 + i;
            #pragma unroll
            for (int j = 0; j < 4; j++) {
                int kg = k0 + tx*4 + j;
                float p = 0.f;
                if (kg <= qg && kpk[tx*4 + j]) {
                    // exp(30*tanh(y/30)) = exp(30 - 60/(e^{y/15}+1))
                    float y = s[i][j] * scale + cbk[tx*4 + j];
                    float u = __expf(y * (1.0f / 15.0f));
                    p = __expf(30.f - __fdividef(60.f, u + 1.f));
                }
                Ps[ty*4 + i][tx*4 + j] = p;
            }
        }
        __syncthreads();
        if (tid < 64) {
            float sum = 0.f;
            #pragma unroll 8
            for (int kk = 0; kk < 64; kk++) sum += Ps[tid][kk];
            dens[tid] += sum;
        }
        #pragma unroll 8
        for (int kk = 0; kk < 64; kk++) {
            float rp[4], rv[4];
            #pragma unroll
            for (int i = 0; i < 4; i++) rp[i] = Ps[ty*4 + i][kk];
            #pragma unroll
            for (int j = 0; j < 4; j++) rv[j] = Vs[kk][tx*4 + j];
            #pragma unroll
            for (int i = 0; i < 4; i++)
                #pragma unroll
                for (int j = 0; j < 4; j++) acc[i][j] += rp[i] * rv[j];
        }
    }
    __syncthreads();
    #pragma unroll
    for (int i = 0; i < 4; i++) {
        float dinv = 1.f / dens[ty*4 + i];
        size_t row = (size_t)(b * Sz + q0 + ty*4 + i);
        size_t colb = h * DKz + tx * 4;
        __nv_bfloat16 h0,l0,h1,l1,h2,l2,h3,l3;
        bsplit(acc[i][0]*dinv, h0, l0);
        bsplit(acc[i][1]*dinv, h1, l1);
        bsplit(acc[i][2]*dinv, h2, l2);
        bsplit(acc[i][3]*dinv, h3, l3);
        uint2 ph = { bpack(h0,h1), bpack(h2,h3) };
        uint2 pl = { bpack(l0,l1), bpack(l2,l3) };
        *(uint2*)(o_hi + row * Dz + colb) = ph;
        *(uint2*)(o_lo + row * Dz + colb) = pl;
    }
}

// ---------------------------------------------------------------------------
// Host launcher
// ---------------------------------------------------------------------------
extern "C" void kernel_launch(void* const* d_in, const int* in_sizes, int n_in,
                              void* d_out, int out_size)
{
    const int*   tok  = (const int*)  d_in[0];
    const float* cnt  = (const float*)d_in[1];
    const float* emb  = (const float*)d_in[2];
    const float* Wq   = (const float*)d_in[3];
    const float* bq   = (const float*)d_in[4];
    const float* Wk   = (const float*)d_in[5];
    const float* bk   = (const float*)d_in[6];
    const float* Wv   = (const float*)d_in[7];
    const float* bv   = (const float*)d_in[8];
    const float* Wo   = (const float*)d_in[9];
    const float* bo   = (const float*)d_in[10];
    const float* ln1g = (const float*)d_in[11];
    const float* ln1b = (const float*)d_in[12];
    const float* ln2g = (const float*)d_in[13];
    const float* ln2b = (const float*)d_in[14];
    const float* W1   = (const float*)d_in[15];
    const float* b1   = (const float*)d_in[16];
    const float* W2   = (const float*)d_in[17];
    const float* b2   = (const float*)d_in[18];
    const float* cbk  = (const float*)d_in[19];
    float* out = (float*)d_out;

    cudaFuncSetAttribute(attn_kernel, cudaFuncAttributeMaxDynamicSharedMemorySize, ATTN_SMEM);
    cudaFuncSetAttribute(qkv3_kernel, cudaFuncAttributeMaxDynamicSharedMemorySize, GSMEM);
    cudaFuncSetAttribute(gemm3_kernel<2,0>, cudaFuncAttributeMaxDynamicSharedMemorySize, GSMEM);
    cudaFuncSetAttribute(gemm3_kernel<1,1>, cudaFuncAttributeMaxDynamicSharedMemorySize, GSMEM);

    float *px, *pxn, *pq, *pk, *pv, *pcb;
    int *pkeep;
    __nv_bfloat16 *pwth, *pwtl, *pxnh, *pxnl, *poh, *pol, *ph1h, *ph1l;
    cudaGetSymbolAddress((void**)&px,   g_x);
    cudaGetSymbolAddress((void**)&pxn,  g_xn);
    cudaGetSymbolAddress((void**)&pq,   g_q);
    cudaGetSymbolAddress((void**)&pk,   g_k);
    cudaGetSymbolAddress((void**)&pv,   g_v);
    cudaGetSymbolAddress((void**)&pcb,  g_cb);
    cudaGetSymbolAddress((void**)&pkeep, g_keep);
    cudaGetSymbolAddress((void**)&pwth, g_wth);
    cudaGetSymbolAddress((void**)&pwtl, g_wtl);
    cudaGetSymbolAddress((void**)&pxnh, g_xnh);
    cudaGetSymbolAddress((void**)&pxnl, g_xnl);
    cudaGetSymbolAddress((void**)&poh,  g_oh);
    cudaGetSymbolAddress((void**)&pol,  g_ol);
    cudaGetSymbolAddress((void**)&ph1h, g_h1h);
    cudaGetSymbolAddress((void**)&ph1l, g_h1l);

    // one-time per launch: transpose + split all weights
    tsplit_kernel<<<dim3(16,16,Lz), 256>>>(Wq, pwth+OFF_WQ, pwtl+OFF_WQ, Dz, Dz);
    tsplit_kernel<<<dim3(16,16,Lz), 256>>>(Wk, pwth+OFF_WK, pwtl+OFF_WK, Dz, Dz);
    tsplit_kernel<<<dim3(16,16,Lz), 256>>>(Wv, pwth+OFF_WV, pwtl+OFF_WV, Dz, Dz);
    tsplit_kernel<<<dim3(16,16,Lz), 256>>>(Wo, pwth+OFF_WO, pwtl+OFF_WO, Dz, Dz);
    tsplit_kernel<<<dim3(64,16,Lz), 256>>>(W1, pwth+OFF_W1, pwtl+OFF_W1, Dz, DFFz);
    tsplit_kernel<<<dim3(16,64,Lz), 256>>>(W2, pwth+OFF_W2, pwtl+OFF_W2, DFFz, Dz);

    embed_kernel<<<ROWS, 128>>>(tok, cnt, emb);

    dim3 gD(Dz / 128, ROWS / 128);      // (4, 32)
    dim3 gQKV(12, ROWS / 128);          // (12, 32)
    dim3 gF(DFFz / 128, ROWS / 128);    // (16, 32)

    for (int l = 0; l < Lz; l++) {
        layernorm_kernel<<<ROWS, 128>>>(px, ln1g + l*Dz, ln1b + l*Dz, pxn, pxnh, pxnl);

        qkv3_kernel<<<gQKV, 512, GSMEM>>>(pxnh, pxnl,
            pwth + OFF_WQ + (size_t)l*DD, pwtl + OFF_WQ + (size_t)l*DD,
            pwth + OFF_WK + (size_t)l*DD, pwtl + OFF_WK + (size_t)l*DD,
            pwth + OFF_WV + (size_t)l*DD, pwtl + OFF_WV + (size_t)l*DD,
            bq + l*Dz, bk + l*Dz, bv + l*Dz, pq, pk, pv);

        quantdq_kernel<<<dim3(ROWS * Hz / 8, 2), 256>>>(
            pk, pv, cbk + (size_t)(l*2 + 0)*8, cbk + (size_t)(l*2 + 1)*8);

        attn_kernel<<<dim3(Sz/64, Bz*Hz), 256, ATTN_SMEM>>>(pq, pk, pv, poh, pol, pcb, pkeep);

        // x = o @ Wo + bo + xn
        gemm3_kernel<2,0><<<gD, 512, GSMEM>>>(ROWS, Dz, Dz, poh, pol,
            pwth + OFF_WO + (size_t)l*DD, pwtl + OFF_WO + (size_t)l*DD,
            bo + l*Dz, pxn, px, nullptr, nullptr);

        layernorm_kernel<<<ROWS, 128>>>(px, ln2g + l*Dz, ln2b + l*Dz, pxn, pxnh, pxnl);

        // h1 = gelu(xn2 @ W1 + b1), bf16-pair output
        gemm3_kernel<1,1><<<gF, 512, GSMEM>>>(ROWS, DFFz, Dz, pxnh, pxnl,
            pwth + OFF_W1 + (size_t)l*DF, pwtl + OFF_W1 + (size_t)l*DF,
            b1 + l*DFFz, nullptr, nullptr, ph1h, ph1l);

        // x = h1 @ W2 + b2 + xn2
        float* dst = (l == Lz - 1) ? out : px;
        gemm3_kernel<2,0><<<gD, 512, GSMEM>>>(ROWS, Dz, DFFz, ph1h, ph1l,
            pwth + OFF_W2 + (size_t)l*DF, pwtl + OFF_W2 + (size_t)l*DF,
            b2 + l*Dz, pxn, dst, nullptr, nullptr);
    }
}

// round 7
// speedup vs baseline: 2.7614x; 1.4260x over previous
#include <cuda_runtime.h>
#include <cuda_bf16.h>
#include <cstdint>

// Problem constants
#define Bz 4
#define Sz 1024
#define Dz 512
#define Hz 8
#define DKz 64
#define Lz 4
#define DFFz 2048
#define SOFTCAP 30.0f
#define PAD_IDX 0
#define START_IDX 1

#define ROWS (Bz*Sz)           // 4096
#define XSZ  (ROWS*Dz)         // 2,097,152
#define H1SZ (ROWS*DFFz)       // 8,388,608
#define DD   (Dz*Dz)
#define DF   (Dz*DFFz)

#define OFF_WQ 0
#define OFF_WK (4*DD)
#define OFF_WV (8*DD)
#define OFF_WO (12*DD)
#define OFF_W1 (16*DD)
#define OFF_W2 (16*DD + 4*DF)
#define WT_TOT (16*DD + 8*DF)

// Persistent scratch
__device__ float g_x[XSZ];
__device__ float g_xn[XSZ];
__device__ float g_k[XSZ];
__device__ float g_v[XSZ];
__device__ float g_cb[ROWS];
__device__ int   g_keep[ROWS];
__device__ __align__(16) __nv_bfloat16 g_wth[WT_TOT];
__device__ __align__(16) __nv_bfloat16 g_wtl[WT_TOT];
__device__ __align__(16) __nv_bfloat16 g_xnh[XSZ], g_xnl[XSZ];
__device__ __align__(16) __nv_bfloat16 g_qh[XSZ],  g_ql[XSZ];
__device__ __align__(16) __nv_bfloat16 g_kh[XSZ],  g_kl[XSZ];
__device__ __align__(16) __nv_bfloat16 g_vh[XSZ],  g_vl[XSZ];
__device__ __align__(16) __nv_bfloat16 g_oh[XSZ],  g_ol[XSZ];
__device__ __align__(16) __nv_bfloat16 g_h1h[H1SZ], g_h1l[H1SZ];

// ---------------------------------------------------------------------------
// helpers
// ---------------------------------------------------------------------------
__device__ __forceinline__ void bsplit(float x, __nv_bfloat16& h, __nv_bfloat16& l)
{
    h = __float2bfloat16_rn(x);
    l = __float2bfloat16_rn(x - __bfloat162float(h));
}
__device__ __forceinline__ uint32_t bpack(__nv_bfloat16 a, __nv_bfloat16 b)
{
    uint16_t ua = *reinterpret_cast<uint16_t*>(&a);
    uint16_t ub = *reinterpret_cast<uint16_t*>(&b);
    return (uint32_t)ua | ((uint32_t)ub << 16);
}
// split two floats into packed bf16 hi-pair and lo-pair
__device__ __forceinline__ void psplit2(float x, float y, uint32_t& h, uint32_t& l)
{
    __nv_bfloat16 hx, lx, hy, ly;
    bsplit(x, hx, lx); bsplit(y, hy, ly);
    h = bpack(hx, hy); l = bpack(lx, ly);
}
__device__ __forceinline__ float gelu_fast(float x)
{
    float t = 0.7978845608028654f * (x + 0.044715f * x * x * x);
    float e = __expf(2.f * t);
    return x - x * __fdividef(1.f, e + 1.f);
}

#define MMA_BF16(d, a0, a1, a2, a3, b0, b1) \
    asm volatile("mma.sync.aligned.m16n8k16.row.col.f32.bf16.bf16.f32 " \
        "{%0,%1,%2,%3},{%4,%5,%6,%7},{%8,%9},{%0,%1,%2,%3};" \
        : "+f"(d[0]), "+f"(d[1]), "+f"(d[2]), "+f"(d[3]) \
        : "r"(a0), "r"(a1), "r"(a2), "r"(a3), "r"(b0), "r"(b1))

#define LDSM4(r, addr) \
    asm volatile("ldmatrix.sync.aligned.m8n8.x4.shared.b16 {%0,%1,%2,%3},[%4];" \
        : "=r"((r)[0]), "=r"((r)[1]), "=r"((r)[2]), "=r"((r)[3]) : "r"(addr))
#define LDSM4T(r, addr) \
    asm volatile("ldmatrix.sync.aligned.m8n8.x4.trans.shared.b16 {%0,%1,%2,%3},[%4];" \
        : "=r"((r)[0]), "=r"((r)[1]), "=r"((r)[2]), "=r"((r)[3]) : "r"(addr))

__device__ __forceinline__ void cp16(uint32_t dst, const void* src)
{
    uint64_t g = (uint64_t)__cvta_generic_to_global(src);
    asm volatile("cp.async.cg.shared.global [%0], [%1], 16;" :: "r"(dst), "l"(g));
}
#define CP_COMMIT() asm volatile("cp.async.commit_group;")
#define CP_WAIT2()  asm volatile("cp.async.wait_group 2;")
#define CP_WAIT0()  asm volatile("cp.async.wait_group 0;")

// ---------------------------------------------------------------------------
// Embedding
// ---------------------------------------------------------------------------
__global__ void embed_kernel(const int* __restrict__ tok,
                             const float* __restrict__ cnt,
                             const float* __restrict__ emb)
{
    int r = blockIdx.x;
    int b = r / Sz, s = r % Sz;
    int t; float c;
    if (s == 0) { t = START_IDX; c = 1.0f; }
    else        { t = tok[b*Sz + s - 1]; c = cnt[b*Sz + s - 1]; }
    if (threadIdx.x == 0) {
        g_cb[r]   = log1pf(c + 1e-6f);
        g_keep[r] = (t != PAD_IDX);
    }
    const float4* src = (const float4*)(emb + (size_t)t * Dz);
    float4* dst = (float4*)(g_x + (size_t)r * Dz);
    dst[threadIdx.x] = src[threadIdx.x];
}

// ---------------------------------------------------------------------------
// Weight transpose + bf16 split
// ---------------------------------------------------------------------------
__global__ void tsplit_kernel(const float* __restrict__ src,
                              __nv_bfloat16* __restrict__ dh,
                              __nv_bfloat16* __restrict__ dl,
                              int K, int N)
{
    __shared__ float t[32][33];
    size_t lo = (size_t)blockIdx.z * K * N;
    src += lo; dh += lo; dl += lo;
    int n0 = blockIdx.x * 32, k0 = blockIdx.y * 32;
    int tx = threadIdx.x & 31, ty = threadIdx.x >> 5;
    #pragma unroll
    for (int i = 0; i < 4; i++)
        t[ty + 8*i][tx] = src[(size_t)(k0 + ty + 8*i) * N + n0 + tx];
    __syncthreads();
    #pragma unroll
    for (int i = 0; i < 4; i++) {
        float v = t[tx][ty + 8*i];
        __nv_bfloat16 h, l; bsplit(v, h, l);
        size_t idx = (size_t)(n0 + ty + 8*i) * K + k0 + tx;
        dh[idx] = h; dl[idx] = l;
    }
}

// ---------------------------------------------------------------------------
// LayerNorm -> fp32 + bf16 hi/lo
// ---------------------------------------------------------------------------
__device__ __forceinline__ float block_reduce_sum(float v, float* red)
{
    int lane = threadIdx.x & 31, warp = threadIdx.x >> 5;
    #pragma unroll
    for (int o = 16; o > 0; o >>= 1) v += __shfl_xor_sync(0xffffffffu, v, o);
    if (lane == 0) red[warp] = v;
    __syncthreads();
    float r = 0.f;
    if (warp == 0) {
        r = (lane < (blockDim.x >> 5)) ? red[lane] : 0.f;
        #pragma unroll
        for (int o = 16; o > 0; o >>= 1) r += __shfl_xor_sync(0xffffffffu, r, o);
        if (lane == 0) red[0] = r;
    }
    __syncthreads();
    r = red[0];
    __syncthreads();
    return r;
}

__global__ void layernorm_kernel(const float* __restrict__ x,
                                 const float* __restrict__ gam,
                                 const float* __restrict__ bet,
                                 float* __restrict__ out,
                                 __nv_bfloat16* __restrict__ outh,
                                 __nv_bfloat16* __restrict__ outl)
{
    __shared__ float red[32];
    int r = blockIdx.x;
    const float4* xr = (const float4*)(x + (size_t)r * Dz);
    float4 v = xr[threadIdx.x];
    float s = v.x + v.y + v.z + v.w;
    float tot = block_reduce_sum(s, red);
    float mu = tot * (1.0f / Dz);
    float d0 = v.x - mu, d1 = v.y - mu, d2 = v.z - mu, d3 = v.w - mu;
    float sq = d0*d0 + d1*d1 + d2*d2 + d3*d3;
    float var = block_reduce_sum(sq, red) * (1.0f / Dz);
    float rstd = rsqrtf(var + 1e-5f);
    float4 gg = ((const float4*)gam)[threadIdx.x];
    float4 bb = ((const float4*)bet)[threadIdx.x];
    float4 o;
    o.x = d0 * rstd * gg.x + bb.x;
    o.y = d1 * rstd * gg.y + bb.y;
    o.z = d2 * rstd * gg.z + bb.z;
    o.w = d3 * rstd * gg.w + bb.w;
    ((float4*)(out + (size_t)r * Dz))[threadIdx.x] = o;
    uint32_t h0, l0, h1, l1;
    psplit2(o.x, o.y, h0, l0);
    psplit2(o.z, o.w, h1, l1);
    uint2 ph = { h0, h1 }, pl = { l0, l1 };
    *(uint2*)(outh + (size_t)r * Dz + threadIdx.x * 4) = ph;
    *(uint2*)(outl + (size_t)r * Dz + threadIdx.x * 4) = pl;
}

// ---------------------------------------------------------------------------
// GEMM v3 (bf16 3-term split, cp.async 4-stage, ldmatrix)
// ---------------------------------------------------------------------------
#define GSTAGE 24576
#define GSMEM  (4 * GSTAGE)

__device__ __forceinline__ void stage_load(
    uint32_t smem_u32, int s, int k0, int K,
    const __nv_bfloat16* Ah, const __nv_bfloat16* Al,
    const __nv_bfloat16* Bh, const __nv_bfloat16* Bl,
    int aBase, int bBase, int tid)
{
    #pragma unroll
    for (int rep = 0; rep < 2; rep++) {
        int c = tid + rep * 512;
        int arr = c >> 8, r = (c >> 1) & 127, h = c & 1;
        const __nv_bfloat16* g =
            (arr == 0) ? Ah + (size_t)(aBase + r) * K :
            (arr == 1) ? Al + (size_t)(aBase + r) * K :
            (arr == 2) ? Bh + (size_t)(bBase + r) * K :
                         Bl + (size_t)(bBase + r) * K;
        uint32_t dst = smem_u32 + s * GSTAGE + arr * 6144 + r * 48 + h * 16;
        cp16(dst, g + k0 + h * 8);
    }
}

template<int EPI>
__device__ __forceinline__ void gemm3_body(
    int M, int N, int K,
    const __nv_bfloat16* __restrict__ Ah, const __nv_bfloat16* __restrict__ Al,
    const __nv_bfloat16* __restrict__ Bh, const __nv_bfloat16* __restrict__ Bl,
    const float* __restrict__ bias, const float* __restrict__ res,
    float* __restrict__ C, __nv_bfloat16* __restrict__ Ch,
    __nv_bfloat16* __restrict__ Cl, bool outbf, int bx, int by)
{
    extern __shared__ __align__(16) char smraw[];
    uint32_t smem_u32 = (uint32_t)__cvta_generic_to_shared(smraw);
    int tid = threadIdx.x;
    int lane = tid & 31, warp = tid >> 5;
    int wm = warp >> 2, wn = warp & 3;
    int gid = lane >> 2, tig = lane & 3;
    int aBase = by * 128, bBase = bx * 128;

    float acc[2][4][4];
    #pragma unroll
    for (int mt = 0; mt < 2; mt++)
        #pragma unroll
        for (int nt = 0; nt < 4; nt++)
            #pragma unroll
            for (int i = 0; i < 4; i++) acc[mt][nt][i] = 0.f;

    int nIter = K / 16;
    #pragma unroll
    for (int s = 0; s < 3; s++) {
        stage_load(smem_u32, s, s * 16, K, Ah, Al, Bh, Bl, aBase, bBase, tid);
        CP_COMMIT();
    }

    uint32_t aoff = (uint32_t)((wm*32 + (lane & 15)) * 48 + (lane >> 4) * 16);
    int brow = wn*32 + ((lane & 7) | (((lane >> 4) & 1) << 3));
    uint32_t boff = (uint32_t)(brow * 48 + ((lane >> 3) & 1) * 16);

    for (int it = 0; it < nIter; it++) {
        CP_WAIT2();
        __syncthreads();
        int s = it & 3;
        int nk = it + 3;
        if (nk < nIter)
            stage_load(smem_u32, nk & 3, nk * 16, K, Ah, Al, Bh, Bl, aBase, bBase, tid);
        CP_COMMIT();

        uint32_t sb = smem_u32 + s * GSTAGE;
        uint32_t ah[2][4], al[2][4], bh[2][4], bl[2][4];
        LDSM4(ah[0], sb + aoff);
        LDSM4(ah[1], sb + aoff + 768);
        LDSM4(al[0], sb + 6144 + aoff);
        LDSM4(al[1], sb + 6144 + aoff + 768);
        LDSM4(bh[0], sb + 12288 + boff);
        LDSM4(bh[1], sb + 12288 + boff + 768);
        LDSM4(bl[0], sb + 18432 + boff);
        LDSM4(bl[1], sb + 18432 + boff + 768);

        #pragma unroll
        for (int mt = 0; mt < 2; mt++)
            #pragma unroll
            for (int nt = 0; nt < 4; nt++) {
                int p = nt >> 1, q = (nt & 1) * 2;
                MMA_BF16(acc[mt][nt], ah[mt][0], ah[mt][1], ah[mt][2], ah[mt][3],
                         bh[p][q], bh[p][q+1]);
                MMA_BF16(acc[mt][nt], ah[mt][0], ah[mt][1], ah[mt][2], ah[mt][3],
                         bl[p][q], bl[p][q+1]);
                MMA_BF16(acc[mt][nt], al[mt][0], al[mt][1], al[mt][2], al[mt][3],
                         bh[p][q], bh[p][q+1]);
            }
    }

    size_t rowBase = (size_t)by * 128 + wm * 32;
    size_t colBase = (size_t)bx * 128 + wn * 32;
    #pragma unroll
    for (int nt = 0; nt < 4; nt++) {
        size_t c = colBase + nt * 8 + tig * 2;
        float2 bb = *(const float2*)(bias + c);
        #pragma unroll
        for (int mt = 0; mt < 2; mt++) {
            size_t r0 = rowBase + mt * 16 + gid;
            size_t r1 = r0 + 8;
            float2 v0, v1;
            v0.x = acc[mt][nt][0] + bb.x; v0.y = acc[mt][nt][1] + bb.y;
            v1.x = acc[mt][nt][2] + bb.x; v1.y = acc[mt][nt][3] + bb.y;
            if (EPI == 1) {
                v0.x = gelu_fast(v0.x); v0.y = gelu_fast(v0.y);
                v1.x = gelu_fast(v1.x); v1.y = gelu_fast(v1.y);
            }
            if (EPI == 2) {
                float2 q0 = *(const float2*)(res + r0 * N + c);
                float2 q1 = *(const float2*)(res + r1 * N + c);
                v0.x += q0.x; v0.y += q0.y;
                v1.x += q1.x; v1.y += q1.y;
            }
            if (outbf) {
                uint32_t h, l;
                psplit2(v0.x, v0.y, h, l);
                *(uint32_t*)(Ch + r0 * N + c) = h;
                *(uint32_t*)(Cl + r0 * N + c) = l;
                psplit2(v1.x, v1.y, h, l);
                *(uint32_t*)(Ch + r1 * N + c) = h;
                *(uint32_t*)(Cl + r1 * N + c) = l;
            } else {
                *(float2*)(C + r0 * N + c) = v0;
                *(float2*)(C + r1 * N + c) = v1;
            }
        }
    }
}

template<int EPI>
__global__ void __launch_bounds__(512, 1)
gemm3_kernel(int M, int N, int K,
             const __nv_bfloat16* Ah, const __nv_bfloat16* Al,
             const __nv_bfloat16* Bh, const __nv_bfloat16* Bl,
             const float* bias, const float* res,
             float* C, __nv_bfloat16* Ch, __nv_bfloat16* Cl, int outbf)
{
    gemm3_body<EPI>(M, N, K, Ah, Al, Bh, Bl, bias, res, C, Ch, Cl, outbf != 0,
                    blockIdx.x, blockIdx.y);
}

// Fused QKV: q -> bf16 pairs, k/v -> fp32 (quantdq consumes)
__global__ void __launch_bounds__(512, 1)
qkv3_kernel(const __nv_bfloat16* Ah, const __nv_bfloat16* Al,
            const __nv_bfloat16* WqH, const __nv_bfloat16* WqL,
            const __nv_bfloat16* WkH, const __nv_bfloat16* WkL,
            const __nv_bfloat16* WvH, const __nv_bfloat16* WvL,
            const float* bq, const float* bk, const float* bv,
            __nv_bfloat16* Cqh, __nv_bfloat16* Cql,
            float* Ck, float* Cv)
{
    int which = blockIdx.x >> 2;
    int bx = blockIdx.x & 3;
    const __nv_bfloat16* Bh = (which == 0) ? WqH : (which == 1) ? WkH : WvH;
    const __nv_bfloat16* Bl = (which == 0) ? WqL : (which == 1) ? WkL : WvL;
    const float* b = (which == 0) ? bq : (which == 1) ? bk : bv;
    float* C = (which == 1) ? Ck : Cv;
    gemm3_body<0>(ROWS, Dz, Dz, Ah, Al, Bh, Bl, b, nullptr, C, Cqh, Cql,
                  which == 0, bx, blockIdx.y);
}

// ---------------------------------------------------------------------------
// quant-dequant: fp32 in -> bf16 hi/lo out
// ---------------------------------------------------------------------------
__global__ void quantdq_kernel(const float* __restrict__ tk, const float* __restrict__ tv,
                               __nv_bfloat16* __restrict__ okh, __nv_bfloat16* __restrict__ okl,
                               __nv_bfloat16* __restrict__ ovh, __nv_bfloat16* __restrict__ ovl,
                               const float* __restrict__ lvk,
                               const float* __restrict__ lvv)
{
    __shared__ float lv[8];
    const float* t = (blockIdx.y == 0) ? tk : tv;
    __nv_bfloat16* oh = (blockIdx.y == 0) ? okh : ovh;
    __nv_bfloat16* ol = (blockIdx.y == 0) ? okl : ovl;
    const float* levels = (blockIdx.y == 0) ? lvk : lvv;
    if (threadIdx.x < 8) lv[threadIdx.x] = levels[threadIdx.x];
    __syncthreads();
    int warp = threadIdx.x >> 5, lane = threadIdx.x & 31;
    int w = blockIdx.x * 8 + warp;
    size_t off = (size_t)(w / Hz) * Dz + (size_t)(w % Hz) * DKz;
    const float* p = t + off;

    float x0 = p[lane], x1 = p[lane + 32];
    float ss = x0 * x0 + x1 * x1;
    #pragma unroll
    for (int o = 16; o > 0; o >>= 1) ss += __shfl_xor_sync(0xffffffffu, ss, o);
    float nrm = sqrtf(ss);
    float inv = 1.f / (nrm + 1e-8f);
    float u0 = x0 * inv, u1 = x1 * inv;
    float a0 = fabsf(u0), a1 = fabsf(u1);
    float sg0 = (u0 >= 0.f) ? 1.f : -1.f;
    float sg1 = (u1 >= 0.f) ? 1.f : -1.f;

    float q0 = lv[0], b0 = fabsf(a0 - lv[0]);
    float q1 = lv[0], b1 = fabsf(a1 - lv[0]);
    #pragma unroll
    for (int i = 1; i < 8; i++) {
        float d0 = fabsf(a0 - lv[i]);
        if (d0 < b0) { b0 = d0; q0 = lv[i]; }
        float d1 = fabsf(a1 - lv[i]);
        if (d1 < b1) { b1 = d1; q1 = lv[i]; }
    }
    float num = a0 * q0 + a1 * q1;
    float den = q0 * q0 + q1 * q1;
    #pragma unroll
    for (int o = 16; o > 0; o >>= 1) {
        num += __shfl_xor_sync(0xffffffffu, num, o);
        den += __shfl_xor_sync(0xffffffffu, den, o);
    }
    float rmag = num / (den + 1e-8f);
    float r0 = sg0 * q0 * rmag * nrm;
    float r1 = sg1 * q1 * rmag * nrm;
    __nv_bfloat16 h, l;
    bsplit(r0, h, l); oh[off + lane] = h;      ol[off + lane] = l;
    bsplit(r1, h, l); oh[off + lane + 32] = h; ol[off + lane + 32] = l;
}

// ---------------------------------------------------------------------------
// Tensor-core attention: bf16 3-term QK^T and PV, in-register softmax.
// 128 threads, 4 warps x 16 q-rows, 64x64 tiles, balanced (qt, 15-qt).
// ---------------------------------------------------------------------------
#define AT_STRIDE 144                    // bytes per 64-bf16 row (+16B pad)
#define AT_TILE   (64 * AT_STRIDE)       // 9216
#define AT_Q_H 0
#define AT_Q_L (1 * AT_TILE)
#define AT_K_H (2 * AT_TILE)
#define AT_K_L (3 * AT_TILE)
#define AT_V_H (4 * AT_TILE)
#define AT_V_L (5 * AT_TILE)
#define AT_CB  (6 * AT_TILE)
#define AT_MK  (6 * AT_TILE + 256)
#define ATTN2_SMEM (6 * AT_TILE + 512)

__global__ void __launch_bounds__(128, 1)
attn2_kernel(const __nv_bfloat16* __restrict__ qh, const __nv_bfloat16* __restrict__ ql,
             const __nv_bfloat16* __restrict__ kh, const __nv_bfloat16* __restrict__ kl,
             const __nv_bfloat16* __restrict__ vh, const __nv_bfloat16* __restrict__ vl,
             __nv_bfloat16* __restrict__ o_hi, __nv_bfloat16* __restrict__ o_lo,
             const float* __restrict__ cb, const int* __restrict__ keep)
{
    extern __shared__ __align__(16) char sm2[];
    uint32_t sb = (uint32_t)__cvta_generic_to_shared(sm2);
    float* cbs = (float*)(sm2 + AT_CB);
    float* mks = (float*)(sm2 + AT_MK);

    int tid = threadIdx.x;
    int lane = tid & 31, warp = tid >> 5;
    int gid = lane >> 2, tig = lane & 3;
    int bh = blockIdx.y;
    int b = bh >> 3, h = bh & 7;
    size_t hcol = (size_t)h * DKz;

    // per-warp fragment addresses
    uint32_t qaddr_base = (uint32_t)((warp*16 + (lane & 15)) * AT_STRIDE + (lane >> 4) * 16);
    uint32_t krow_off   = (uint32_t)(((lane & 7) | (((lane >> 4) & 1) << 3)) * AT_STRIDE
                                     + ((lane >> 3) & 1) * 16);
    uint32_t vaddr_base = (uint32_t)((lane & 15) * AT_STRIDE + ((lane >> 4) << 3) * 2);

    #pragma unroll
    for (int sub = 0; sub < 2; sub++) {
        int qt = (sub == 0) ? blockIdx.x : 15 - blockIdx.x;
        int q0 = qt * 64;

        // load Q tiles (hi/lo)
        #pragma unroll
        for (int i = 0; i < 8; i++) {
            int c = tid + i * 128;
            int arr = c >> 9, r = (c >> 3) & 63, ch = c & 7;
            const __nv_bfloat16* src = (arr ? ql : qh)
                + (size_t)(b * Sz + q0 + r) * Dz + hcol + ch * 8;
            cp16(sb + (arr ? AT_Q_L : AT_Q_H) + r * AT_STRIDE + ch * 16, src);
        }
        CP_COMMIT();

        float acc_o[8][4];
        #pragma unroll
        for (int nt = 0; nt < 8; nt++)
            #pragma unroll
            for (int i = 0; i < 4; i++) acc_o[nt][i] = 0.f;
        float den0 = 0.f, den1 = 0.f;

        for (int kt = 0; kt <= qt; kt++) {
            int k0 = kt * 64;
            #pragma unroll
            for (int i = 0; i < 16; i++) {
                int c = tid + i * 128;
                int arr = c >> 9, r = (c >> 3) & 63, ch = c & 7;
                const __nv_bfloat16* src =
                    (arr == 0 ? kh : arr == 1 ? kl : arr == 2 ? vh : vl)
                    + (size_t)(b * Sz + k0 + r) * Dz + hcol + ch * 8;
                cp16(sb + AT_K_H + arr * AT_TILE + r * AT_STRIDE + ch * 16, src);
            }
            CP_COMMIT();
            if (tid < 64) {
                cbs[tid] = cb[b * Sz + k0 + tid];
                mks[tid] = keep[b * Sz + k0 + tid] ? 1.f : 0.f;
            }
            CP_WAIT0();
            __syncthreads();

            // S = Q @ K^T (3-term)
            float s[8][4];
            #pragma unroll
            for (int nt = 0; nt < 8; nt++)
                #pragma unroll
                for (int i = 0; i < 4; i++) s[nt][i] = 0.f;

            #pragma unroll
            for (int ks = 0; ks < 4; ks++) {
                uint32_t qa[4], qb[4];
                LDSM4(qa, sb + AT_Q_H + qaddr_base + ks * 32);
                LDSM4(qb, sb + AT_Q_L + qaddr_base + ks * 32);
                uint32_t KH[4][4], KL[4][4];
                #pragma unroll
                for (int g = 0; g < 4; g++) {
                    uint32_t off = (uint32_t)(g * 16 * AT_STRIDE) + krow_off + ks * 32;
                    LDSM4(KH[g], sb + AT_K_H + off);
                    LDSM4(KL[g], sb + AT_K_L + off);
                }
                #pragma unroll
                for (int nt = 0; nt < 8; nt++) {
                    int g = nt >> 1, q = (nt & 1) * 2;
                    MMA_BF16(s[nt], qa[0], qa[1], qa[2], qa[3], KH[g][q], KH[g][q+1]);
                    MMA_BF16(s[nt], qa[0], qa[1], qa[2], qa[3], KL[g][q], KL[g][q+1]);
                    MMA_BF16(s[nt], qb[0], qb[1], qb[2], qb[3], KH[g][q], KH[g][q+1]);
                }
            }

            // softcap + mask + exp in registers
            int qrow = q0 + warp * 16 + gid;
            #pragma unroll
            for (int nt = 0; nt < 8; nt++) {
                #pragma unroll
                for (int i = 0; i < 4; i++) {
                    int kgl = nt * 8 + tig * 2 + (i & 1);
                    int qg = qrow + (i >> 1) * 8;
                    float y = s[nt][i] * 0.125f + cbs[kgl];
                    float u = __expf(y * (1.0f / 15.0f));
                    float p = __expf(30.f - __fdividef(60.f, u + 1.f)) * mks[kgl];
                    s[nt][i] = (k0 + kgl <= qg) ? p : 0.f;
                }
            }
            #pragma unroll
            for (int nt = 0; nt < 8; nt++) {
                den0 += s[nt][0] + s[nt][1];
                den1 += s[nt][2] + s[nt][3];
            }

            // O += P @ V (3-term); P fragments straight from s
            #pragma unroll
            for (int j = 0; j < 4; j++) {
                uint32_t pa[4], pb[4];
                psplit2(s[2*j][0],   s[2*j][1],   pa[0], pb[0]);
                psplit2(s[2*j][2],   s[2*j][3],   pa[1], pb[1]);
                psplit2(s[2*j+1][0], s[2*j+1][1], pa[2], pb[2]);
                psplit2(s[2*j+1][2], s[2*j+1][3], pa[3], pb[3]);
                #pragma unroll
                for (int dg = 0; dg < 4; dg++) {
                    uint32_t VH4[4], VL4[4];
                    uint32_t voff = vaddr_base + (uint32_t)(j * 16 * AT_STRIDE) + dg * 32;
                    LDSM4T(VH4, sb + AT_V_H + voff);
                    LDSM4T(VL4, sb + AT_V_L + voff);
                    MMA_BF16(acc_o[2*dg],   pa[0], pa[1], pa[2], pa[3], VH4[0], VH4[1]);
                    MMA_BF16(acc_o[2*dg],   pa[0], pa[1], pa[2], pa[3], VL4[0], VL4[1]);
                    MMA_BF16(acc_o[2*dg],   pb[0], pb[1], pb[2], pb[3], VH4[0], VH4[1]);
                    MMA_BF16(acc_o[2*dg+1], pa[0], pa[1], pa[2], pa[3], VH4[2], VH4[3]);
                    MMA_BF16(acc_o[2*dg+1], pa[0], pa[1], pa[2], pa[3], VL4[2], VL4[3]);
                    MMA_BF16(acc_o[2*dg+1], pb[0], pb[1], pb[2], pb[3], VH4[2], VH4[3]);
                }
            }
            __syncthreads();
        }

        den0 += __shfl_xor_sync(0xffffffffu, den0, 1);
        den0 += __shfl_xor_sync(0xffffffffu, den0, 2);
        den1 += __shfl_xor_sync(0xffffffffu, den1, 1);
        den1 += __shfl_xor_sync(0xffffffffu, den1, 2);
        float i0 = __fdividef(1.f, den0);
        float i1 = __fdividef(1.f, den1);

        size_t r0 = (size_t)(b * Sz + q0 + warp * 16 + gid);
        size_t r1 = r0 + 8;
        #pragma unroll
        for (int nt = 0; nt < 8; nt++) {
            size_t c = hcol + nt * 8 + tig * 2;
            uint32_t hh, ll;
            psplit2(acc_o[nt][0] * i0, acc_o[nt][1] * i0, hh, ll);
            *(uint32_t*)(o_hi + r0 * Dz + c) = hh;
            *(uint32_t*)(o_lo + r0 * Dz + c) = ll;
            psplit2(acc_o[nt][2] * i1, acc_o[nt][3] * i1, hh, ll);
            *(uint32_t*)(o_hi + r1 * Dz + c) = hh;
            *(uint32_t*)(o_lo + r1 * Dz + c) = ll;
        }
    }
}

// ---------------------------------------------------------------------------
// Host launcher
// ---------------------------------------------------------------------------
extern "C" void kernel_launch(void* const* d_in, const int* in_sizes, int n_in,
                              void* d_out, int out_size)
{
    const int*   tok  = (const int*)  d_in[0];
    const float* cnt  = (const float*)d_in[1];
    const float* emb  = (const float*)d_in[2];
    const float* Wq   = (const float*)d_in[3];
    const float* bq   = (const float*)d_in[4];
    const float* Wk   = (const float*)d_in[5];
    const float* bk   = (const float*)d_in[6];
    const float* Wv   = (const float*)d_in[7];
    const float* bv   = (const float*)d_in[8];
    const float* Wo   = (const float*)d_in[9];
    const float* bo   = (const float*)d_in[10];
    const float* ln1g = (const float*)d_in[11];
    const float* ln1b = (const float*)d_in[12];
    const float* ln2g = (const float*)d_in[13];
    const float* ln2b = (const float*)d_in[14];
    const float* W1   = (const float*)d_in[15];
    const float* b1   = (const float*)d_in[16];
    const float* W2   = (const float*)d_in[17];
    const float* b2   = (const float*)d_in[18];
    const float* cbk  = (const float*)d_in[19];
    float* out = (float*)d_out;

    cudaFuncSetAttribute(attn2_kernel, cudaFuncAttributeMaxDynamicSharedMemorySize, ATTN2_SMEM);
    cudaFuncSetAttribute(qkv3_kernel, cudaFuncAttributeMaxDynamicSharedMemorySize, GSMEM);
    cudaFuncSetAttribute(gemm3_kernel<2>, cudaFuncAttributeMaxDynamicSharedMemorySize, GSMEM);
    cudaFuncSetAttribute(gemm3_kernel<1>, cudaFuncAttributeMaxDynamicSharedMemorySize, GSMEM);

    float *px, *pxn, *pk, *pv, *pcb;
    int *pkeep;
    __nv_bfloat16 *pwth, *pwtl, *pxnh, *pxnl, *pqh, *pql, *pkh, *pkl, *pvh, *pvl;
    __nv_bfloat16 *poh, *pol, *ph1h, *ph1l;
    cudaGetSymbolAddress((void**)&px,   g_x);
    cudaGetSymbolAddress((void**)&pxn,  g_xn);
    cudaGetSymbolAddress((void**)&pk,   g_k);
    cudaGetSymbolAddress((void**)&pv,   g_v);
    cudaGetSymbolAddress((void**)&pcb,  g_cb);
    cudaGetSymbolAddress((void**)&pkeep, g_keep);
    cudaGetSymbolAddress((void**)&pwth, g_wth);
    cudaGetSymbolAddress((void**)&pwtl, g_wtl);
    cudaGetSymbolAddress((void**)&pxnh, g_xnh);
    cudaGetSymbolAddress((void**)&pxnl, g_xnl);
    cudaGetSymbolAddress((void**)&pqh,  g_qh);
    cudaGetSymbolAddress((void**)&pql,  g_ql);
    cudaGetSymbolAddress((void**)&pkh,  g_kh);
    cudaGetSymbolAddress((void**)&pkl,  g_kl);
    cudaGetSymbolAddress((void**)&pvh,  g_vh);
    cudaGetSymbolAddress((void**)&pvl,  g_vl);
    cudaGetSymbolAddress((void**)&poh,  g_oh);
    cudaGetSymbolAddress((void**)&pol,  g_ol);
    cudaGetSymbolAddress((void**)&ph1h, g_h1h);
    cudaGetSymbolAddress((void**)&ph1l, g_h1l);

    tsplit_kernel<<<dim3(16,16,Lz), 256>>>(Wq, pwth+OFF_WQ, pwtl+OFF_WQ, Dz, Dz);
    tsplit_kernel<<<dim3(16,16,Lz), 256>>>(Wk, pwth+OFF_WK, pwtl+OFF_WK, Dz, Dz);
    tsplit_kernel<<<dim3(16,16,Lz), 256>>>(Wv, pwth+OFF_WV, pwtl+OFF_WV, Dz, Dz);
    tsplit_kernel<<<dim3(16,16,Lz), 256>>>(Wo, pwth+OFF_WO, pwtl+OFF_WO, Dz, Dz);
    tsplit_kernel<<<dim3(64,16,Lz), 256>>>(W1, pwth+OFF_W1, pwtl+OFF_W1, Dz, DFFz);
    tsplit_kernel<<<dim3(16,64,Lz), 256>>>(W2, pwth+OFF_W2, pwtl+OFF_W2, DFFz, Dz);

    embed_kernel<<<ROWS, 128>>>(tok, cnt, emb);

    dim3 gD(Dz / 128, ROWS / 128);
    dim3 gQKV(12, ROWS / 128);
    dim3 gF(DFFz / 128, ROWS / 128);

    for (int l = 0; l < Lz; l++) {
        layernorm_kernel<<<ROWS, 128>>>(px, ln1g + l*Dz, ln1b + l*Dz, pxn, pxnh, pxnl);

        qkv3_kernel<<<gQKV, 512, GSMEM>>>(pxnh, pxnl,
            pwth + OFF_WQ + (size_t)l*DD, pwtl + OFF_WQ + (size_t)l*DD,
            pwth + OFF_WK + (size_t)l*DD, pwtl + OFF_WK + (size_t)l*DD,
            pwth + OFF_WV + (size_t)l*DD, pwtl + OFF_WV + (size_t)l*DD,
            bq + l*Dz, bk + l*Dz, bv + l*Dz, pqh, pql, pk, pv);

        quantdq_kernel<<<dim3(ROWS * Hz / 8, 2), 256>>>(
            pk, pv, pkh, pkl, pvh, pvl,
            cbk + (size_t)(l*2 + 0)*8, cbk + (size_t)(l*2 + 1)*8);

        attn2_kernel<<<dim3(8, Bz*Hz), 128, ATTN2_SMEM>>>(
            pqh, pql, pkh, pkl, pvh, pvl, poh, pol, pcb, pkeep);

        gemm3_kernel<2><<<gD, 512, GSMEM>>>(ROWS, Dz, Dz, poh, pol,
            pwth + OFF_WO + (size_t)l*DD, pwtl + OFF_WO + (size_t)l*DD,
            bo + l*Dz, pxn, px, nullptr, nullptr, 0);

        layernorm_kernel<<<ROWS, 128>>>(px, ln2g + l*Dz, ln2b + l*Dz, pxn, pxnh, pxnl);

        gemm3_kernel<1><<<gF, 512, GSMEM>>>(ROWS, DFFz, Dz, pxnh, pxnl,
            pwth + OFF_W1 + (size_t)l*DF, pwtl + OFF_W1 + (size_t)l*DF,
            b1 + l*DFFz, nullptr, nullptr, ph1h, ph1l, 1);

        float* dst = (l == Lz - 1) ? out : px;
        gemm3_kernel<2><<<gD, 512, GSMEM>>>(ROWS, Dz, DFFz, ph1h, ph1l,
            pwth + OFF_W2 + (size_t)l*DF, pwtl + OFF_W2 + (size_t)l*DF,
            b2 + l*Dz, pxn, dst, nullptr, nullptr, 0);
    }
}

// round 11
// speedup vs baseline: 2.7979x; 1.0132x over previous
#include <cuda_runtime.h>
#include <cuda_bf16.h>
#include <cstdint>

// Problem constants
#define Bz 4
#define Sz 1024
#define Dz 512
#define Hz 8
#define DKz 64
#define Lz 4
#define DFFz 2048
#define SOFTCAP 30.0f
#define PAD_IDX 0
#define START_IDX 1

#define ROWS (Bz*Sz)           // 4096
#define XSZ  (ROWS*Dz)         // 2,097,152
#define H1SZ (ROWS*DFFz)       // 8,388,608
#define DD   (Dz*Dz)
#define DF   (Dz*DFFz)

#define OFF_WQ 0
#define OFF_WK (4*DD)
#define OFF_WV (8*DD)
#define OFF_WO (12*DD)
#define OFF_W1 (16*DD)
#define OFF_W2 (16*DD + 4*DF)
#define WT_TOT (16*DD + 8*DF)

// Persistent scratch
__device__ float g_x[XSZ];
__device__ float g_xn[XSZ];
__device__ float g_k[XSZ];
__device__ float g_v[XSZ];
__device__ float g_cb[ROWS];
__device__ int   g_keep[ROWS];
__device__ __align__(16) __nv_bfloat16 g_wth[WT_TOT];
__device__ __align__(16) __nv_bfloat16 g_wtl[WT_TOT];
__device__ __align__(16) __nv_bfloat16 g_xnh[XSZ], g_xnl[XSZ];
__device__ __align__(16) __nv_bfloat16 g_qh[XSZ],  g_ql[XSZ];
__device__ __align__(16) __nv_bfloat16 g_kh[XSZ],  g_kl[XSZ];
__device__ __align__(16) __nv_bfloat16 g_vh[XSZ],  g_vl[XSZ];
__device__ __align__(16) __nv_bfloat16 g_oh[XSZ],  g_ol[XSZ];
__device__ __align__(16) __nv_bfloat16 g_h1h[H1SZ], g_h1l[H1SZ];

// ---------------------------------------------------------------------------
// helpers
// ---------------------------------------------------------------------------
__device__ __forceinline__ void bsplit(float x, __nv_bfloat16& h, __nv_bfloat16& l)
{
    h = __float2bfloat16_rn(x);
    l = __float2bfloat16_rn(x - __bfloat162float(h));
}
__device__ __forceinline__ uint32_t bpack(__nv_bfloat16 a, __nv_bfloat16 b)
{
    uint16_t ua = *reinterpret_cast<uint16_t*>(&a);
    uint16_t ub = *reinterpret_cast<uint16_t*>(&b);
    return (uint32_t)ua | ((uint32_t)ub << 16);
}
__device__ __forceinline__ void psplit2(float x, float y, uint32_t& h, uint32_t& l)
{
    __nv_bfloat16 hx, lx, hy, ly;
    bsplit(x, hx, lx); bsplit(y, hy, ly);
    h = bpack(hx, hy); l = bpack(lx, ly);
}
__device__ __forceinline__ float gelu_fast(float x)
{
    float t = 0.7978845608028654f * (x + 0.044715f * x * x * x);
    float e = __expf(2.f * t);
    return x - x * __fdividef(1.f, e + 1.f);
}

#define MMA_BF16(d, a0, a1, a2, a3, b0, b1) \
    asm volatile("mma.sync.aligned.m16n8k16.row.col.f32.bf16.bf16.f32 " \
        "{%0,%1,%2,%3},{%4,%5,%6,%7},{%8,%9},{%0,%1,%2,%3};" \
        : "+f"(d[0]), "+f"(d[1]), "+f"(d[2]), "+f"(d[3]) \
        : "r"(a0), "r"(a1), "r"(a2), "r"(a3), "r"(b0), "r"(b1))

#define LDSM4(r, addr) \
    asm volatile("ldmatrix.sync.aligned.m8n8.x4.shared.b16 {%0,%1,%2,%3},[%4];" \
        : "=r"((r)[0]), "=r"((r)[1]), "=r"((r)[2]), "=r"((r)[3]) : "r"(addr))
#define LDSM4T(r, addr) \
    asm volatile("ldmatrix.sync.aligned.m8n8.x4.trans.shared.b16 {%0,%1,%2,%3},[%4];" \
        : "=r"((r)[0]), "=r"((r)[1]), "=r"((r)[2]), "=r"((r)[3]) : "r"(addr))

__device__ __forceinline__ void cp16(uint32_t dst, const void* src)
{
    uint64_t g = (uint64_t)__cvta_generic_to_global(src);
    asm volatile("cp.async.cg.shared.global [%0], [%1], 16;" :: "r"(dst), "l"(g));
}
#define CP_COMMIT() asm volatile("cp.async.commit_group;")
#define CP_WAIT2()  asm volatile("cp.async.wait_group 2;")
#define CP_WAIT0()  asm volatile("cp.async.wait_group 0;")

// ---------------------------------------------------------------------------
// Embedding
// ---------------------------------------------------------------------------
__global__ void embed_kernel(const int* __restrict__ tok,
                             const float* __restrict__ cnt,
                             const float* __restrict__ emb)
{
    int r = blockIdx.x;
    int b = r / Sz, s = r % Sz;
    int t; float c;
    if (s == 0) { t = START_IDX; c = 1.0f; }
    else        { t = tok[b*Sz + s - 1]; c = cnt[b*Sz + s - 1]; }
    if (threadIdx.x == 0) {
        g_cb[r]   = log1pf(c + 1e-6f);
        g_keep[r] = (t != PAD_IDX);
    }
    const float4* src = (const float4*)(emb + (size_t)t * Dz);
    float4* dst = (float4*)(g_x + (size_t)r * Dz);
    dst[threadIdx.x] = src[threadIdx.x];
}

// ---------------------------------------------------------------------------
// Weight transpose + bf16 split
// ---------------------------------------------------------------------------
__global__ void tsplit_kernel(const float* __restrict__ src,
                              __nv_bfloat16* __restrict__ dh,
                              __nv_bfloat16* __restrict__ dl,
                              int K, int N)
{
    __shared__ float t[32][33];
    size_t lo = (size_t)blockIdx.z * K * N;
    src += lo; dh += lo; dl += lo;
    int n0 = blockIdx.x * 32, k0 = blockIdx.y * 32;
    int tx = threadIdx.x & 31, ty = threadIdx.x >> 5;
    #pragma unroll
    for (int i = 0; i < 4; i++)
        t[ty + 8*i][tx] = src[(size_t)(k0 + ty + 8*i) * N + n0 + tx];
    __syncthreads();
    #pragma unroll
    for (int i = 0; i < 4; i++) {
        float v = t[tx][ty + 8*i];
        __nv_bfloat16 h, l; bsplit(v, h, l);
        size_t idx = (size_t)(n0 + ty + 8*i) * K + k0 + tx;
        dh[idx] = h; dl[idx] = l;
    }
}

// ---------------------------------------------------------------------------
// LayerNorm -> fp32 + bf16 hi/lo
// ---------------------------------------------------------------------------
__device__ __forceinline__ float block_reduce_sum(float v, float* red)
{
    int lane = threadIdx.x & 31, warp = threadIdx.x >> 5;
    #pragma unroll
    for (int o = 16; o > 0; o >>= 1) v += __shfl_xor_sync(0xffffffffu, v, o);
    if (lane == 0) red[warp] = v;
    __syncthreads();
    float r = 0.f;
    if (warp == 0) {
        r = (lane < (blockDim.x >> 5)) ? red[lane] : 0.f;
        #pragma unroll
        for (int o = 16; o > 0; o >>= 1) r += __shfl_xor_sync(0xffffffffu, r, o);
        if (lane == 0) red[0] = r;
    }
    __syncthreads();
    r = red[0];
    __syncthreads();
    return r;
}

__global__ void layernorm_kernel(const float* __restrict__ x,
                                 const float* __restrict__ gam,
                                 const float* __restrict__ bet,
                                 float* __restrict__ out,
                                 __nv_bfloat16* __restrict__ outh,
                                 __nv_bfloat16* __restrict__ outl)
{
    __shared__ float red[32];
    int r = blockIdx.x;
    const float4* xr = (const float4*)(x + (size_t)r * Dz);
    float4 v = xr[threadIdx.x];
    float s = v.x + v.y + v.z + v.w;
    float tot = block_reduce_sum(s, red);
    float mu = tot * (1.0f / Dz);
    float d0 = v.x - mu, d1 = v.y - mu, d2 = v.z - mu, d3 = v.w - mu;
    float sq = d0*d0 + d1*d1 + d2*d2 + d3*d3;
    float var = block_reduce_sum(sq, red) * (1.0f / Dz);
    float rstd = rsqrtf(var + 1e-5f);
    float4 gg = ((const float4*)gam)[threadIdx.x];
    float4 bb = ((const float4*)bet)[threadIdx.x];
    float4 o;
    o.x = d0 * rstd * gg.x + bb.x;
    o.y = d1 * rstd * gg.y + bb.y;
    o.z = d2 * rstd * gg.z + bb.z;
    o.w = d3 * rstd * gg.w + bb.w;
    ((float4*)(out + (size_t)r * Dz))[threadIdx.x] = o;
    uint32_t h0, l0, h1, l1;
    psplit2(o.x, o.y, h0, l0);
    psplit2(o.z, o.w, h1, l1);
    uint2 ph = { h0, h1 }, pl = { l0, l1 };
    *(uint2*)(outh + (size_t)r * Dz + threadIdx.x * 4) = ph;
    *(uint2*)(outl + (size_t)r * Dz + threadIdx.x * 4) = pl;
}

// ---------------------------------------------------------------------------
// GEMM v4: bf16 3-term split, cp.async 4-stage, ldmatrix.
// 256 threads / 8 warps, warp tile 64x32 (48 MMA : 12 LDSM per k16 iter),
// __launch_bounds__(256,2) -> 2 CTAs/SM (192KB smem, 16 warps/SM).
// ---------------------------------------------------------------------------
#define GSTAGE 24576
#define GSMEM  (4 * GSTAGE)

__device__ __forceinline__ void stage_load(
    uint32_t smem_u32, int s, int k0, int K,
    const __nv_bfloat16* Ah, const __nv_bfloat16* Al,
    const __nv_bfloat16* Bh, const __nv_bfloat16* Bl,
    int aBase, int bBase, int tid)
{
    #pragma unroll
    for (int rep = 0; rep < 4; rep++) {
        int c = tid + rep * 256;
        int arr = c >> 8, r = (c >> 1) & 127, h = c & 1;
        const __nv_bfloat16* g =
            (arr == 0) ? Ah + (size_t)(aBase + r) * K :
            (arr == 1) ? Al + (size_t)(aBase + r) * K :
            (arr == 2) ? Bh + (size_t)(bBase + r) * K :
                         Bl + (size_t)(bBase + r) * K;
        uint32_t dst = smem_u32 + s * GSTAGE + arr * 6144 + r * 48 + h * 16;
        cp16(dst, g + k0 + h * 8);
    }
}

template<int EPI>
__device__ __forceinline__ void gemm3_body(
    int M, int N, int K,
    const __nv_bfloat16* __restrict__ Ah, const __nv_bfloat16* __restrict__ Al,
    const __nv_bfloat16* __restrict__ Bh, const __nv_bfloat16* __restrict__ Bl,
    const float* __restrict__ bias, const float* __restrict__ res,
    float* __restrict__ C, __nv_bfloat16* __restrict__ Ch,
    __nv_bfloat16* __restrict__ Cl, bool outbf, int bx, int by)
{
    extern __shared__ __align__(16) char smraw[];
    uint32_t smem_u32 = (uint32_t)__cvta_generic_to_shared(smraw);
    int tid = threadIdx.x;
    int lane = tid & 31, warp = tid >> 5;
    int wm = warp >> 2, wn = warp & 3;         // 2x4 warps, tile 64x32
    int gid = lane >> 2, tig = lane & 3;
    int aBase = by * 128, bBase = bx * 128;

    float acc[4][4][4];
    #pragma unroll
    for (int mt = 0; mt < 4; mt++)
        #pragma unroll
        for (int nt = 0; nt < 4; nt++)
            #pragma unroll
            for (int i = 0; i < 4; i++) acc[mt][nt][i] = 0.f;

    int nIter = K / 16;
    #pragma unroll
    for (int s = 0; s < 3; s++) {
        stage_load(smem_u32, s, s * 16, K, Ah, Al, Bh, Bl, aBase, bBase, tid);
        CP_COMMIT();
    }

    uint32_t aoff = (uint32_t)((wm*64 + (lane & 15)) * 48 + (lane >> 4) * 16);
    int brow = wn*32 + ((lane & 7) | (((lane >> 4) & 1) << 3));
    uint32_t boff = (uint32_t)(brow * 48 + ((lane >> 3) & 1) * 16);

    for (int it = 0; it < nIter; it++) {
        CP_WAIT2();
        __syncthreads();
        int s = it & 3;
        int nk = it + 3;
        if (nk < nIter)
            stage_load(smem_u32, nk & 3, nk * 16, K, Ah, Al, Bh, Bl, aBase, bBase, tid);
        CP_COMMIT();

        uint32_t sb = smem_u32 + s * GSTAGE;
        uint32_t bh[2][4], bl[2][4];
        LDSM4(bh[0], sb + 12288 + boff);
        LDSM4(bh[1], sb + 12288 + boff + 768);
        LDSM4(bl[0], sb + 18432 + boff);
        LDSM4(bl[1], sb + 18432 + boff + 768);

        #pragma unroll
        for (int mt = 0; mt < 4; mt++) {
            uint32_t ah[4], al[4];
            LDSM4(ah, sb + aoff + mt * 768);
            LDSM4(al, sb + 6144 + aoff + mt * 768);
            #pragma unroll
            for (int nt = 0; nt < 4; nt++) {
                int p = nt >> 1, q = (nt & 1) * 2;
                MMA_BF16(acc[mt][nt], ah[0], ah[1], ah[2], ah[3],
                         bh[p][q], bh[p][q+1]);
                MMA_BF16(acc[mt][nt], ah[0], ah[1], ah[2], ah[3],
                         bl[p][q], bl[p][q+1]);
                MMA_BF16(acc[mt][nt], al[0], al[1], al[2], al[3],
                         bh[p][q], bh[p][q+1]);
            }
        }
    }

    size_t rowBase = (size_t)by * 128 + wm * 64;
    size_t colBase = (size_t)bx * 128 + wn * 32;
    #pragma unroll
    for (int nt = 0; nt < 4; nt++) {
        size_t c = colBase + nt * 8 + tig * 2;
        float2 bb = *(const float2*)(bias + c);
        #pragma unroll
        for (int mt = 0; mt < 4; mt++) {
            size_t r0 = rowBase + mt * 16 + gid;
            size_t r1 = r0 + 8;
            float2 v0, v1;
            v0.x = acc[mt][nt][0] + bb.x; v0.y = acc[mt][nt][1] + bb.y;
            v1.x = acc[mt][nt][2] + bb.x; v1.y = acc[mt][nt][3] + bb.y;
            if (EPI == 1) {
                v0.x = gelu_fast(v0.x); v0.y = gelu_fast(v0.y);
                v1.x = gelu_fast(v1.x); v1.y = gelu_fast(v1.y);
            }
            if (EPI == 2) {
                float2 q0 = *(const float2*)(res + r0 * N + c);
                float2 q1 = *(const float2*)(res + r1 * N + c);
                v0.x += q0.x; v0.y += q0.y;
                v1.x += q1.x; v1.y += q1.y;
            }
            if (outbf) {
                uint32_t h, l;
                psplit2(v0.x, v0.y, h, l);
                *(uint32_t*)(Ch + r0 * N + c) = h;
                *(uint32_t*)(Cl + r0 * N + c) = l;
                psplit2(v1.x, v1.y, h, l);
                *(uint32_t*)(Ch + r1 * N + c) = h;
                *(uint32_t*)(Cl + r1 * N + c) = l;
            } else {
                *(float2*)(C + r0 * N + c) = v0;
                *(float2*)(C + r1 * N + c) = v1;
            }
        }
    }
}

template<int EPI>
__global__ void __launch_bounds__(256, 2)
gemm3_kernel(int M, int N, int K,
             const __nv_bfloat16* Ah, const __nv_bfloat16* Al,
             const __nv_bfloat16* Bh, const __nv_bfloat16* Bl,
             const float* bias, const float* res,
             float* C, __nv_bfloat16* Ch, __nv_bfloat16* Cl, int outbf)
{
    gemm3_body<EPI>(M, N, K, Ah, Al, Bh, Bl, bias, res, C, Ch, Cl, outbf != 0,
                    blockIdx.x, blockIdx.y);
}

// Fused QKV: q -> bf16 pairs, k/v -> fp32 (quantdq consumes)
__global__ void __launch_bounds__(256, 2)
qkv3_kernel(const __nv_bfloat16* Ah, const __nv_bfloat16* Al,
            const __nv_bfloat16* WqH, const __nv_bfloat16* WqL,
            const __nv_bfloat16* WkH, const __nv_bfloat16* WkL,
            const __nv_bfloat16* WvH, const __nv_bfloat16* WvL,
            const float* bq, const float* bk, const float* bv,
            __nv_bfloat16* Cqh, __nv_bfloat16* Cql,
            float* Ck, float* Cv)
{
    int which = blockIdx.x >> 2;
    int bx = blockIdx.x & 3;
    const __nv_bfloat16* Bh = (which == 0) ? WqH : (which == 1) ? WkH : WvH;
    const __nv_bfloat16* Bl = (which == 0) ? WqL : (which == 1) ? WkL : WvL;
    const float* b = (which == 0) ? bq : (which == 1) ? bk : bv;
    float* C = (which == 1) ? Ck : Cv;
    gemm3_body<0>(ROWS, Dz, Dz, Ah, Al, Bh, Bl, b, nullptr, C, Cqh, Cql,
                  which == 0, bx, blockIdx.y);
}

// ---------------------------------------------------------------------------
// quant-dequant: fp32 in -> bf16 hi/lo out
// ---------------------------------------------------------------------------
__global__ void quantdq_kernel(const float* __restrict__ tk, const float* __restrict__ tv,
                               __nv_bfloat16* __restrict__ okh, __nv_bfloat16* __restrict__ okl,
                               __nv_bfloat16* __restrict__ ovh, __nv_bfloat16* __restrict__ ovl,
                               const float* __restrict__ lvk,
                               const float* __restrict__ lvv)
{
    __shared__ float lv[8];
    const float* t = (blockIdx.y == 0) ? tk : tv;
    __nv_bfloat16* oh = (blockIdx.y == 0) ? okh : ovh;
    __nv_bfloat16* ol = (blockIdx.y == 0) ? okl : ovl;
    const float* levels = (blockIdx.y == 0) ? lvk : lvv;
    if (threadIdx.x < 8) lv[threadIdx.x] = levels[threadIdx.x];
    __syncthreads();
    int warp = threadIdx.x >> 5, lane = threadIdx.x & 31;
    int w = blockIdx.x * 8 + warp;
    size_t off = (size_t)(w / Hz) * Dz + (size_t)(w % Hz) * DKz;
    const float* p = t + off;

    float x0 = p[lane], x1 = p[lane + 32];
    float ss = x0 * x0 + x1 * x1;
    #pragma unroll
    for (int o = 16; o > 0; o >>= 1) ss += __shfl_xor_sync(0xffffffffu, ss, o);
    float nrm = sqrtf(ss);
    float inv = 1.f / (nrm + 1e-8f);
    float u0 = x0 * inv, u1 = x1 * inv;
    float a0 = fabsf(u0), a1 = fabsf(u1);
    float sg0 = (u0 >= 0.f) ? 1.f : -1.f;
    float sg1 = (u1 >= 0.f) ? 1.f : -1.f;

    float q0 = lv[0], b0 = fabsf(a0 - lv[0]);
    float q1 = lv[0], b1 = fabsf(a1 - lv[0]);
    #pragma unroll
    for (int i = 1; i < 8; i++) {
        float d0 = fabsf(a0 - lv[i]);
        if (d0 < b0) { b0 = d0; q0 = lv[i]; }
        float d1 = fabsf(a1 - lv[i]);
        if (d1 < b1) { b1 = d1; q1 = lv[i]; }
    }
    float num = a0 * q0 + a1 * q1;
    float den = q0 * q0 + q1 * q1;
    #pragma unroll
    for (int o = 16; o > 0; o >>= 1) {
        num += __shfl_xor_sync(0xffffffffu, num, o);
        den += __shfl_xor_sync(0xffffffffu, den, o);
    }
    float rmag = num / (den + 1e-8f);
    float r0 = sg0 * q0 * rmag * nrm;
    float r1 = sg1 * q1 * rmag * nrm;
    __nv_bfloat16 h, l;
    bsplit(r0, h, l); oh[off + lane] = h;      ol[off + lane] = l;
    bsplit(r1, h, l); oh[off + lane + 32] = h; ol[off + lane + 32] = l;
}

// ---------------------------------------------------------------------------
// Tensor-core attention (R7, unchanged — passing at 9.45e-5)
// ---------------------------------------------------------------------------
#define AT_STRIDE 144
#define AT_TILE   (64 * AT_STRIDE)
#define AT_Q_H 0
#define AT_Q_L (1 * AT_TILE)
#define AT_K_H (2 * AT_TILE)
#define AT_K_L (3 * AT_TILE)
#define AT_V_H (4 * AT_TILE)
#define AT_V_L (5 * AT_TILE)
#define AT_CB  (6 * AT_TILE)
#define AT_MK  (6 * AT_TILE + 256)
#define ATTN2_SMEM (6 * AT_TILE + 512)

__global__ void __launch_bounds__(128, 1)
attn2_kernel(const __nv_bfloat16* __restrict__ qh, const __nv_bfloat16* __restrict__ ql,
             const __nv_bfloat16* __restrict__ kh, const __nv_bfloat16* __restrict__ kl,
             const __nv_bfloat16* __restrict__ vh, const __nv_bfloat16* __restrict__ vl,
             __nv_bfloat16* __restrict__ o_hi, __nv_bfloat16* __restrict__ o_lo,
             const float* __restrict__ cb, const int* __restrict__ keep)
{
    extern __shared__ __align__(16) char sm2[];
    uint32_t sb = (uint32_t)__cvta_generic_to_shared(sm2);
    float* cbs = (float*)(sm2 + AT_CB);
    float* mks = (float*)(sm2 + AT_MK);

    int tid = threadIdx.x;
    int lane = tid & 31, warp = tid >> 5;
    int gid = lane >> 2, tig = lane & 3;
    int bh = blockIdx.y;
    int b = bh >> 3, h = bh & 7;
    size_t hcol = (size_t)h * DKz;

    uint32_t qaddr_base = (uint32_t)((warp*16 + (lane & 15)) * AT_STRIDE + (lane >> 4) * 16);
    uint32_t krow_off   = (uint32_t)(((lane & 7) | (((lane >> 4) & 1) << 3)) * AT_STRIDE
                                     + ((lane >> 3) & 1) * 16);
    uint32_t vaddr_base = (uint32_t)((lane & 15) * AT_STRIDE + ((lane >> 4) << 3) * 2);

    #pragma unroll
    for (int sub = 0; sub < 2; sub++) {
        int qt = (sub == 0) ? blockIdx.x : 15 - blockIdx.x;
        int q0 = qt * 64;

        #pragma unroll
        for (int i = 0; i < 8; i++) {
            int c = tid + i * 128;
            int arr = c >> 9, r = (c >> 3) & 63, ch = c & 7;
            const __nv_bfloat16* src = (arr ? ql : qh)
                + (size_t)(b * Sz + q0 + r) * Dz + hcol + ch * 8;
            cp16(sb + (arr ? AT_Q_L : AT_Q_H) + r * AT_STRIDE + ch * 16, src);
        }
        CP_COMMIT();

        float acc_o[8][4];
        #pragma unroll
        for (int nt = 0; nt < 8; nt++)
            #pragma unroll
            for (int i = 0; i < 4; i++) acc_o[nt][i] = 0.f;
        float den0 = 0.f, den1 = 0.f;

        for (int kt = 0; kt <= qt; kt++) {
            int k0 = kt * 64;
            #pragma unroll
            for (int i = 0; i < 16; i++) {
                int c = tid + i * 128;
                int arr = c >> 9, r = (c >> 3) & 63, ch = c & 7;
                const __nv_bfloat16* src =
                    (arr == 0 ? kh : arr == 1 ? kl : arr == 2 ? vh : vl)
                    + (size_t)(b * Sz + k0 + r) * Dz + hcol + ch * 8;
                cp16(sb + AT_K_H + arr * AT_TILE + r * AT_STRIDE + ch * 16, src);
            }
            CP_COMMIT();
            if (tid < 64) {
                cbs[tid] = cb[b * Sz + k0 + tid];
                mks[tid] = keep[b * Sz + k0 + tid] ? 1.f : 0.f;
            }
            CP_WAIT0();
            __syncthreads();

            float s[8][4];
            #pragma unroll
            for (int nt = 0; nt < 8; nt++)
                #pragma unroll
                for (int i = 0; i < 4; i++) s[nt][i] = 0.f;

            #pragma unroll
            for (int ks = 0; ks < 4; ks++) {
                uint32_t qa[4], qb[4];
                LDSM4(qa, sb + AT_Q_H + qaddr_base + ks * 32);
                LDSM4(qb, sb + AT_Q_L + qaddr_base + ks * 32);
                uint32_t KH[4][4], KL[4][4];
                #pragma unroll
                for (int g = 0; g < 4; g++) {
                    uint32_t off = (uint32_t)(g * 16 * AT_STRIDE) + krow_off + ks * 32;
                    LDSM4(KH[g], sb + AT_K_H + off);
                    LDSM4(KL[g], sb + AT_K_L + off);
                }
                #pragma unroll
                for (int nt = 0; nt < 8; nt++) {
                    int g = nt >> 1, q = (nt & 1) * 2;
                    MMA_BF16(s[nt], qa[0], qa[1], qa[2], qa[3], KH[g][q], KH[g][q+1]);
                    MMA_BF16(s[nt], qa[0], qa[1], qa[2], qa[3], KL[g][q], KL[g][q+1]);
                    MMA_BF16(s[nt], qb[0], qb[1], qb[2], qb[3], KH[g][q], KH[g][q+1]);
                }
            }

            int qrow = q0 + warp * 16 + gid;
            #pragma unroll
            for (int nt = 0; nt < 8; nt++) {
                #pragma unroll
                for (int i = 0; i < 4; i++) {
                    int kgl = nt * 8 + tig * 2 + (i & 1);
                    int qg = qrow + (i >> 1) * 8;
                    float y = s[nt][i] * 0.125f + cbs[kgl];
                    float u = __expf(y * (1.0f / 15.0f));
                    float p = __expf(30.f - __fdividef(60.f, u + 1.f)) * mks[kgl];
                    s[nt][i] = (k0 + kgl <= qg) ? p : 0.f;
                }
            }
            #pragma unroll
            for (int nt = 0; nt < 8; nt++) {
                den0 += s[nt][0] + s[nt][1];
                den1 += s[nt][2] + s[nt][3];
            }

            #pragma unroll
            for (int j = 0; j < 4; j++) {
                uint32_t pa[4], pb[4];
                psplit2(s[2*j][0],   s[2*j][1],   pa[0], pb[0]);
                psplit2(s[2*j][2],   s[2*j][3],   pa[1], pb[1]);
                psplit2(s[2*j+1][0], s[2*j+1][1], pa[2], pb[2]);
                psplit2(s[2*j+1][2], s[2*j+1][3], pa[3], pb[3]);
                #pragma unroll
                for (int dg = 0; dg < 4; dg++) {
                    uint32_t VH4[4], VL4[4];
                    uint32_t voff = vaddr_base + (uint32_t)(j * 16 * AT_STRIDE) + dg * 32;
                    LDSM4T(VH4, sb + AT_V_H + voff);
                    LDSM4T(VL4, sb + AT_V_L + voff);
                    MMA_BF16(acc_o[2*dg],   pa[0], pa[1], pa[2], pa[3], VH4[0], VH4[1]);
                    MMA_BF16(acc_o[2*dg],   pa[0], pa[1], pa[2], pa[3], VL4[0], VL4[1]);
                    MMA_BF16(acc_o[2*dg],   pb[0], pb[1], pb[2], pb[3], VH4[0], VH4[1]);
                    MMA_BF16(acc_o[2*dg+1], pa[0], pa[1], pa[2], pa[3], VH4[2], VH4[3]);
                    MMA_BF16(acc_o[2*dg+1], pa[0], pa[1], pa[2], pa[3], VL4[2], VL4[3]);
                    MMA_BF16(acc_o[2*dg+1], pb[0], pb[1], pb[2], pb[3], VH4[2], VH4[3]);
                }
            }
            __syncthreads();
        }

        den0 += __shfl_xor_sync(0xffffffffu, den0, 1);
        den0 += __shfl_xor_sync(0xffffffffu, den0, 2);
        den1 += __shfl_xor_sync(0xffffffffu, den1, 1);
        den1 += __shfl_xor_sync(0xffffffffu, den1, 2);
        float i0 = __fdividef(1.f, den0);
        float i1 = __fdividef(1.f, den1);

        size_t r0 = (size_t)(b * Sz + q0 + warp * 16 + gid);
        size_t r1 = r0 + 8;
        #pragma unroll
        for (int nt = 0; nt < 8; nt++) {
            size_t c = hcol + nt * 8 + tig * 2;
            uint32_t hh, ll;
            psplit2(acc_o[nt][0] * i0, acc_o[nt][1] * i0, hh, ll);
            *(uint32_t*)(o_hi + r0 * Dz + c) = hh;
            *(uint32_t*)(o_lo + r0 * Dz + c) = ll;
            psplit2(acc_o[nt][2] * i1, acc_o[nt][3] * i1, hh, ll);
            *(uint32_t*)(o_hi + r1 * Dz + c) = hh;
            *(uint32_t*)(o_lo + r1 * Dz + c) = ll;
        }
    }
}

// ---------------------------------------------------------------------------
// Host launcher
// ---------------------------------------------------------------------------
extern "C" void kernel_launch(void* const* d_in, const int* in_sizes, int n_in,
                              void* d_out, int out_size)
{
    const int*   tok  = (const int*)  d_in[0];
    const float* cnt  = (const float*)d_in[1];
    const float* emb  = (const float*)d_in[2];
    const float* Wq   = (const float*)d_in[3];
    const float* bq   = (const float*)d_in[4];
    const float* Wk   = (const float*)d_in[5];
    const float* bk   = (const float*)d_in[6];
    const float* Wv   = (const float*)d_in[7];
    const float* bv   = (const float*)d_in[8];
    const float* Wo   = (const float*)d_in[9];
    const float* bo   = (const float*)d_in[10];
    const float* ln1g = (const float*)d_in[11];
    const float* ln1b = (const float*)d_in[12];
    const float* ln2g = (const float*)d_in[13];
    const float* ln2b = (const float*)d_in[14];
    const float* W1   = (const float*)d_in[15];
    const float* b1   = (const float*)d_in[16];
    const float* W2   = (const float*)d_in[17];
    const float* b2   = (const float*)d_in[18];
    const float* cbk  = (const float*)d_in[19];
    float* out = (float*)d_out;

    cudaFuncSetAttribute(attn2_kernel, cudaFuncAttributeMaxDynamicSharedMemorySize, ATTN2_SMEM);
    cudaFuncSetAttribute(qkv3_kernel, cudaFuncAttributeMaxDynamicSharedMemorySize, GSMEM);
    cudaFuncSetAttribute(gemm3_kernel<2>, cudaFuncAttributeMaxDynamicSharedMemorySize, GSMEM);
    cudaFuncSetAttribute(gemm3_kernel<1>, cudaFuncAttributeMaxDynamicSharedMemorySize, GSMEM);

    float *px, *pxn, *pk, *pv, *pcb;
    int *pkeep;
    __nv_bfloat16 *pwth, *pwtl, *pxnh, *pxnl, *pqh, *pql, *pkh, *pkl, *pvh, *pvl;
    __nv_bfloat16 *poh, *pol, *ph1h, *ph1l;
    cudaGetSymbolAddress((void**)&px,   g_x);
    cudaGetSymbolAddress((void**)&pxn,  g_xn);
    cudaGetSymbolAddress((void**)&pk,   g_k);
    cudaGetSymbolAddress((void**)&pv,   g_v);
    cudaGetSymbolAddress((void**)&pcb,  g_cb);
    cudaGetSymbolAddress((void**)&pkeep, g_keep);
    cudaGetSymbolAddress((void**)&pwth, g_wth);
    cudaGetSymbolAddress((void**)&pwtl, g_wtl);
    cudaGetSymbolAddress((void**)&pxnh, g_xnh);
    cudaGetSymbolAddress((void**)&pxnl, g_xnl);
    cudaGetSymbolAddress((void**)&pqh,  g_qh);
    cudaGetSymbolAddress((void**)&pql,  g_ql);
    cudaGetSymbolAddress((void**)&pkh,  g_kh);
    cudaGetSymbolAddress((void**)&pkl,  g_kl);
    cudaGetSymbolAddress((void**)&pvh,  g_vh);
    cudaGetSymbolAddress((void**)&pvl,  g_vl);
    cudaGetSymbolAddress((void**)&poh,  g_oh);
    cudaGetSymbolAddress((void**)&pol,  g_ol);
    cudaGetSymbolAddress((void**)&ph1h, g_h1h);
    cudaGetSymbolAddress((void**)&ph1l, g_h1l);

    tsplit_kernel<<<dim3(16,16,Lz), 256>>>(Wq, pwth+OFF_WQ, pwtl+OFF_WQ, Dz, Dz);
    tsplit_kernel<<<dim3(16,16,Lz), 256>>>(Wk, pwth+OFF_WK, pwtl+OFF_WK, Dz, Dz);
    tsplit_kernel<<<dim3(16,16,Lz), 256>>>(Wv, pwth+OFF_WV, pwtl+OFF_WV, Dz, Dz);
    tsplit_kernel<<<dim3(16,16,Lz), 256>>>(Wo, pwth+OFF_WO, pwtl+OFF_WO, Dz, Dz);
    tsplit_kernel<<<dim3(64,16,Lz), 256>>>(W1, pwth+OFF_W1, pwtl+OFF_W1, Dz, DFFz);
    tsplit_kernel<<<dim3(16,64,Lz), 256>>>(W2, pwth+OFF_W2, pwtl+OFF_W2, DFFz, Dz);

    embed_kernel<<<ROWS, 128>>>(tok, cnt, emb);

    dim3 gD(Dz / 128, ROWS / 128);
    dim3 gQKV(12, ROWS / 128);
    dim3 gF(DFFz / 128, ROWS / 128);

    for (int l = 0; l < Lz; l++) {
        layernorm_kernel<<<ROWS, 128>>>(px, ln1g + l*Dz, ln1b + l*Dz, pxn, pxnh, pxnl);

        qkv3_kernel<<<gQKV, 256, GSMEM>>>(pxnh, pxnl,
            pwth + OFF_WQ + (size_t)l*DD, pwtl + OFF_WQ + (size_t)l*DD,
            pwth + OFF_WK + (size_t)l*DD, pwtl + OFF_WK + (size_t)l*DD,
            pwth + OFF_WV + (size_t)l*DD, pwtl + OFF_WV + (size_t)l*DD,
            bq + l*Dz, bk + l*Dz, bv + l*Dz, pqh, pql, pk, pv);

        quantdq_kernel<<<dim3(ROWS * Hz / 8, 2), 256>>>(
            pk, pv, pkh, pkl, pvh, pvl,
            cbk + (size_t)(l*2 + 0)*8, cbk + (size_t)(l*2 + 1)*8);

        attn2_kernel<<<dim3(8, Bz*Hz), 128, ATTN2_SMEM>>>(
            pqh, pql, pkh, pkl, pvh, pvl, poh, pol, pcb, pkeep);

        gemm3_kernel<2><<<gD, 256, GSMEM>>>(ROWS, Dz, Dz, poh, pol,
            pwth + OFF_WO + (size_t)l*DD, pwtl + OFF_WO + (size_t)l*DD,
            bo + l*Dz, pxn, px, nullptr, nullptr, 0);

        layernorm_kernel<<<ROWS, 128>>>(px, ln2g + l*Dz, ln2b + l*Dz, pxn, pxnh, pxnl);

        gemm3_kernel<1><<<gF, 256, GSMEM>>>(ROWS, DFFz, Dz, pxnh, pxnl,
            pwth + OFF_W1 + (size_t)l*DF, pwtl + OFF_W1 + (size_t)l*DF,
            b1 + l*DFFz, nullptr, nullptr, ph1h, ph1l, 1);

        float* dst = (l == Lz - 1) ? out : px;
        gemm3_kernel<2><<<gD, 256, GSMEM>>>(ROWS, Dz, DFFz, ph1h, ph1l,
            pwth + OFF_W2 + (size_t)l*DF, pwtl + OFF_W2 + (size_t)l*DF,
            b2 + l*Dz, pxn, dst, nullptr, nullptr, 0);
    }
}

// round 13
// speedup vs baseline: 2.8426x; 1.0160x over previous
#include <cuda_runtime.h>
#include <cuda_bf16.h>
#include <cstdint>

// Problem constants
#define Bz 4
#define Sz 1024
#define Dz 512
#define Hz 8
#define DKz 64
#define Lz 4
#define DFFz 2048
#define SOFTCAP 30.0f
#define PAD_IDX 0
#define START_IDX 1

#define ROWS (Bz*Sz)           // 4096
#define XSZ  (ROWS*Dz)         // 2,097,152
#define H1SZ (ROWS*DFFz)       // 8,388,608
#define DD   (Dz*Dz)
#define DF   (Dz*DFFz)

#define OFF_WQ 0
#define OFF_WK (4*DD)
#define OFF_WV (8*DD)
#define OFF_WO (12*DD)
#define OFF_W1 (16*DD)
#define OFF_W2 (16*DD + 4*DF)
#define WT_TOT (16*DD + 8*DF)

// Persistent scratch
__device__ float g_x[XSZ];
__device__ float g_xn[XSZ];
__device__ float g_k[XSZ];
__device__ float g_v[XSZ];
__device__ float g_cb[ROWS];
__device__ int   g_keep[ROWS];
__device__ __align__(16) __nv_bfloat16 g_wth[WT_TOT];
__device__ __align__(16) __nv_bfloat16 g_wtl[WT_TOT];
__device__ __align__(16) __nv_bfloat16 g_xnh[XSZ], g_xnl[XSZ];
__device__ __align__(16) __nv_bfloat16 g_qh[XSZ],  g_ql[XSZ];
__device__ __align__(16) __nv_bfloat16 g_kh[XSZ],  g_kl[XSZ];
__device__ __align__(16) __nv_bfloat16 g_vh[XSZ],  g_vl[XSZ];
__device__ __align__(16) __nv_bfloat16 g_oh[XSZ],  g_ol[XSZ];
__device__ __align__(16) __nv_bfloat16 g_h1h[H1SZ], g_h1l[H1SZ];

// ---------------------------------------------------------------------------
// helpers
// ---------------------------------------------------------------------------
__device__ __forceinline__ void bsplit(float x, __nv_bfloat16& h, __nv_bfloat16& l)
{
    h = __float2bfloat16_rn(x);
    l = __float2bfloat16_rn(x - __bfloat162float(h));
}
__device__ __forceinline__ uint32_t bpack(__nv_bfloat16 a, __nv_bfloat16 b)
{
    uint16_t ua = *reinterpret_cast<uint16_t*>(&a);
    uint16_t ub = *reinterpret_cast<uint16_t*>(&b);
    return (uint32_t)ua | ((uint32_t)ub << 16);
}
__device__ __forceinline__ void psplit2(float x, float y, uint32_t& h, uint32_t& l)
{
    __nv_bfloat16 hx, lx, hy, ly;
    bsplit(x, hx, lx); bsplit(y, hy, ly);
    h = bpack(hx, hy); l = bpack(lx, ly);
}
__device__ __forceinline__ float gelu_fast(float x)
{
    float t = 0.7978845608028654f * (x + 0.044715f * x * x * x);
    float e = __expf(2.f * t);
    return x - x * __fdividef(1.f, e + 1.f);
}

#define MMA_BF16(d, a0, a1, a2, a3, b0, b1) \
    asm volatile("mma.sync.aligned.m16n8k16.row.col.f32.bf16.bf16.f32 " \
        "{%0,%1,%2,%3},{%4,%5,%6,%7},{%8,%9},{%0,%1,%2,%3};" \
        : "+f"(d[0]), "+f"(d[1]), "+f"(d[2]), "+f"(d[3]) \
        : "r"(a0), "r"(a1), "r"(a2), "r"(a3), "r"(b0), "r"(b1))

#define LDSM4(r, addr) \
    asm volatile("ldmatrix.sync.aligned.m8n8.x4.shared.b16 {%0,%1,%2,%3},[%4];" \
        : "=r"((r)[0]), "=r"((r)[1]), "=r"((r)[2]), "=r"((r)[3]) : "r"(addr))
#define LDSM4T(r, addr) \
    asm volatile("ldmatrix.sync.aligned.m8n8.x4.trans.shared.b16 {%0,%1,%2,%3},[%4];" \
        : "=r"((r)[0]), "=r"((r)[1]), "=r"((r)[2]), "=r"((r)[3]) : "r"(addr))

__device__ __forceinline__ void cp16(uint32_t dst, const void* src)
{
    uint64_t g = (uint64_t)__cvta_generic_to_global(src);
    asm volatile("cp.async.cg.shared.global [%0], [%1], 16;" :: "r"(dst), "l"(g));
}
#define CP_COMMIT() asm volatile("cp.async.commit_group;")
#define CP_WAIT2()  asm volatile("cp.async.wait_group 2;")
#define CP_WAIT1()  asm volatile("cp.async.wait_group 1;")
#define CP_WAIT0()  asm volatile("cp.async.wait_group 0;")

// ---------------------------------------------------------------------------
// Embedding
// ---------------------------------------------------------------------------
__global__ void embed_kernel(const int* __restrict__ tok,
                             const float* __restrict__ cnt,
                             const float* __restrict__ emb)
{
    int r = blockIdx.x;
    int b = r / Sz, s = r % Sz;
    int t; float c;
    if (s == 0) { t = START_IDX; c = 1.0f; }
    else        { t = tok[b*Sz + s - 1]; c = cnt[b*Sz + s - 1]; }
    if (threadIdx.x == 0) {
        g_cb[r]   = log1pf(c + 1e-6f);
        g_keep[r] = (t != PAD_IDX);
    }
    const float4* src = (const float4*)(emb + (size_t)t * Dz);
    float4* dst = (float4*)(g_x + (size_t)r * Dz);
    dst[threadIdx.x] = src[threadIdx.x];
}

// ---------------------------------------------------------------------------
// Merged weight transpose + bf16 split: ALL weights in ONE launch.
// blockIdx.x in [0, 12288): [0,4096)=WQ/WK/WV/WO, [4096,8192)=W1, [8192,12288)=W2
// ---------------------------------------------------------------------------
__global__ void tsplit_all_kernel(const float* __restrict__ Wq, const float* __restrict__ Wk,
                                  const float* __restrict__ Wv, const float* __restrict__ Wo,
                                  const float* __restrict__ W1, const float* __restrict__ W2,
                                  __nv_bfloat16* __restrict__ dh_base,
                                  __nv_bfloat16* __restrict__ dl_base)
{
    __shared__ float t[32][33];
    int bid = blockIdx.x;
    const float* src; size_t doff; int K, N, n0, k0;
    if (bid < 4096) {
        int w = bid >> 10, r = bid & 1023;
        int layer = r >> 8, tt = r & 255;
        src  = ((w == 0) ? Wq : (w == 1) ? Wk : (w == 2) ? Wv : Wo) + (size_t)layer * DD;
        doff = (size_t)w * 4 * DD + (size_t)layer * DD;
        K = Dz; N = Dz;
        n0 = (tt & 15) * 32; k0 = (tt >> 4) * 32;
    } else if (bid < 8192) {
        int r = bid - 4096, layer = r >> 10, tt = r & 1023;
        src  = W1 + (size_t)layer * DF;
        doff = (size_t)OFF_W1 + (size_t)layer * DF;
        K = Dz; N = DFFz;
        n0 = (tt & 63) * 32; k0 = (tt >> 6) * 32;
    } else {
        int r = bid - 8192, layer = r >> 10, tt = r & 1023;
        src  = W2 + (size_t)layer * DF;
        doff = (size_t)OFF_W2 + (size_t)layer * DF;
        K = DFFz; N = Dz;
        n0 = (tt & 15) * 32; k0 = (tt >> 4) * 32;
    }
    __nv_bfloat16* dh = dh_base + doff;
    __nv_bfloat16* dl = dl_base + doff;
    int tx = threadIdx.x & 31, ty = threadIdx.x >> 5;
    #pragma unroll
    for (int i = 0; i < 4; i++)
        t[ty + 8*i][tx] = src[(size_t)(k0 + ty + 8*i) * N + n0 + tx];
    __syncthreads();
    #pragma unroll
    for (int i = 0; i < 4; i++) {
        float v = t[tx][ty + 8*i];
        __nv_bfloat16 h, l; bsplit(v, h, l);
        size_t idx = (size_t)(n0 + ty + 8*i) * K + k0 + tx;
        dh[idx] = h; dl[idx] = l;
    }
}

// ---------------------------------------------------------------------------
// LayerNorm -> fp32 + bf16 hi/lo
// ---------------------------------------------------------------------------
__device__ __forceinline__ float block_reduce_sum(float v, float* red)
{
    int lane = threadIdx.x & 31, warp = threadIdx.x >> 5;
    #pragma unroll
    for (int o = 16; o > 0; o >>= 1) v += __shfl_xor_sync(0xffffffffu, v, o);
    if (lane == 0) red[warp] = v;
    __syncthreads();
    float r = 0.f;
    if (warp == 0) {
        r = (lane < (blockDim.x >> 5)) ? red[lane] : 0.f;
        #pragma unroll
        for (int o = 16; o > 0; o >>= 1) r += __shfl_xor_sync(0xffffffffu, r, o);
        if (lane == 0) red[0] = r;
    }
    __syncthreads();
    r = red[0];
    __syncthreads();
    return r;
}

__global__ void layernorm_kernel(const float* __restrict__ x,
                                 const float* __restrict__ gam,
                                 const float* __restrict__ bet,
                                 float* __restrict__ out,
                                 __nv_bfloat16* __restrict__ outh,
                                 __nv_bfloat16* __restrict__ outl)
{
    __shared__ float red[32];
    int r = blockIdx.x;
    const float4* xr = (const float4*)(x + (size_t)r * Dz);
    float4 v = xr[threadIdx.x];
    float s = v.x + v.y + v.z + v.w;
    float tot = block_reduce_sum(s, red);
    float mu = tot * (1.0f / Dz);
    float d0 = v.x - mu, d1 = v.y - mu, d2 = v.z - mu, d3 = v.w - mu;
    float sq = d0*d0 + d1*d1 + d2*d2 + d3*d3;
    float var = block_reduce_sum(sq, red) * (1.0f / Dz);
    float rstd = rsqrtf(var + 1e-5f);
    float4 gg = ((const float4*)gam)[threadIdx.x];
    float4 bb = ((const float4*)bet)[threadIdx.x];
    float4 o;
    o.x = d0 * rstd * gg.x + bb.x;
    o.y = d1 * rstd * gg.y + bb.y;
    o.z = d2 * rstd * gg.z + bb.z;
    o.w = d3 * rstd * gg.w + bb.w;
    ((float4*)(out + (size_t)r * Dz))[threadIdx.x] = o;
    uint32_t h0, l0, h1, l1;
    psplit2(o.x, o.y, h0, l0);
    psplit2(o.z, o.w, h1, l1);
    uint2 ph = { h0, h1 }, pl = { l0, l1 };
    *(uint2*)(outh + (size_t)r * Dz + threadIdx.x * 4) = ph;
    *(uint2*)(outl + (size_t)r * Dz + threadIdx.x * 4) = pl;
}

// ---------------------------------------------------------------------------
// GEMM v4 (unchanged from R11 passing version)
// ---------------------------------------------------------------------------
#define GSTAGE 24576
#define GSMEM  (4 * GSTAGE)

__device__ __forceinline__ void stage_load(
    uint32_t smem_u32, int s, int k0, int K,
    const __nv_bfloat16* Ah, const __nv_bfloat16* Al,
    const __nv_bfloat16* Bh, const __nv_bfloat16* Bl,
    int aBase, int bBase, int tid)
{
    #pragma unroll
    for (int rep = 0; rep < 4; rep++) {
        int c = tid + rep * 256;
        int arr = c >> 8, r = (c >> 1) & 127, h = c & 1;
        const __nv_bfloat16* g =
            (arr == 0) ? Ah + (size_t)(aBase + r) * K :
            (arr == 1) ? Al + (size_t)(aBase + r) * K :
            (arr == 2) ? Bh + (size_t)(bBase + r) * K :
                         Bl + (size_t)(bBase + r) * K;
        uint32_t dst = smem_u32 + s * GSTAGE + arr * 6144 + r * 48 + h * 16;
        cp16(dst, g + k0 + h * 8);
    }
}

template<int EPI>
__device__ __forceinline__ void gemm3_body(
    int M, int N, int K,
    const __nv_bfloat16* __restrict__ Ah, const __nv_bfloat16* __restrict__ Al,
    const __nv_bfloat16* __restrict__ Bh, const __nv_bfloat16* __restrict__ Bl,
    const float* __restrict__ bias, const float* __restrict__ res,
    float* __restrict__ C, __nv_bfloat16* __restrict__ Ch,
    __nv_bfloat16* __restrict__ Cl, bool outbf, int bx, int by)
{
    extern __shared__ __align__(16) char smraw[];
    uint32_t smem_u32 = (uint32_t)__cvta_generic_to_shared(smraw);
    int tid = threadIdx.x;
    int lane = tid & 31, warp = tid >> 5;
    int wm = warp >> 2, wn = warp & 3;
    int gid = lane >> 2, tig = lane & 3;
    int aBase = by * 128, bBase = bx * 128;

    float acc[4][4][4];
    #pragma unroll
    for (int mt = 0; mt < 4; mt++)
        #pragma unroll
        for (int nt = 0; nt < 4; nt++)
            #pragma unroll
            for (int i = 0; i < 4; i++) acc[mt][nt][i] = 0.f;

    int nIter = K / 16;
    #pragma unroll
    for (int s = 0; s < 3; s++) {
        stage_load(smem_u32, s, s * 16, K, Ah, Al, Bh, Bl, aBase, bBase, tid);
        CP_COMMIT();
    }

    uint32_t aoff = (uint32_t)((wm*64 + (lane & 15)) * 48 + (lane >> 4) * 16);
    int brow = wn*32 + ((lane & 7) | (((lane >> 4) & 1) << 3));
    uint32_t boff = (uint32_t)(brow * 48 + ((lane >> 3) & 1) * 16);

    for (int it = 0; it < nIter; it++) {
        CP_WAIT2();
        __syncthreads();
        int s = it & 3;
        int nk = it + 3;
        if (nk < nIter)
            stage_load(smem_u32, nk & 3, nk * 16, K, Ah, Al, Bh, Bl, aBase, bBase, tid);
        CP_COMMIT();

        uint32_t sb = smem_u32 + s * GSTAGE;
        uint32_t bh[2][4], bl[2][4];
        LDSM4(bh[0], sb + 12288 + boff);
        LDSM4(bh[1], sb + 12288 + boff + 768);
        LDSM4(bl[0], sb + 18432 + boff);
        LDSM4(bl[1], sb + 18432 + boff + 768);

        #pragma unroll
        for (int mt = 0; mt < 4; mt++) {
            uint32_t ah[4], al[4];
            LDSM4(ah, sb + aoff + mt * 768);
            LDSM4(al, sb + 6144 + aoff + mt * 768);
            #pragma unroll
            for (int nt = 0; nt < 4; nt++) {
                int p = nt >> 1, q = (nt & 1) * 2;
                MMA_BF16(acc[mt][nt], ah[0], ah[1], ah[2], ah[3],
                         bh[p][q], bh[p][q+1]);
                MMA_BF16(acc[mt][nt], ah[0], ah[1], ah[2], ah[3],
                         bl[p][q], bl[p][q+1]);
                MMA_BF16(acc[mt][nt], al[0], al[1], al[2], al[3],
                         bh[p][q], bh[p][q+1]);
            }
        }
    }

    size_t rowBase = (size_t)by * 128 + wm * 64;
    size_t colBase = (size_t)bx * 128 + wn * 32;
    #pragma unroll
    for (int nt = 0; nt < 4; nt++) {
        size_t c = colBase + nt * 8 + tig * 2;
        float2 bb = *(const float2*)(bias + c);
        #pragma unroll
        for (int mt = 0; mt < 4; mt++) {
            size_t r0 = rowBase + mt * 16 + gid;
            size_t r1 = r0 + 8;
            float2 v0, v1;
            v0.x = acc[mt][nt][0] + bb.x; v0.y = acc[mt][nt][1] + bb.y;
            v1.x = acc[mt][nt][2] + bb.x; v1.y = acc[mt][nt][3] + bb.y;
            if (EPI == 1) {
                v0.x = gelu_fast(v0.x); v0.y = gelu_fast(v0.y);
                v1.x = gelu_fast(v1.x); v1.y = gelu_fast(v1.y);
            }
            if (EPI == 2) {
                float2 q0 = *(const float2*)(res + r0 * N + c);
                float2 q1 = *(const float2*)(res + r1 * N + c);
                v0.x += q0.x; v0.y += q0.y;
                v1.x += q1.x; v1.y += q1.y;
            }
            if (outbf) {
                uint32_t h, l;
                psplit2(v0.x, v0.y, h, l);
                *(uint32_t*)(Ch + r0 * N + c) = h;
                *(uint32_t*)(Cl + r0 * N + c) = l;
                psplit2(v1.x, v1.y, h, l);
                *(uint32_t*)(Ch + r1 * N + c) = h;
                *(uint32_t*)(Cl + r1 * N + c) = l;
            } else {
                *(float2*)(C + r0 * N + c) = v0;
                *(float2*)(C + r1 * N + c) = v1;
            }
        }
    }
}

template<int EPI>
__global__ void __launch_bounds__(256, 2)
gemm3_kernel(int M, int N, int K,
             const __nv_bfloat16* Ah, const __nv_bfloat16* Al,
             const __nv_bfloat16* Bh, const __nv_bfloat16* Bl,
             const float* bias, const float* res,
             float* C, __nv_bfloat16* Ch, __nv_bfloat16* Cl, int outbf)
{
    gemm3_body<EPI>(M, N, K, Ah, Al, Bh, Bl, bias, res, C, Ch, Cl, outbf != 0,
                    blockIdx.x, blockIdx.y);
}

__global__ void __launch_bounds__(256, 2)
qkv3_kernel(const __nv_bfloat16* Ah, const __nv_bfloat16* Al,
            const __nv_bfloat16* WqH, const __nv_bfloat16* WqL,
            const __nv_bfloat16* WkH, const __nv_bfloat16* WkL,
            const __nv_bfloat16* WvH, const __nv_bfloat16* WvL,
            const float* bq, const float* bk, const float* bv,
            __nv_bfloat16* Cqh, __nv_bfloat16* Cql,
            float* Ck, float* Cv)
{
    int which = blockIdx.x >> 2;
    int bx = blockIdx.x & 3;
    const __nv_bfloat16* Bh = (which == 0) ? WqH : (which == 1) ? WkH : WvH;
    const __nv_bfloat16* Bl = (which == 0) ? WqL : (which == 1) ? WkL : WvL;
    const float* b = (which == 0) ? bq : (which == 1) ? bk : bv;
    float* C = (which == 1) ? Ck : Cv;
    gemm3_body<0>(ROWS, Dz, Dz, Ah, Al, Bh, Bl, b, nullptr, C, Cqh, Cql,
                  which == 0, bx, blockIdx.y);
}

// ---------------------------------------------------------------------------
// quant-dequant: fp32 in -> bf16 hi/lo out
// ---------------------------------------------------------------------------
__global__ void quantdq_kernel(const float* __restrict__ tk, const float* __restrict__ tv,
                               __nv_bfloat16* __restrict__ okh, __nv_bfloat16* __restrict__ okl,
                               __nv_bfloat16* __restrict__ ovh, __nv_bfloat16* __restrict__ ovl,
                               const float* __restrict__ lvk,
                               const float* __restrict__ lvv)
{
    __shared__ float lv[8];
    const float* t = (blockIdx.y == 0) ? tk : tv;
    __nv_bfloat16* oh = (blockIdx.y == 0) ? okh : ovh;
    __nv_bfloat16* ol = (blockIdx.y == 0) ? okl : ovl;
    const float* levels = (blockIdx.y == 0) ? lvk : lvv;
    if (threadIdx.x < 8) lv[threadIdx.x] = levels[threadIdx.x];
    __syncthreads();
    int warp = threadIdx.x >> 5, lane = threadIdx.x & 31;
    int w = blockIdx.x * 8 + warp;
    size_t off = (size_t)(w / Hz) * Dz + (size_t)(w % Hz) * DKz;
    const float* p = t + off;

    float x0 = p[lane], x1 = p[lane + 32];
    float ss = x0 * x0 + x1 * x1;
    #pragma unroll
    for (int o = 16; o > 0; o >>= 1) ss += __shfl_xor_sync(0xffffffffu, ss, o);
    float nrm = sqrtf(ss);
    float inv = 1.f / (nrm + 1e-8f);
    float u0 = x0 * inv, u1 = x1 * inv;
    float a0 = fabsf(u0), a1 = fabsf(u1);
    float sg0 = (u0 >= 0.f) ? 1.f : -1.f;
    float sg1 = (u1 >= 0.f) ? 1.f : -1.f;

    float q0 = lv[0], b0 = fabsf(a0 - lv[0]);
    float q1 = lv[0], b1 = fabsf(a1 - lv[0]);
    #pragma unroll
    for (int i = 1; i < 8; i++) {
        float d0 = fabsf(a0 - lv[i]);
        if (d0 < b0) { b0 = d0; q0 = lv[i]; }
        float d1 = fabsf(a1 - lv[i]);
        if (d1 < b1) { b1 = d1; q1 = lv[i]; }
    }
    float num = a0 * q0 + a1 * q1;
    float den = q0 * q0 + q1 * q1;
    #pragma unroll
    for (int o = 16; o > 0; o >>= 1) {
        num += __shfl_xor_sync(0xffffffffu, num, o);
        den += __shfl_xor_sync(0xffffffffu, den, o);
    }
    float rmag = num / (den + 1e-8f);
    float r0 = sg0 * q0 * rmag * nrm;
    float r1 = sg1 * q1 * rmag * nrm;
    __nv_bfloat16 h, l;
    bsplit(r0, h, l); oh[off + lane] = h;      ol[off + lane] = l;
    bsplit(r1, h, l); oh[off + lane + 32] = h; ol[off + lane + 32] = l;
}

// ---------------------------------------------------------------------------
// Tensor-core attention v2: double-buffered K/V tiles (prefetch kt+1 during
// compute of kt). Q(2 tiles) + K/V(2 stages x 4 tiles) = 92KB smem.
// ---------------------------------------------------------------------------
#define AT_STRIDE 144
#define AT_TILE   (64 * AT_STRIDE)       // 9216
#define AT2_Q_H   0
#define AT2_Q_L   AT_TILE
#define AT2_KV(s) (2*AT_TILE + (s)*(4*AT_TILE))   // K_H,K_L,V_H,V_L consecutive
#define AT2_CB    (10*AT_TILE)                     // float cbs[2][64]; mks[2][64]
#define ATTN2_SMEM (10*AT_TILE + 1024)             // 93,184

__device__ __forceinline__ void at_load_kv(
    uint32_t sb, int s,
    const __nv_bfloat16* kh, const __nv_bfloat16* kl,
    const __nv_bfloat16* vh, const __nv_bfloat16* vl,
    int b, int k0, size_t hcol, int tid)
{
    #pragma unroll
    for (int i = 0; i < 16; i++) {
        int c = tid + i * 128;
        int arr = c >> 9, r = (c >> 3) & 63, ch = c & 7;
        const __nv_bfloat16* src =
            (arr == 0 ? kh : arr == 1 ? kl : arr == 2 ? vh : vl)
            + (size_t)(b * Sz + k0 + r) * Dz + hcol + ch * 8;
        cp16(sb + AT2_KV(s) + arr * AT_TILE + r * AT_STRIDE + ch * 16, src);
    }
}

__global__ void __launch_bounds__(128, 1)
attn2_kernel(const __nv_bfloat16* __restrict__ qh, const __nv_bfloat16* __restrict__ ql,
             const __nv_bfloat16* __restrict__ kh, const __nv_bfloat16* __restrict__ kl,
             const __nv_bfloat16* __restrict__ vh, const __nv_bfloat16* __restrict__ vl,
             __nv_bfloat16* __restrict__ o_hi, __nv_bfloat16* __restrict__ o_lo,
             const float* __restrict__ cb, const int* __restrict__ keep)
{
    extern __shared__ __align__(16) char sm2[];
    uint32_t sb = (uint32_t)__cvta_generic_to_shared(sm2);
    float* cbs = (float*)(sm2 + AT2_CB);        // [2][64]
    float* mks = cbs + 128;                     // [2][64]

    int tid = threadIdx.x;
    int lane = tid & 31, warp = tid >> 5;
    int gid = lane >> 2, tig = lane & 3;
    int bh = blockIdx.y;
    int b = bh >> 3, h = bh & 7;
    size_t hcol = (size_t)h * DKz;

    uint32_t qaddr_base = (uint32_t)((warp*16 + (lane & 15)) * AT_STRIDE + (lane >> 4) * 16);
    uint32_t krow_off   = (uint32_t)(((lane & 7) | (((lane >> 4) & 1) << 3)) * AT_STRIDE
                                     + ((lane >> 3) & 1) * 16);
    uint32_t vaddr_base = (uint32_t)((lane & 15) * AT_STRIDE + ((lane >> 4) << 3) * 2);

    #pragma unroll
    for (int sub = 0; sub < 2; sub++) {
        int qt = (sub == 0) ? blockIdx.x : 15 - blockIdx.x;
        int q0 = qt * 64;

        // Q tiles (own group)
        #pragma unroll
        for (int i = 0; i < 8; i++) {
            int c = tid + i * 128;
            int arr = c >> 9, r = (c >> 3) & 63, ch = c & 7;
            const __nv_bfloat16* src = (arr ? ql : qh)
                + (size_t)(b * Sz + q0 + r) * Dz + hcol + ch * 8;
            cp16(sb + (arr ? AT2_Q_L : AT2_Q_H) + r * AT_STRIDE + ch * 16, src);
        }
        CP_COMMIT();
        // KV tile 0 into stage 0 (own group)
        at_load_kv(sb, 0, kh, kl, vh, vl, b, 0, hcol, tid);
        CP_COMMIT();
        if (tid < 64) {
            cbs[tid] = cb[b * Sz + tid];
            mks[tid] = keep[b * Sz + tid] ? 1.f : 0.f;
        }

        float acc_o[8][4];
        #pragma unroll
        for (int nt = 0; nt < 8; nt++)
            #pragma unroll
            for (int i = 0; i < 4; i++) acc_o[nt][i] = 0.f;
        float den0 = 0.f, den1 = 0.f;

        for (int kt = 0; kt <= qt; kt++) {
            int stg = kt & 1;
            bool more = (kt + 1 <= qt);
            if (more) {
                at_load_kv(sb, stg ^ 1, kh, kl, vh, vl, b, (kt + 1) * 64, hcol, tid);
                CP_COMMIT();
                if (tid < 64) {
                    cbs[(stg ^ 1) * 64 + tid] = cb[b * Sz + (kt + 1) * 64 + tid];
                    mks[(stg ^ 1) * 64 + tid] = keep[b * Sz + (kt + 1) * 64 + tid] ? 1.f : 0.f;
                }
                CP_WAIT1();
            } else {
                CP_WAIT0();
            }
            __syncthreads();

            uint32_t kvb = sb + AT2_KV(stg);
            int k0 = kt * 64;
            float* cbt = cbs + stg * 64;
            float* mkt = mks + stg * 64;

            float s[8][4];
            #pragma unroll
            for (int nt = 0; nt < 8; nt++)
                #pragma unroll
                for (int i = 0; i < 4; i++) s[nt][i] = 0.f;

            #pragma unroll
            for (int ks = 0; ks < 4; ks++) {
                uint32_t qa[4], qb[4];
                LDSM4(qa, sb + AT2_Q_H + qaddr_base + ks * 32);
                LDSM4(qb, sb + AT2_Q_L + qaddr_base + ks * 32);
                uint32_t KH[4][4], KL[4][4];
                #pragma unroll
                for (int g = 0; g < 4; g++) {
                    uint32_t off = (uint32_t)(g * 16 * AT_STRIDE) + krow_off + ks * 32;
                    LDSM4(KH[g], kvb + off);
                    LDSM4(KL[g], kvb + AT_TILE + off);
                }
                #pragma unroll
                for (int nt = 0; nt < 8; nt++) {
                    int g = nt >> 1, q = (nt & 1) * 2;
                    MMA_BF16(s[nt], qa[0], qa[1], qa[2], qa[3], KH[g][q], KH[g][q+1]);
                    MMA_BF16(s[nt], qa[0], qa[1], qa[2], qa[3], KL[g][q], KL[g][q+1]);
                    MMA_BF16(s[nt], qb[0], qb[1], qb[2], qb[3], KH[g][q], KH[g][q+1]);
                }
            }

            int qrow = q0 + warp * 16 + gid;
            #pragma unroll
            for (int nt = 0; nt < 8; nt++) {
                #pragma unroll
                for (int i = 0; i < 4; i++) {
                    int kgl = nt * 8 + tig * 2 + (i & 1);
                    int qg = qrow + (i >> 1) * 8;
                    float y = s[nt][i] * 0.125f + cbt[kgl];
                    float u = __expf(y * (1.0f / 15.0f));
                    float p = __expf(30.f - __fdividef(60.f, u + 1.f)) * mkt[kgl];
                    s[nt][i] = (k0 + kgl <= qg) ? p : 0.f;
                }
            }
            #pragma unroll
            for (int nt = 0; nt < 8; nt++) {
                den0 += s[nt][0] + s[nt][1];
                den1 += s[nt][2] + s[nt][3];
            }

            #pragma unroll
            for (int j = 0; j < 4; j++) {
                uint32_t pa[4], pb[4];
                psplit2(s[2*j][0],   s[2*j][1],   pa[0], pb[0]);
                psplit2(s[2*j][2],   s[2*j][3],   pa[1], pb[1]);
                psplit2(s[2*j+1][0], s[2*j+1][1], pa[2], pb[2]);
                psplit2(s[2*j+1][2], s[2*j+1][3], pa[3], pb[3]);
                #pragma unroll
                for (int dg = 0; dg < 4; dg++) {
                    uint32_t VH4[4], VL4[4];
                    uint32_t voff = vaddr_base + (uint32_t)(j * 16 * AT_STRIDE) + dg * 32;
                    LDSM4T(VH4, kvb + 2 * AT_TILE + voff);
                    LDSM4T(VL4, kvb + 3 * AT_TILE + voff);
                    MMA_BF16(acc_o[2*dg],   pa[0], pa[1], pa[2], pa[3], VH4[0], VH4[1]);
                    MMA_BF16(acc_o[2*dg],   pa[0], pa[1], pa[2], pa[3], VL4[0], VL4[1]);
                    MMA_BF16(acc_o[2*dg],   pb[0], pb[1], pb[2], pb[3], VH4[0], VH4[1]);
                    MMA_BF16(acc_o[2*dg+1], pa[0], pa[1], pa[2], pa[3], VH4[2], VH4[3]);
                    MMA_BF16(acc_o[2*dg+1], pa[0], pa[1], pa[2], pa[3], VL4[2], VL4[3]);
                    MMA_BF16(acc_o[2*dg+1], pb[0], pb[1], pb[2], pb[3], VH4[2], VH4[3]);
                }
            }
            __syncthreads();
        }

        den0 += __shfl_xor_sync(0xffffffffu, den0, 1);
        den0 += __shfl_xor_sync(0xffffffffu, den0, 2);
        den1 += __shfl_xor_sync(0xffffffffu, den1, 1);
        den1 += __shfl_xor_sync(0xffffffffu, den1, 2);
        float i0 = __fdividef(1.f, den0);
        float i1 = __fdividef(1.f, den1);

        size_t r0 = (size_t)(b * Sz + q0 + warp * 16 + gid);
        size_t r1 = r0 + 8;
        #pragma unroll
        for (int nt = 0; nt < 8; nt++) {
            size_t c = hcol + nt * 8 + tig * 2;
            uint32_t hh, ll;
            psplit2(acc_o[nt][0] * i0, acc_o[nt][1] * i0, hh, ll);
            *(uint32_t*)(o_hi + r0 * Dz + c) = hh;
            *(uint32_t*)(o_lo + r0 * Dz + c) = ll;
            psplit2(acc_o[nt][2] * i1, acc_o[nt][3] * i1, hh, ll);
            *(uint32_t*)(o_hi + r1 * Dz + c) = hh;
            *(uint32_t*)(o_lo + r1 * Dz + c) = ll;
        }
    }
}

// ---------------------------------------------------------------------------
// Host launcher
// ---------------------------------------------------------------------------
extern "C" void kernel_launch(void* const* d_in, const int* in_sizes, int n_in,
                              void* d_out, int out_size)
{
    const int*   tok  = (const int*)  d_in[0];
    const float* cnt  = (const float*)d_in[1];
    const float* emb  = (const float*)d_in[2];
    const float* Wq   = (const float*)d_in[3];
    const float* bq   = (const float*)d_in[4];
    const float* Wk   = (const float*)d_in[5];
    const float* bk   = (const float*)d_in[6];
    const float* Wv   = (const float*)d_in[7];
    const float* bv   = (const float*)d_in[8];
    const float* Wo   = (const float*)d_in[9];
    const float* bo   = (const float*)d_in[10];
    const float* ln1g = (const float*)d_in[11];
    const float* ln1b = (const float*)d_in[12];
    const float* ln2g = (const float*)d_in[13];
    const float* ln2b = (const float*)d_in[14];
    const float* W1   = (const float*)d_in[15];
    const float* b1   = (const float*)d_in[16];
    const float* W2   = (const float*)d_in[17];
    const float* b2   = (const float*)d_in[18];
    const float* cbk  = (const float*)d_in[19];
    float* out = (float*)d_out;

    cudaFuncSetAttribute(attn2_kernel, cudaFuncAttributeMaxDynamicSharedMemorySize, ATTN2_SMEM);
    cudaFuncSetAttribute(qkv3_kernel, cudaFuncAttributeMaxDynamicSharedMemorySize, GSMEM);
    cudaFuncSetAttribute(gemm3_kernel<2>, cudaFuncAttributeMaxDynamicSharedMemorySize, GSMEM);
    cudaFuncSetAttribute(gemm3_kernel<1>, cudaFuncAttributeMaxDynamicSharedMemorySize, GSMEM);

    float *px, *pxn, *pk, *pv, *pcb;
    int *pkeep;
    __nv_bfloat16 *pwth, *pwtl, *pxnh, *pxnl, *pqh, *pql, *pkh, *pkl, *pvh, *pvl;
    __nv_bfloat16 *poh, *pol, *ph1h, *ph1l;
    cudaGetSymbolAddress((void**)&px,   g_x);
    cudaGetSymbolAddress((void**)&pxn,  g_xn);
    cudaGetSymbolAddress((void**)&pk,   g_k);
    cudaGetSymbolAddress((void**)&pv,   g_v);
    cudaGetSymbolAddress((void**)&pcb,  g_cb);
    cudaGetSymbolAddress((void**)&pkeep, g_keep);
    cudaGetSymbolAddress((void**)&pwth, g_wth);
    cudaGetSymbolAddress((void**)&pwtl, g_wtl);
    cudaGetSymbolAddress((void**)&pxnh, g_xnh);
    cudaGetSymbolAddress((void**)&pxnl, g_xnl);
    cudaGetSymbolAddress((void**)&pqh,  g_qh);
    cudaGetSymbolAddress((void**)&pql,  g_ql);
    cudaGetSymbolAddress((void**)&pkh,  g_kh);
    cudaGetSymbolAddress((void**)&pkl,  g_kl);
    cudaGetSymbolAddress((void**)&pvh,  g_vh);
    cudaGetSymbolAddress((void**)&pvl,  g_vl);
    cudaGetSymbolAddress((void**)&poh,  g_oh);
    cudaGetSymbolAddress((void**)&pol,  g_ol);
    cudaGetSymbolAddress((void**)&ph1h, g_h1h);
    cudaGetSymbolAddress((void**)&ph1l, g_h1l);

    // ONE launch for all weight transposes (also puts attn2 at ncu's -s 5 slot)
    tsplit_all_kernel<<<12288, 256>>>(Wq, Wk, Wv, Wo, W1, W2, pwth, pwtl);

    embed_kernel<<<ROWS, 128>>>(tok, cnt, emb);

    dim3 gD(Dz / 128, ROWS / 128);
    dim3 gQKV(12, ROWS / 128);
    dim3 gF(DFFz / 128, ROWS / 128);

    for (int l = 0; l < Lz; l++) {
        layernorm_kernel<<<ROWS, 128>>>(px, ln1g + l*Dz, ln1b + l*Dz, pxn, pxnh, pxnl);

        qkv3_kernel<<<gQKV, 256, GSMEM>>>(pxnh, pxnl,
            pwth + OFF_WQ + (size_t)l*DD, pwtl + OFF_WQ + (size_t)l*DD,
            pwth + OFF_WK + (size_t)l*DD, pwtl + OFF_WK + (size_t)l*DD,
            pwth + OFF_WV + (size_t)l*DD, pwtl + OFF_WV + (size_t)l*DD,
            bq + l*Dz, bk + l*Dz, bv + l*Dz, pqh, pql, pk, pv);

        quantdq_kernel<<<dim3(ROWS * Hz / 8, 2), 256>>>(
            pk, pv, pkh, pkl, pvh, pvl,
            cbk + (size_t)(l*2 + 0)*8, cbk + (size_t)(l*2 + 1)*8);

        attn2_kernel<<<dim3(8, Bz*Hz), 128, ATTN2_SMEM>>>(
            pqh, pql, pkh, pkl, pvh, pvl, poh, pol, pcb, pkeep);

        gemm3_kernel<2><<<gD, 256, GSMEM>>>(ROWS, Dz, Dz, poh, pol,
            pwth + OFF_WO + (size_t)l*DD, pwtl + OFF_WO + (size_t)l*DD,
            bo + l*Dz, pxn, px, nullptr, nullptr, 0);

        layernorm_kernel<<<ROWS, 128>>>(px, ln2g + l*Dz, ln2b + l*Dz, pxn, pxnh, pxnl);

        gemm3_kernel<1><<<gF, 256, GSMEM>>>(ROWS, DFFz, Dz, pxnh, pxnl,
            pwth + OFF_W1 + (size_t)l*DF, pwtl + OFF_W1 + (size_t)l*DF,
            b1 + l*DFFz, nullptr, nullptr, ph1h, ph1l, 1);

        float* dst = (l == Lz - 1) ? out : px;
        gemm3_kernel<2><<<gD, 256, GSMEM>>>(ROWS, Dz, DFFz, ph1h, ph1l,
            pwth + OFF_W2 + (size_t)l*DF, pwtl + OFF_W2 + (size_t)l*DF,
            b2 + l*Dz, pxn, dst, nullptr, nullptr, 0);
    }
}

// round 16
// speedup vs baseline: 3.3474x; 1.1776x over previous
#include <cuda_runtime.h>
#include <cuda_bf16.h>
#include <cstdint>

// Problem constants
#define Bz 4
#define Sz 1024
#define Dz 512
#define Hz 8
#define DKz 64
#define Lz 4
#define DFFz 2048
#define SOFTCAP 30.0f
#define PAD_IDX 0
#define START_IDX 1

#define ROWS (Bz*Sz)           // 4096
#define XSZ  (ROWS*Dz)         // 2,097,152
#define H1SZ (ROWS*DFFz)       // 8,388,608
#define DD   (Dz*Dz)
#define DF   (Dz*DFFz)

#define OFF_WQ 0
#define OFF_WK (4*DD)
#define OFF_WV (8*DD)
#define OFF_WO (12*DD)
#define OFF_W1 (16*DD)
#define OFF_W2 (16*DD + 4*DF)
#define WT_TOT (16*DD + 8*DF)

// Persistent scratch
__device__ float g_x[XSZ];
__device__ float g_xn[XSZ];
__device__ float g_k[XSZ];
__device__ float g_v[XSZ];
__device__ float g_cb[ROWS];
__device__ int   g_keep[ROWS];
__device__ __align__(16) __nv_bfloat16 g_wth[WT_TOT];
__device__ __align__(16) __nv_bfloat16 g_wtl[WT_TOT];
__device__ __align__(16) __nv_bfloat16 g_xnh[XSZ], g_xnl[XSZ];
__device__ __align__(16) __nv_bfloat16 g_qh[XSZ],  g_ql[XSZ];
__device__ __align__(16) __nv_bfloat16 g_kh[XSZ],  g_kl[XSZ];
__device__ __align__(16) __nv_bfloat16 g_vh[XSZ],  g_vl[XSZ];
__device__ __align__(16) __nv_bfloat16 g_oh[XSZ],  g_ol[XSZ];
__device__ __align__(16) __nv_bfloat16 g_h1h[H1SZ], g_h1l[H1SZ];

// ---------------------------------------------------------------------------
// helpers
// ---------------------------------------------------------------------------
__device__ __forceinline__ void bsplit(float x, __nv_bfloat16& h, __nv_bfloat16& l)
{
    h = __float2bfloat16_rn(x);
    l = __float2bfloat16_rn(x - __bfloat162float(h));
}
__device__ __forceinline__ uint32_t bpack(__nv_bfloat16 a, __nv_bfloat16 b)
{
    uint16_t ua = *reinterpret_cast<uint16_t*>(&a);
    uint16_t ub = *reinterpret_cast<uint16_t*>(&b);
    return (uint32_t)ua | ((uint32_t)ub << 16);
}
__device__ __forceinline__ void psplit2(float x, float y, uint32_t& h, uint32_t& l)
{
    __nv_bfloat16 hx, lx, hy, ly;
    bsplit(x, hx, lx); bsplit(y, hy, ly);
    h = bpack(hx, hy); l = bpack(lx, ly);
}
__device__ __forceinline__ float gelu_fast(float x)
{
    float t = 0.7978845608028654f * (x + 0.044715f * x * x * x);
    float e = __expf(2.f * t);
    return x - x * __fdividef(1.f, e + 1.f);
}

#define MMA_BF16(d, a0, a1, a2, a3, b0, b1) \
    asm volatile("mma.sync.aligned.m16n8k16.row.col.f32.bf16.bf16.f32 " \
        "{%0,%1,%2,%3},{%4,%5,%6,%7},{%8,%9},{%0,%1,%2,%3};" \
        : "+f"(d[0]), "+f"(d[1]), "+f"(d[2]), "+f"(d[3]) \
        : "r"(a0), "r"(a1), "r"(a2), "r"(a3), "r"(b0), "r"(b1))

#define LDSM4(r, addr) \
    asm volatile("ldmatrix.sync.aligned.m8n8.x4.shared.b16 {%0,%1,%2,%3},[%4];" \
        : "=r"((r)[0]), "=r"((r)[1]), "=r"((r)[2]), "=r"((r)[3]) : "r"(addr))
#define LDSM4T(r, addr) \
    asm volatile("ldmatrix.sync.aligned.m8n8.x4.trans.shared.b16 {%0,%1,%2,%3},[%4];" \
        : "=r"((r)[0]), "=r"((r)[1]), "=r"((r)[2]), "=r"((r)[3]) : "r"(addr))

__device__ __forceinline__ void cp16(uint32_t dst, const void* src)
{
    uint64_t g = (uint64_t)__cvta_generic_to_global(src);
    asm volatile("cp.async.cg.shared.global [%0], [%1], 16;" :: "r"(dst), "l"(g));
}
#define CP_COMMIT() asm volatile("cp.async.commit_group;")
#define CP_WAIT1()  asm volatile("cp.async.wait_group 1;")
#define CP_WAIT0()  asm volatile("cp.async.wait_group 0;")

// ---------------------------------------------------------------------------
// Embedding
// ---------------------------------------------------------------------------
__global__ void embed_kernel(const int* __restrict__ tok,
                             const float* __restrict__ cnt,
                             const float* __restrict__ emb)
{
    int r = blockIdx.x;
    int b = r / Sz, s = r % Sz;
    int t; float c;
    if (s == 0) { t = START_IDX; c = 1.0f; }
    else        { t = tok[b*Sz + s - 1]; c = cnt[b*Sz + s - 1]; }
    if (threadIdx.x == 0) {
        g_cb[r]   = log1pf(c + 1e-6f);
        g_keep[r] = (t != PAD_IDX);
    }
    const float4* src = (const float4*)(emb + (size_t)t * Dz);
    float4* dst = (float4*)(g_x + (size_t)r * Dz);
    dst[threadIdx.x] = src[threadIdx.x];
}

// ---------------------------------------------------------------------------
// Merged weight transpose + bf16 split: ALL weights in ONE launch.
// ---------------------------------------------------------------------------
__global__ void tsplit_all_kernel(const float* __restrict__ Wq, const float* __restrict__ Wk,
                                  const float* __restrict__ Wv, const float* __restrict__ Wo,
                                  const float* __restrict__ W1, const float* __restrict__ W2,
                                  __nv_bfloat16* __restrict__ dh_base,
                                  __nv_bfloat16* __restrict__ dl_base)
{
    __shared__ float t[32][33];
    int bid = blockIdx.x;
    const float* src; size_t doff; int K, N, n0, k0;
    if (bid < 4096) {
        int w = bid >> 10, r = bid & 1023;
        int layer = r >> 8, tt = r & 255;
        src  = ((w == 0) ? Wq : (w == 1) ? Wk : (w == 2) ? Wv : Wo) + (size_t)layer * DD;
        doff = (size_t)w * 4 * DD + (size_t)layer * DD;
        K = Dz; N = Dz;
        n0 = (tt & 15) * 32; k0 = (tt >> 4) * 32;
    } else if (bid < 8192) {
        int r = bid - 4096, layer = r >> 10, tt = r & 1023;
        src  = W1 + (size_t)layer * DF;
        doff = (size_t)OFF_W1 + (size_t)layer * DF;
        K = Dz; N = DFFz;
        n0 = (tt & 63) * 32; k0 = (tt >> 6) * 32;
    } else {
        int r = bid - 8192, layer = r >> 10, tt = r & 1023;
        src  = W2 + (size_t)layer * DF;
        doff = (size_t)OFF_W2 + (size_t)layer * DF;
        K = DFFz; N = Dz;
        n0 = (tt & 15) * 32; k0 = (tt >> 4) * 32;
    }
    __nv_bfloat16* dh = dh_base + doff;
    __nv_bfloat16* dl = dl_base + doff;
    int tx = threadIdx.x & 31, ty = threadIdx.x >> 5;
    #pragma unroll
    for (int i = 0; i < 4; i++)
        t[ty + 8*i][tx] = src[(size_t)(k0 + ty + 8*i) * N + n0 + tx];
    __syncthreads();
    #pragma unroll
    for (int i = 0; i < 4; i++) {
        float v = t[tx][ty + 8*i];
        __nv_bfloat16 h, l; bsplit(v, h, l);
        size_t idx = (size_t)(n0 + ty + 8*i) * K + k0 + tx;
        dh[idx] = h; dl[idx] = l;
    }
}

// ---------------------------------------------------------------------------
// LayerNorm -> fp32 + bf16 hi/lo
// ---------------------------------------------------------------------------
__device__ __forceinline__ float block_reduce_sum(float v, float* red)
{
    int lane = threadIdx.x & 31, warp = threadIdx.x >> 5;
    #pragma unroll
    for (int o = 16; o > 0; o >>= 1) v += __shfl_xor_sync(0xffffffffu, v, o);
    if (lane == 0) red[warp] = v;
    __syncthreads();
    float r = 0.f;
    if (warp == 0) {
        r = (lane < (blockDim.x >> 5)) ? red[lane] : 0.f;
        #pragma unroll
        for (int o = 16; o > 0; o >>= 1) r += __shfl_xor_sync(0xffffffffu, r, o);
        if (lane == 0) red[0] = r;
    }
    __syncthreads();
    r = red[0];
    __syncthreads();
    return r;
}

__global__ void layernorm_kernel(const float* __restrict__ x,
                                 const float* __restrict__ gam,
                                 const float* __restrict__ bet,
                                 float* __restrict__ out,
                                 __nv_bfloat16* __restrict__ outh,
                                 __nv_bfloat16* __restrict__ outl)
{
    __shared__ float red[32];
    int r = blockIdx.x;
    const float4* xr = (const float4*)(x + (size_t)r * Dz);
    float4 v = xr[threadIdx.x];
    float s = v.x + v.y + v.z + v.w;
    float tot = block_reduce_sum(s, red);
    float mu = tot * (1.0f / Dz);
    float d0 = v.x - mu, d1 = v.y - mu, d2 = v.z - mu, d3 = v.w - mu;
    float sq = d0*d0 + d1*d1 + d2*d2 + d3*d3;
    float var = block_reduce_sum(sq, red) * (1.0f / Dz);
    float rstd = rsqrtf(var + 1e-5f);
    float4 gg = ((const float4*)gam)[threadIdx.x];
    float4 bb = ((const float4*)bet)[threadIdx.x];
    float4 o;
    o.x = d0 * rstd * gg.x + bb.x;
    o.y = d1 * rstd * gg.y + bb.y;
    o.z = d2 * rstd * gg.z + bb.z;
    o.w = d3 * rstd * gg.w + bb.w;
    ((float4*)(out + (size_t)r * Dz))[threadIdx.x] = o;
    uint32_t h0, l0, h1, l1;
    psplit2(o.x, o.y, h0, l0);
    psplit2(o.z, o.w, h1, l1);
    uint2 ph = { h0, h1 }, pl = { l0, l1 };
    *(uint2*)(outh + (size_t)r * Dz + threadIdx.x * 4) = ph;
    *(uint2*)(outl + (size_t)r * Dz + threadIdx.x * 4) = pl;
}

// ---------------------------------------------------------------------------
// GEMM v5b: bf16 3-term split, BK=32, 2-stage double buffer.
// Stage: 4 arrays (Ah,Al,Bh,Bl) x 128 rows x 80B (64B data + 16B pad).
// 80B stride: 16B-aligned (cp.async/ldmatrix OK); 20 words/row => 8-row LDSM
// group hits words {0,20,8,28,16,4,24,12} -> all 32 banks, conflict-free.
// One wait+sync per BK=32 (24 LDSM + 96 MMA per warp between barriers).
// 256 thr / 8 warps, warp tile 64x32, 2 CTAs/SM (164KB smem).
// ---------------------------------------------------------------------------
#define GARR   10240                // 128 * 80
#define GSTAGE (4 * GARR)           // 40960
#define GSMEM  (2 * GSTAGE)         // 81920

__device__ __forceinline__ void stage_load(
    uint32_t smem_u32, int s, int k0, int K,
    const __nv_bfloat16* Ah, const __nv_bfloat16* Al,
    const __nv_bfloat16* Bh, const __nv_bfloat16* Bl,
    int aBase, int bBase, int tid)
{
    #pragma unroll
    for (int rep = 0; rep < 8; rep++) {
        int c = tid + rep * 256;          // 0..2047
        int arr = c >> 9;                 // 0..3
        int rem = c & 511;
        int r = rem >> 2, h = rem & 3;    // row 0..127, 16B-chunk 0..3
        const __nv_bfloat16* g =
            (arr == 0) ? Ah + (size_t)(aBase + r) * K :
            (arr == 1) ? Al + (size_t)(aBase + r) * K :
            (arr == 2) ? Bh + (size_t)(bBase + r) * K :
                         Bl + (size_t)(bBase + r) * K;
        uint32_t dst = smem_u32 + s * GSTAGE + arr * GARR + r * 80 + h * 16;
        cp16(dst, g + k0 + h * 8);
    }
}

template<int EPI>
__device__ __forceinline__ void gemm3_body(
    int M, int N, int K,
    const __nv_bfloat16* __restrict__ Ah, const __nv_bfloat16* __restrict__ Al,
    const __nv_bfloat16* __restrict__ Bh, const __nv_bfloat16* __restrict__ Bl,
    const float* __restrict__ bias, const float* __restrict__ res,
    float* __restrict__ C, __nv_bfloat16* __restrict__ Ch,
    __nv_bfloat16* __restrict__ Cl, bool outbf, int bx, int by)
{
    extern __shared__ __align__(16) char smraw[];
    uint32_t smem_u32 = (uint32_t)__cvta_generic_to_shared(smraw);
    int tid = threadIdx.x;
    int lane = tid & 31, warp = tid >> 5;
    int wm = warp >> 2, wn = warp & 3;
    int gid = lane >> 2, tig = lane & 3;
    int aBase = by * 128, bBase = bx * 128;

    float acc[4][4][4];
    #pragma unroll
    for (int mt = 0; mt < 4; mt++)
        #pragma unroll
        for (int nt = 0; nt < 4; nt++)
            #pragma unroll
            for (int i = 0; i < 4; i++) acc[mt][nt][i] = 0.f;

    int nIter = K / 32;
    stage_load(smem_u32, 0, 0, K, Ah, Al, Bh, Bl, aBase, bBase, tid);
    CP_COMMIT();

    uint32_t aoff = (uint32_t)((wm*64 + (lane & 15)) * 80 + (lane >> 4) * 16);
    int brow = wn*32 + ((lane & 7) | (((lane >> 4) & 1) << 3));
    uint32_t boff = (uint32_t)(brow * 80 + ((lane >> 3) & 1) * 16);

    int stg = 0;
    for (int it = 0; it < nIter; it++) {
        CP_WAIT0();
        __syncthreads();
        if (it + 1 < nIter) {
            stage_load(smem_u32, stg ^ 1, (it + 1) * 32, K, Ah, Al, Bh, Bl,
                       aBase, bBase, tid);
            CP_COMMIT();
        }

        uint32_t sb = smem_u32 + stg * GSTAGE;
        #pragma unroll
        for (int ks = 0; ks < 2; ks++) {
            uint32_t kso = (uint32_t)(ks * 32);
            uint32_t bh[2][4], bl[2][4];
            LDSM4(bh[0], sb + 2*GARR + boff + kso);
            LDSM4(bh[1], sb + 2*GARR + boff + kso + 1280);
            LDSM4(bl[0], sb + 3*GARR + boff + kso);
            LDSM4(bl[1], sb + 3*GARR + boff + kso + 1280);

            #pragma unroll
            for (int mt = 0; mt < 4; mt++) {
                uint32_t ah[4], al[4];
                LDSM4(ah, sb + aoff + kso + mt * 1280);
                LDSM4(al, sb + GARR + aoff + kso + mt * 1280);
                #pragma unroll
                for (int nt = 0; nt < 4; nt++) {
                    int p = nt >> 1, q = (nt & 1) * 2;
                    MMA_BF16(acc[mt][nt], ah[0], ah[1], ah[2], ah[3],
                             bh[p][q], bh[p][q+1]);
                    MMA_BF16(acc[mt][nt], ah[0], ah[1], ah[2], ah[3],
                             bl[p][q], bl[p][q+1]);
                    MMA_BF16(acc[mt][nt], al[0], al[1], al[2], al[3],
                             bh[p][q], bh[p][q+1]);
                }
            }
        }
        stg ^= 1;
    }

    size_t rowBase = (size_t)by * 128 + wm * 64;
    size_t colBase = (size_t)bx * 128 + wn * 32;
    #pragma unroll
    for (int nt = 0; nt < 4; nt++) {
        size_t c = colBase + nt * 8 + tig * 2;
        float2 bb = *(const float2*)(bias + c);
        #pragma unroll
        for (int mt = 0; mt < 4; mt++) {
            size_t r0 = rowBase + mt * 16 + gid;
            size_t r1 = r0 + 8;
            float2 v0, v1;
            v0.x = acc[mt][nt][0] + bb.x; v0.y = acc[mt][nt][1] + bb.y;
            v1.x = acc[mt][nt][2] + bb.x; v1.y = acc[mt][nt][3] + bb.y;
            if (EPI == 1) {
                v0.x = gelu_fast(v0.x); v0.y = gelu_fast(v0.y);
                v1.x = gelu_fast(v1.x); v1.y = gelu_fast(v1.y);
            }
            if (EPI == 2) {
                float2 q0 = *(const float2*)(res + r0 * N + c);
                float2 q1 = *(const float2*)(res + r1 * N + c);
                v0.x += q0.x; v0.y += q0.y;
                v1.x += q1.x; v1.y += q1.y;
            }
            if (outbf) {
                uint32_t h, l;
                psplit2(v0.x, v0.y, h, l);
                *(uint32_t*)(Ch + r0 * N + c) = h;
                *(uint32_t*)(Cl + r0 * N + c) = l;
                psplit2(v1.x, v1.y, h, l);
                *(uint32_t*)(Ch + r1 * N + c) = h;
                *(uint32_t*)(Cl + r1 * N + c) = l;
            } else {
                *(float2*)(C + r0 * N + c) = v0;
                *(float2*)(C + r1 * N + c) = v1;
            }
        }
    }
}

template<int EPI>
__global__ void __launch_bounds__(256, 2)
gemm3_kernel(int M, int N, int K,
             const __nv_bfloat16* Ah, const __nv_bfloat16* Al,
             const __nv_bfloat16* Bh, const __nv_bfloat16* Bl,
             const float* bias, const float* res,
             float* C, __nv_bfloat16* Ch, __nv_bfloat16* Cl, int outbf)
{
    gemm3_body<EPI>(M, N, K, Ah, Al, Bh, Bl, bias, res, C, Ch, Cl, outbf != 0,
                    blockIdx.x, blockIdx.y);
}

__global__ void __launch_bounds__(256, 2)
qkv3_kernel(const __nv_bfloat16* Ah, const __nv_bfloat16* Al,
            const __nv_bfloat16* WqH, const __nv_bfloat16* WqL,
            const __nv_bfloat16* WkH, const __nv_bfloat16* WkL,
            const __nv_bfloat16* WvH, const __nv_bfloat16* WvL,
            const float* bq, const float* bk, const float* bv,
            __nv_bfloat16* Cqh, __nv_bfloat16* Cql,
            float* Ck, float* Cv)
{
    int which = blockIdx.x >> 2;
    int bx = blockIdx.x & 3;
    const __nv_bfloat16* Bh = (which == 0) ? WqH : (which == 1) ? WkH : WvH;
    const __nv_bfloat16* Bl = (which == 0) ? WqL : (which == 1) ? WkL : WvL;
    const float* b = (which == 0) ? bq : (which == 1) ? bk : bv;
    float* C = (which == 1) ? Ck : Cv;
    gemm3_body<0>(ROWS, Dz, Dz, Ah, Al, Bh, Bl, b, nullptr, C, Cqh, Cql,
                  which == 0, bx, blockIdx.y);
}

// ---------------------------------------------------------------------------
// quant-dequant: fp32 in -> bf16 hi/lo out
// ---------------------------------------------------------------------------
__global__ void quantdq_kernel(const float* __restrict__ tk, const float* __restrict__ tv,
                               __nv_bfloat16* __restrict__ okh, __nv_bfloat16* __restrict__ okl,
                               __nv_bfloat16* __restrict__ ovh, __nv_bfloat16* __restrict__ ovl,
                               const float* __restrict__ lvk,
                               const float* __restrict__ lvv)
{
    __shared__ float lv[8];
    const float* t = (blockIdx.y == 0) ? tk : tv;
    __nv_bfloat16* oh = (blockIdx.y == 0) ? okh : ovh;
    __nv_bfloat16* ol = (blockIdx.y == 0) ? okl : ovl;
    const float* levels = (blockIdx.y == 0) ? lvk : lvv;
    if (threadIdx.x < 8) lv[threadIdx.x] = levels[threadIdx.x];
    __syncthreads();
    int warp = threadIdx.x >> 5, lane = threadIdx.x & 31;
    int w = blockIdx.x * 8 + warp;
    size_t off = (size_t)(w / Hz) * Dz + (size_t)(w % Hz) * DKz;
    const float* p = t + off;

    float x0 = p[lane], x1 = p[lane + 32];
    float ss = x0 * x0 + x1 * x1;
    #pragma unroll
    for (int o = 16; o > 0; o >>= 1) ss += __shfl_xor_sync(0xffffffffu, ss, o);
    float nrm = sqrtf(ss);
    float inv = 1.f / (nrm + 1e-8f);
    float u0 = x0 * inv, u1 = x1 * inv;
    float a0 = fabsf(u0), a1 = fabsf(u1);
    float sg0 = (u0 >= 0.f) ? 1.f : -1.f;
    float sg1 = (u1 >= 0.f) ? 1.f : -1.f;

    float q0 = lv[0], b0 = fabsf(a0 - lv[0]);
    float q1 = lv[0], b1 = fabsf(a1 - lv[0]);
    #pragma unroll
    for (int i = 1; i < 8; i++) {
        float d0 = fabsf(a0 - lv[i]);
        if (d0 < b0) { b0 = d0; q0 = lv[i]; }
        float d1 = fabsf(a1 - lv[i]);
        if (d1 < b1) { b1 = d1; q1 = lv[i]; }
    }
    float num = a0 * q0 + a1 * q1;
    float den = q0 * q0 + q1 * q1;
    #pragma unroll
    for (int o = 16; o > 0; o >>= 1) {
        num += __shfl_xor_sync(0xffffffffu, num, o);
        den += __shfl_xor_sync(0xffffffffu, den, o);
    }
    float rmag = num / (den + 1e-8f);
    float r0 = sg0 * q0 * rmag * nrm;
    float r1 = sg1 * q1 * rmag * nrm;
    __nv_bfloat16 h, l;
    bsplit(r0, h, l); oh[off + lane] = h;      ol[off + lane] = l;
    bsplit(r1, h, l); oh[off + lane + 32] = h; ol[off + lane + 32] = l;
}

// ---------------------------------------------------------------------------
// Tensor-core attention v2 (R13 passing version, unchanged)
// ---------------------------------------------------------------------------
#define AT_STRIDE 144
#define AT_TILE   (64 * AT_STRIDE)
#define AT2_Q_H   0
#define AT2_Q_L   AT_TILE
#define AT2_KV(s) (2*AT_TILE + (s)*(4*AT_TILE))
#define AT2_CB    (10*AT_TILE)
#define ATTN2_SMEM (10*AT_TILE + 1024)

__device__ __forceinline__ void at_load_kv(
    uint32_t sb, int s,
    const __nv_bfloat16* kh, const __nv_bfloat16* kl,
    const __nv_bfloat16* vh, const __nv_bfloat16* vl,
    int b, int k0, size_t hcol, int tid)
{
    #pragma unroll
    for (int i = 0; i < 16; i++) {
        int c = tid + i * 128;
        int arr = c >> 9, r = (c >> 3) & 63, ch = c & 7;
        const __nv_bfloat16* src =
            (arr == 0 ? kh : arr == 1 ? kl : arr == 2 ? vh : vl)
            + (size_t)(b * Sz + k0 + r) * Dz + hcol + ch * 8;
        cp16(sb + AT2_KV(s) + arr * AT_TILE + r * AT_STRIDE + ch * 16, src);
    }
}

__global__ void __launch_bounds__(128, 1)
attn2_kernel(const __nv_bfloat16* __restrict__ qh, const __nv_bfloat16* __restrict__ ql,
             const __nv_bfloat16* __restrict__ kh, const __nv_bfloat16* __restrict__ kl,
             const __nv_bfloat16* __restrict__ vh, const __nv_bfloat16* __restrict__ vl,
             __nv_bfloat16* __restrict__ o_hi, __nv_bfloat16* __restrict__ o_lo,
             const float* __restrict__ cb, const int* __restrict__ keep)
{
    extern __shared__ __align__(16) char sm2[];
    uint32_t sb = (uint32_t)__cvta_generic_to_shared(sm2);
    float* cbs = (float*)(sm2 + AT2_CB);
    float* mks = cbs + 128;

    int tid = threadIdx.x;
    int lane = tid & 31, warp = tid >> 5;
    int gid = lane >> 2, tig = lane & 3;
    int bh = blockIdx.y;
    int b = bh >> 3, h = bh & 7;
    size_t hcol = (size_t)h * DKz;

    uint32_t qaddr_base = (uint32_t)((warp*16 + (lane & 15)) * AT_STRIDE + (lane >> 4) * 16);
    uint32_t krow_off   = (uint32_t)(((lane & 7) | (((lane >> 4) & 1) << 3)) * AT_STRIDE
                                     + ((lane >> 3) & 1) * 16);
    uint32_t vaddr_base = (uint32_t)((lane & 15) * AT_STRIDE + ((lane >> 4) << 3) * 2);

    #pragma unroll
    for (int sub = 0; sub < 2; sub++) {
        int qt = (sub == 0) ? blockIdx.x : 15 - blockIdx.x;
        int q0 = qt * 64;

        #pragma unroll
        for (int i = 0; i < 8; i++) {
            int c = tid + i * 128;
            int arr = c >> 9, r = (c >> 3) & 63, ch = c & 7;
            const __nv_bfloat16* src = (arr ? ql : qh)
                + (size_t)(b * Sz + q0 + r) * Dz + hcol + ch * 8;
            cp16(sb + (arr ? AT2_Q_L : AT2_Q_H) + r * AT_STRIDE + ch * 16, src);
        }
        CP_COMMIT();
        at_load_kv(sb, 0, kh, kl, vh, vl, b, 0, hcol, tid);
        CP_COMMIT();
        if (tid < 64) {
            cbs[tid] = cb[b * Sz + tid];
            mks[tid] = keep[b * Sz + tid] ? 1.f : 0.f;
        }

        float acc_o[8][4];
        #pragma unroll
        for (int nt = 0; nt < 8; nt++)
            #pragma unroll
            for (int i = 0; i < 4; i++) acc_o[nt][i] = 0.f;
        float den0 = 0.f, den1 = 0.f;

        for (int kt = 0; kt <= qt; kt++) {
            int stg = kt & 1;
            bool more = (kt + 1 <= qt);
            if (more) {
                at_load_kv(sb, stg ^ 1, kh, kl, vh, vl, b, (kt + 1) * 64, hcol, tid);
                CP_COMMIT();
                if (tid < 64) {
                    cbs[(stg ^ 1) * 64 + tid] = cb[b * Sz + (kt + 1) * 64 + tid];
                    mks[(stg ^ 1) * 64 + tid] = keep[b * Sz + (kt + 1) * 64 + tid] ? 1.f : 0.f;
                }
                CP_WAIT1();
            } else {
                CP_WAIT0();
            }
            __syncthreads();

            uint32_t kvb = sb + AT2_KV(stg);
            int k0 = kt * 64;
            float* cbt = cbs + stg * 64;
            float* mkt = mks + stg * 64;

            float s[8][4];
            #pragma unroll
            for (int nt = 0; nt < 8; nt++)
                #pragma unroll
                for (int i = 0; i < 4; i++) s[nt][i] = 0.f;

            #pragma unroll
            for (int ks = 0; ks < 4; ks++) {
                uint32_t qa[4], qb[4];
                LDSM4(qa, sb + AT2_Q_H + qaddr_base + ks * 32);
                LDSM4(qb, sb + AT2_Q_L + qaddr_base + ks * 32);
                uint32_t KH[4][4], KL[4][4];
                #pragma unroll
                for (int g = 0; g < 4; g++) {
                    uint32_t off = (uint32_t)(g * 16 * AT_STRIDE) + krow_off + ks * 32;
                    LDSM4(KH[g], kvb + off);
                    LDSM4(KL[g], kvb + AT_TILE + off);
                }
                #pragma unroll
                for (int nt = 0; nt < 8; nt++) {
                    int g = nt >> 1, q = (nt & 1) * 2;
                    MMA_BF16(s[nt], qa[0], qa[1], qa[2], qa[3], KH[g][q], KH[g][q+1]);
                    MMA_BF16(s[nt], qa[0], qa[1], qa[2], qa[3], KL[g][q], KL[g][q+1]);
                    MMA_BF16(s[nt], qb[0], qb[1], qb[2], qb[3], KH[g][q], KH[g][q+1]);
                }
            }

            int qrow = q0 + warp * 16 + gid;
            #pragma unroll
            for (int nt = 0; nt < 8; nt++) {
                #pragma unroll
                for (int i = 0; i < 4; i++) {
                    int kgl = nt * 8 + tig * 2 + (i & 1);
                    int qg = qrow + (i >> 1) * 8;
                    float y = s[nt][i] * 0.125f + cbt[kgl];
                    float u = __expf(y * (1.0f / 15.0f));
                    float p = __expf(30.f - __fdividef(60.f, u + 1.f)) * mkt[kgl];
                    s[nt][i] = (k0 + kgl <= qg) ? p : 0.f;
                }
            }
            #pragma unroll
            for (int nt = 0; nt < 8; nt++) {
                den0 += s[nt][0] + s[nt][1];
                den1 += s[nt][2] + s[nt][3];
            }

            #pragma unroll
            for (int j = 0; j < 4; j++) {
                uint32_t pa[4], pb[4];
                psplit2(s[2*j][0],   s[2*j][1],   pa[0], pb[0]);
                psplit2(s[2*j][2],   s[2*j][3],   pa[1], pb[1]);
                psplit2(s[2*j+1][0], s[2*j+1][1], pa[2], pb[2]);
                psplit2(s[2*j+1][2], s[2*j+1][3], pa[3], pb[3]);
                #pragma unroll
                for (int dg = 0; dg < 4; dg++) {
                    uint32_t VH4[4], VL4[4];
                    uint32_t voff = vaddr_base + (uint32_t)(j * 16 * AT_STRIDE) + dg * 32;
                    LDSM4T(VH4, kvb + 2 * AT_TILE + voff);
                    LDSM4T(VL4, kvb + 3 * AT_TILE + voff);
                    MMA_BF16(acc_o[2*dg],   pa[0], pa[1], pa[2], pa[3], VH4[0], VH4[1]);
                    MMA_BF16(acc_o[2*dg],   pa[0], pa[1], pa[2], pa[3], VL4[0], VL4[1]);
                    MMA_BF16(acc_o[2*dg],   pb[0], pb[1], pb[2], pb[3], VH4[0], VH4[1]);
                    MMA_BF16(acc_o[2*dg+1], pa[0], pa[1], pa[2], pa[3], VH4[2], VH4[3]);
                    MMA_BF16(acc_o[2*dg+1], pa[0], pa[1], pa[2], pa[3], VL4[2], VL4[3]);
                    MMA_BF16(acc_o[2*dg+1], pb[0], pb[1], pb[2], pb[3], VH4[2], VH4[3]);
                }
            }
            __syncthreads();
        }

        den0 += __shfl_xor_sync(0xffffffffu, den0, 1);
        den0 += __shfl_xor_sync(0xffffffffu, den0, 2);
        den1 += __shfl_xor_sync(0xffffffffu, den1, 1);
        den1 += __shfl_xor_sync(0xffffffffu, den1, 2);
        float i0 = __fdividef(1.f, den0);
        float i1 = __fdividef(1.f, den1);

        size_t r0 = (size_t)(b * Sz + q0 + warp * 16 + gid);
        size_t r1 = r0 + 8;
        #pragma unroll
        for (int nt = 0; nt < 8; nt++) {
            size_t c = hcol + nt * 8 + tig * 2;
            uint32_t hh, ll;
            psplit2(acc_o[nt][0] * i0, acc_o[nt][1] * i0, hh, ll);
            *(uint32_t*)(o_hi + r0 * Dz + c) = hh;
            *(uint32_t*)(o_lo + r0 * Dz + c) = ll;
            psplit2(acc_o[nt][2] * i1, acc_o[nt][3] * i1, hh, ll);
            *(uint32_t*)(o_hi + r1 * Dz + c) = hh;
            *(uint32_t*)(o_lo + r1 * Dz + c) = ll;
        }
    }
}

// ---------------------------------------------------------------------------
// Host launcher
// ---------------------------------------------------------------------------
extern "C" void kernel_launch(void* const* d_in, const int* in_sizes, int n_in,
                              void* d_out, int out_size)
{
    const int*   tok  = (const int*)  d_in[0];
    const float* cnt  = (const float*)d_in[1];
    const float* emb  = (const float*)d_in[2];
    const float* Wq   = (const float*)d_in[3];
    const float* bq   = (const float*)d_in[4];
    const float* Wk   = (const float*)d_in[5];
    const float* bk   = (const float*)d_in[6];
    const float* Wv   = (const float*)d_in[7];
    const float* bv   = (const float*)d_in[8];
    const float* Wo   = (const float*)d_in[9];
    const float* bo   = (const float*)d_in[10];
    const float* ln1g = (const float*)d_in[11];
    const float* ln1b = (const float*)d_in[12];
    const float* ln2g = (const float*)d_in[13];
    const float* ln2b = (const float*)d_in[14];
    const float* W1   = (const float*)d_in[15];
    const float* b1   = (const float*)d_in[16];
    const float* W2   = (const float*)d_in[17];
    const float* b2   = (const float*)d_in[18];
    const float* cbk  = (const float*)d_in[19];
    float* out = (float*)d_out;

    cudaFuncSetAttribute(attn2_kernel, cudaFuncAttributeMaxDynamicSharedMemorySize, ATTN2_SMEM);
    cudaFuncSetAttribute(qkv3_kernel, cudaFuncAttributeMaxDynamicSharedMemorySize, GSMEM);
    cudaFuncSetAttribute(gemm3_kernel<2>, cudaFuncAttributeMaxDynamicSharedMemorySize, GSMEM);
    cudaFuncSetAttribute(gemm3_kernel<1>, cudaFuncAttributeMaxDynamicSharedMemorySize, GSMEM);

    float *px, *pxn, *pk, *pv, *pcb;
    int *pkeep;
    __nv_bfloat16 *pwth, *pwtl, *pxnh, *pxnl, *pqh, *pql, *pkh, *pkl, *pvh, *pvl;
    __nv_bfloat16 *poh, *pol, *ph1h, *ph1l;
    cudaGetSymbolAddress((void**)&px,   g_x);
    cudaGetSymbolAddress((void**)&pxn,  g_xn);
    cudaGetSymbolAddress((void**)&pk,   g_k);
    cudaGetSymbolAddress((void**)&pv,   g_v);
    cudaGetSymbolAddress((void**)&pcb,  g_cb);
    cudaGetSymbolAddress((void**)&pkeep, g_keep);
    cudaGetSymbolAddress((void**)&pwth, g_wth);
    cudaGetSymbolAddress((void**)&pwtl, g_wtl);
    cudaGetSymbolAddress((void**)&pxnh, g_xnh);
    cudaGetSymbolAddress((void**)&pxnl, g_xnl);
    cudaGetSymbolAddress((void**)&pqh,  g_qh);
    cudaGetSymbolAddress((void**)&pql,  g_ql);
    cudaGetSymbolAddress((void**)&pkh,  g_kh);
    cudaGetSymbolAddress((void**)&pkl,  g_kl);
    cudaGetSymbolAddress((void**)&pvh,  g_vh);
    cudaGetSymbolAddress((void**)&pvl,  g_vl);
    cudaGetSymbolAddress((void**)&poh,  g_oh);
    cudaGetSymbolAddress((void**)&pol,  g_ol);
    cudaGetSymbolAddress((void**)&ph1h, g_h1h);
    cudaGetSymbolAddress((void**)&ph1l, g_h1l);

    tsplit_all_kernel<<<12288, 256>>>(Wq, Wk, Wv, Wo, W1, W2, pwth, pwtl);

    embed_kernel<<<ROWS, 128>>>(tok, cnt, emb);

    dim3 gD(Dz / 128, ROWS / 128);
    dim3 gQKV(12, ROWS / 128);
    dim3 gF(DFFz / 128, ROWS / 128);

    for (int l = 0; l < Lz; l++) {
        layernorm_kernel<<<ROWS, 128>>>(px, ln1g + l*Dz, ln1b + l*Dz, pxn, pxnh, pxnl);

        qkv3_kernel<<<gQKV, 256, GSMEM>>>(pxnh, pxnl,
            pwth + OFF_WQ + (size_t)l*DD, pwtl + OFF_WQ + (size_t)l*DD,
            pwth + OFF_WK + (size_t)l*DD, pwtl + OFF_WK + (size_t)l*DD,
            pwth + OFF_WV + (size_t)l*DD, pwtl + OFF_WV + (size_t)l*DD,
            bq + l*Dz, bk + l*Dz, bv + l*Dz, pqh, pql, pk, pv);

        quantdq_kernel<<<dim3(ROWS * Hz / 8, 2), 256>>>(
            pk, pv, pkh, pkl, pvh, pvl,
            cbk + (size_t)(l*2 + 0)*8, cbk + (size_t)(l*2 + 1)*8);

        attn2_kernel<<<dim3(8, Bz*Hz), 128, ATTN2_SMEM>>>(
            pqh, pql, pkh, pkl, pvh, pvl, poh, pol, pcb, pkeep);

        gemm3_kernel<2><<<gD, 256, GSMEM>>>(ROWS, Dz, Dz, poh, pol,
            pwth + OFF_WO + (size_t)l*DD, pwtl + OFF_WO + (size_t)l*DD,
            bo + l*Dz, pxn, px, nullptr, nullptr, 0);

        layernorm_kernel<<<ROWS, 128>>>(px, ln2g + l*Dz, ln2b + l*Dz, pxn, pxnh, pxnl);

        gemm3_kernel<1><<<gF, 256, GSMEM>>>(ROWS, DFFz, Dz, pxnh, pxnl,
            pwth + OFF_W1 + (size_t)l*DF, pwtl + OFF_W1 + (size_t)l*DF,
            b1 + l*DFFz, nullptr, nullptr, ph1h, ph1l, 1);

        float* dst = (l == Lz - 1) ? out : px;
        gemm3_kernel<2><<<gD, 256, GSMEM>>>(ROWS, Dz, DFFz, ph1h, ph1l,
            pwth + OFF_W2 + (size_t)l*DF, pwtl + OFF_W2 + (size_t)l*DF,
            b2 + l*Dz, pxn, dst, nullptr, nullptr, 0);
    }
}